// round 1
// baseline (speedup 1.0000x reference)
#include <cuda_runtime.h>
#include <math.h>
#include <stdint.h>

#define N_NODES 65536
#define D       256
#define NS      512
#define HID     256
#define KTOP    10
#define EPSC    1e-8f
#define SCALE_C 0.0625f  /* 256^-0.5 */

// ---------------------------------------------------------------------------
// Scratch (static __device__ arrays; no allocation anywhere)
// ---------------------------------------------------------------------------
__device__ float g_xin  [(size_t)N_NODES * D];
__device__ float g_kk   [(size_t)N_NODES * D];
__device__ float g_vv   [(size_t)N_NODES * D];
__device__ float g_q2   [(size_t)N_NODES * D];
__device__ float g_nodes[(size_t)N_NODES * D];
__device__ float g_tmp  [(size_t)N_NODES * D];
__device__ float g_S    [(size_t)N_NODES * NS];   // dots1 [NS,N] then dots2 [N,NS]

__device__ float g_e    [NS * D];
__device__ float g_q    [NS * D];
__device__ float g_e2cat[NS * 2 * D];
__device__ float g_h1   [NS * HID];
__device__ float g_e2   [NS * D];
__device__ float g_k2   [NS * D];
__device__ float g_edg  [NS * D];

__device__ float g_WqT [D * D];
__device__ float g_WkT [D * D];
__device__ float g_WvT [D * D];
__device__ float g_Wm1T[HID * 2 * D];
__device__ float g_Wm2T[D * HID];
__device__ float g_cwT [D * D];
__device__ float g_Wc0T[D * D];
__device__ float g_Wc1T[D * D];
__device__ float g_WtT [D * D];

// ---------------------------------------------------------------------------
// Transpose [R,C] -> [C,R]
// ---------------------------------------------------------------------------
__global__ void transpose_k(const float* __restrict__ in, float* __restrict__ out,
                            int R, int C) {
    __shared__ float tile[32][33];
    int bx = blockIdx.x * 32, by = blockIdx.y * 32;
    int x = threadIdx.x;
    for (int y = threadIdx.y; y < 32; y += 8)
        tile[y][x] = in[(size_t)(by + y) * C + bx + x];
    __syncthreads();
    for (int y = threadIdx.y; y < 32; y += 8)
        out[(size_t)(bx + y) * R + by + x] = tile[x][y];
}

// ---------------------------------------------------------------------------
// LayerNorm: one warp per row of 256
// ---------------------------------------------------------------------------
__global__ void ln_rows(const float* __restrict__ x, const float* __restrict__ w,
                        const float* __restrict__ b, float* __restrict__ o, int M) {
    int warp = (blockIdx.x * blockDim.x + threadIdx.x) >> 5;
    int lane = threadIdx.x & 31;
    if (warp >= M) return;
    const float* r = x + (size_t)warp * D;
    float v[8]; float s = 0.f;
#pragma unroll
    for (int j = 0; j < 8; j++) { v[j] = r[lane + 32 * j]; s += v[j]; }
#pragma unroll
    for (int st = 16; st; st >>= 1) s += __shfl_xor_sync(0xffffffffu, s, st);
    float mu = s * (1.f / 256.f);
    float q = 0.f;
#pragma unroll
    for (int j = 0; j < 8; j++) { float d = v[j] - mu; q += d * d; }
#pragma unroll
    for (int st = 16; st; st >>= 1) q += __shfl_xor_sync(0xffffffffu, q, st);
    float rinv = rsqrtf(q * (1.f / 256.f) + 1e-5f);
    float* po = o + (size_t)warp * D;
#pragma unroll
    for (int j = 0; j < 8; j++) {
        int c = lane + 32 * j;
        po[c] = (v[j] - mu) * rinv * w[c] + b[c];
    }
}

// edges = mu + exp(logsigma)*noise, then LN
__global__ void edges_ln(const float* __restrict__ noise, const float* __restrict__ emu,
                         const float* __restrict__ elog, const float* __restrict__ w,
                         const float* __restrict__ b, float* __restrict__ o) {
    int warp = (blockIdx.x * blockDim.x + threadIdx.x) >> 5;
    int lane = threadIdx.x & 31;
    if (warp >= NS) return;
    const float* r = noise + (size_t)warp * D;
    float v[8]; float s = 0.f;
#pragma unroll
    for (int j = 0; j < 8; j++) {
        int c = lane + 32 * j;
        v[j] = emu[c] + expf(elog[c]) * r[c];
        s += v[j];
    }
#pragma unroll
    for (int st = 16; st; st >>= 1) s += __shfl_xor_sync(0xffffffffu, s, st);
    float mu = s * (1.f / 256.f);
    float q = 0.f;
#pragma unroll
    for (int j = 0; j < 8; j++) { float d = v[j] - mu; q += d * d; }
#pragma unroll
    for (int st = 16; st; st >>= 1) q += __shfl_xor_sync(0xffffffffu, q, st);
    float rinv = rsqrtf(q * (1.f / 256.f) + 1e-5f);
    float* po = o + (size_t)warp * D;
#pragma unroll
    for (int j = 0; j < 8; j++) {
        int c = lane + 32 * j;
        po[c] = (v[j] - mu) * rinv * w[c] + b[c];
    }
}

// ---------------------------------------------------------------------------
// NT GEMM: C[m,n] = epi( sum_k A[m,k]*B[n,k] )
// A:[M,K] rowmajor, B:[N,K] rowmajor.  All dims divisible by tiles.
// ---------------------------------------------------------------------------
template <int BM, int BN, int BK, int TM, int TN,
          bool USE_SCALE, bool BIAS, bool RELU, bool ACCUM, bool ADDAUX>
__global__ void gemm_nt(const float* __restrict__ A, const float* __restrict__ B,
                        float* __restrict__ C, const float* __restrict__ bias,
                        const float* __restrict__ aux,
                        int M, int N, int K, float scale) {
    constexpr int THREADS = (BM / TM) * (BN / TN);
    __shared__ float As[BK][BM + 4];
    __shared__ float Bs[BK][BN + 4];
    const int bm = blockIdx.y * BM;
    const int bn = blockIdx.x * BN;
    const int tid = threadIdx.x;
    const int tx = tid % (BN / TN);
    const int ty = tid / (BN / TN);
    float acc[TM][TN];
#pragma unroll
    for (int i = 0; i < TM; i++)
#pragma unroll
        for (int j = 0; j < TN; j++) acc[i][j] = 0.f;

    constexpr int A_F4 = BM * BK / 4;
    constexpr int B_F4 = BN * BK / 4;

    for (int k0 = 0; k0 < K; k0 += BK) {
        for (int f = tid; f < A_F4; f += THREADS) {
            int row = f / (BK / 4);
            int kc = (f % (BK / 4)) * 4;
            float4 v = *reinterpret_cast<const float4*>(&A[(size_t)(bm + row) * K + k0 + kc]);
            As[kc + 0][row] = v.x; As[kc + 1][row] = v.y;
            As[kc + 2][row] = v.z; As[kc + 3][row] = v.w;
        }
        for (int f = tid; f < B_F4; f += THREADS) {
            int row = f / (BK / 4);
            int kc = (f % (BK / 4)) * 4;
            float4 v = *reinterpret_cast<const float4*>(&B[(size_t)(bn + row) * K + k0 + kc]);
            Bs[kc + 0][row] = v.x; Bs[kc + 1][row] = v.y;
            Bs[kc + 2][row] = v.z; Bs[kc + 3][row] = v.w;
        }
        __syncthreads();
#pragma unroll
        for (int kk = 0; kk < BK; kk++) {
            float af[TM], bf[TN];
#pragma unroll
            for (int i = 0; i < TM; i++) af[i] = As[kk][ty * TM + i];
#pragma unroll
            for (int j = 0; j < TN; j++) bf[j] = Bs[kk][tx * TN + j];
#pragma unroll
            for (int i = 0; i < TM; i++)
#pragma unroll
                for (int j = 0; j < TN; j++) acc[i][j] += af[i] * bf[j];
        }
        __syncthreads();
    }
#pragma unroll
    for (int i = 0; i < TM; i++) {
        int m = bm + ty * TM + i;
#pragma unroll
        for (int j = 0; j < TN; j++) {
            int n = bn + tx * TN + j;
            float v = acc[i][j];
            if (USE_SCALE) v *= scale;
            if (BIAS) v += bias[n];
            size_t idx = (size_t)m * N + n;
            if (ACCUM) v += C[idx];
            if (ADDAUX) v += aux[idx];
            if (RELU) v = fmaxf(v, 0.f);
            C[idx] = v;
        }
    }
}

// ---------------------------------------------------------------------------
// Slot attention: per slot s (block): over 65536 logits compute max, Z, top-10
// then updates[s] = sum_i w_i * vv[idx_i], with w = (softmax+eps)/(1+N*eps).
// Writes e2cat[s] = concat(e[s], updates[s]).
// ---------------------------------------------------------------------------
__global__ void slot_attend(const float* __restrict__ S1, const float* __restrict__ vv,
                            const float* __restrict__ e, float* __restrict__ e2cat) {
    __shared__ float sv[256 * KTOP];
    __shared__ int   si[256 * KTOP];
    __shared__ float red[256];
    __shared__ float sw[KTOP];
    __shared__ int   sx[KTOP];
    int s = blockIdx.x, tid = threadIdx.x;
    const float* row = S1 + (size_t)s * N_NODES;
    float tv[KTOP]; int ti[KTOP];
#pragma unroll
    for (int i = 0; i < KTOP; i++) { tv[i] = -INFINITY; ti[i] = 0; }
    for (int n = tid; n < N_NODES; n += 256) {
        float v = row[n];
        if (v > tv[KTOP - 1]) {
            int ix = n;
#pragma unroll
            for (int p = 0; p < KTOP; p++)
                if (v > tv[p]) {
                    float tf = tv[p]; tv[p] = v; v = tf;
                    int tt = ti[p]; ti[p] = ix; ix = tt;
                }
        }
    }
#pragma unroll
    for (int i = 0; i < KTOP; i++) { sv[tid * KTOP + i] = tv[i]; si[tid * KTOP + i] = ti[i]; }
    __syncthreads();
    for (int stride = 128; stride >= 1; stride >>= 1) {
        if (tid < stride) {
#pragma unroll
            for (int i = 0; i < KTOP; i++) { tv[i] = sv[tid * KTOP + i]; ti[i] = si[tid * KTOP + i]; }
#pragma unroll
            for (int i = 0; i < KTOP; i++) {
                float v = sv[(tid + stride) * KTOP + i];
                int ix = si[(tid + stride) * KTOP + i];
                if (v > tv[KTOP - 1]) {
#pragma unroll
                    for (int p = 0; p < KTOP; p++)
                        if (v > tv[p]) {
                            float tf = tv[p]; tv[p] = v; v = tf;
                            int tt = ti[p]; ti[p] = ix; ix = tt;
                        }
                }
            }
#pragma unroll
            for (int i = 0; i < KTOP; i++) { sv[tid * KTOP + i] = tv[i]; si[tid * KTOP + i] = ti[i]; }
        }
        __syncthreads();
    }
    float maxv = sv[0];
    float z = 0.f;
    for (int n = tid; n < N_NODES; n += 256) z += expf(row[n] - maxv);
    red[tid] = z;
    __syncthreads();
    for (int st = 128; st >= 1; st >>= 1) {
        if (tid < st) red[tid] += red[tid + st];
        __syncthreads();
    }
    float Z = red[0];
    if (tid < KTOP) {
        float p = expf(sv[tid] - maxv) / Z;
        sw[tid] = (p + EPSC) / (1.f + (float)N_NODES * EPSC);
        sx[tid] = si[tid];
    }
    __syncthreads();
    float acc = 0.f;
#pragma unroll
    for (int i = 0; i < KTOP; i++) acc += sw[i] * vv[(size_t)sx[i] * D + tid];
    e2cat[(size_t)s * 2 * D + D + tid] = acc;
    e2cat[(size_t)s * 2 * D + tid] = e[(size_t)s * D + tid];
}

// ---------------------------------------------------------------------------
// Node attention: one warp per node. 512 logits -> max, Z, top-10 ->
// nodes[n] = sum_i softmax_i * edg[idx_i]   (H values = softmax, masked)
// ---------------------------------------------------------------------------
__global__ void node_attend(const float* __restrict__ S2, const float* __restrict__ edg,
                            float* __restrict__ nodes) {
    int warp = blockIdx.x * (blockDim.x >> 5) + (threadIdx.x >> 5);
    int lane = threadIdx.x & 31;
    const float* row = S2 + (size_t)warp * NS;
    float dv[16];
#pragma unroll
    for (int j = 0; j < 16; j++) dv[j] = row[lane + 32 * j];
    float tv[KTOP]; int ti[KTOP];
#pragma unroll
    for (int i = 0; i < KTOP; i++) { tv[i] = -INFINITY; ti[i] = 0; }
#pragma unroll
    for (int j = 0; j < 16; j++) {
        float v = dv[j]; int ix = lane + 32 * j;
        if (v > tv[KTOP - 1]) {
#pragma unroll
            for (int p = 0; p < KTOP; p++)
                if (v > tv[p]) {
                    float tf = tv[p]; tv[p] = v; v = tf;
                    int tt = ti[p]; ti[p] = ix; ix = tt;
                }
        }
    }
#pragma unroll
    for (int st = 16; st >= 1; st >>= 1) {
        float ov[KTOP]; int oi[KTOP];
#pragma unroll
        for (int i = 0; i < KTOP; i++) {
            ov[i] = __shfl_down_sync(0xffffffffu, tv[i], st);
            oi[i] = __shfl_down_sync(0xffffffffu, ti[i], st);
        }
#pragma unroll
        for (int i = 0; i < KTOP; i++) {
            float v = ov[i]; int ix = oi[i];
            if (v > tv[KTOP - 1]) {
#pragma unroll
                for (int p = 0; p < KTOP; p++)
                    if (v > tv[p]) {
                        float tf = tv[p]; tv[p] = v; v = tf;
                        int tt = ti[p]; ti[p] = ix; ix = tt;
                    }
            }
        }
    }
    float maxv = __shfl_sync(0xffffffffu, tv[0], 0);
    float z = 0.f;
#pragma unroll
    for (int j = 0; j < 16; j++) z += expf(dv[j] - maxv);
#pragma unroll
    for (int st = 16; st; st >>= 1) z += __shfl_xor_sync(0xffffffffu, z, st);
    float zin = 1.f / z;
    float w_[KTOP]; int ix_[KTOP];
#pragma unroll
    for (int i = 0; i < KTOP; i++) {
        float v = __shfl_sync(0xffffffffu, tv[i], 0);
        ix_[i] = __shfl_sync(0xffffffffu, ti[i], 0);
        w_[i] = expf(v - maxv) * zin;
    }
    float* po = nodes + (size_t)warp * D;
#pragma unroll
    for (int j = 0; j < 8; j++) {
        int c = lane + 32 * j;
        float acc = 0.f;
#pragma unroll
        for (int i = 0; i < KTOP; i++) acc += w_[i] * edg[(size_t)ix_[i] * D + c];
        po[c] = acc;
    }
}

// ---------------------------------------------------------------------------
// Launch
// ---------------------------------------------------------------------------
extern "C" void kernel_launch(void* const* d_in, const int* in_sizes, int n_in,
                              void* d_out, int out_size) {
    (void)in_sizes; (void)n_in; (void)out_size;
    const float* x      = (const float*)d_in[0];
    const float* enoise = (const float*)d_in[1];
    const float* emu    = (const float*)d_in[2];
    const float* elog   = (const float*)d_in[3];
    const float* lnw    = (const float*)d_in[4];
    const float* lnb    = (const float*)d_in[5];
    const float* lew    = (const float*)d_in[6];
    const float* leb    = (const float*)d_in[7];
    const float* Wq = (const float*)d_in[8];  const float* bq = (const float*)d_in[9];
    const float* Wk = (const float*)d_in[10]; const float* bk = (const float*)d_in[11];
    const float* Wv = (const float*)d_in[12]; const float* bv = (const float*)d_in[13];
    const float* Wm1 = (const float*)d_in[14]; const float* bm1 = (const float*)d_in[15];
    const float* Wm2 = (const float*)d_in[16]; const float* bm2 = (const float*)d_in[17];
    const float* cw = (const float*)d_in[18];  const float* cb = (const float*)d_in[19];
    const float* Wc0 = (const float*)d_in[20]; const float* bc0 = (const float*)d_in[21];
    const float* Wc1 = (const float*)d_in[22]; const float* bc1 = (const float*)d_in[23];
    const float* Wt = (const float*)d_in[24];  const float* bt = (const float*)d_in[25];
    float* out = (float*)d_out;

    void* p;
    cudaGetSymbolAddress(&p, g_xin);   float* xin = (float*)p;
    cudaGetSymbolAddress(&p, g_kk);    float* kkb = (float*)p;
    cudaGetSymbolAddress(&p, g_vv);    float* vvb = (float*)p;
    cudaGetSymbolAddress(&p, g_q2);    float* q2b = (float*)p;
    cudaGetSymbolAddress(&p, g_nodes); float* nodesb = (float*)p;
    cudaGetSymbolAddress(&p, g_tmp);   float* tmp = (float*)p;
    cudaGetSymbolAddress(&p, g_S);     float* S = (float*)p;
    cudaGetSymbolAddress(&p, g_e);     float* e = (float*)p;
    cudaGetSymbolAddress(&p, g_q);     float* qb = (float*)p;
    cudaGetSymbolAddress(&p, g_e2cat); float* e2cat = (float*)p;
    cudaGetSymbolAddress(&p, g_h1);    float* h1 = (float*)p;
    cudaGetSymbolAddress(&p, g_e2);    float* e2 = (float*)p;
    cudaGetSymbolAddress(&p, g_k2);    float* k2 = (float*)p;
    cudaGetSymbolAddress(&p, g_edg);   float* edg = (float*)p;
    cudaGetSymbolAddress(&p, g_WqT);   float* WqT = (float*)p;
    cudaGetSymbolAddress(&p, g_WkT);   float* WkT = (float*)p;
    cudaGetSymbolAddress(&p, g_WvT);   float* WvT = (float*)p;
    cudaGetSymbolAddress(&p, g_Wm1T);  float* Wm1T = (float*)p;
    cudaGetSymbolAddress(&p, g_Wm2T);  float* Wm2T = (float*)p;
    cudaGetSymbolAddress(&p, g_cwT);   float* cwT = (float*)p;
    cudaGetSymbolAddress(&p, g_Wc0T);  float* Wc0T = (float*)p;
    cudaGetSymbolAddress(&p, g_Wc1T);  float* Wc1T = (float*)p;
    cudaGetSymbolAddress(&p, g_WtT);   float* WtT = (float*)p;

    dim3 tb(32, 8);
    transpose_k<<<dim3(8, 8), tb>>>(Wq, WqT, D, D);
    transpose_k<<<dim3(8, 8), tb>>>(Wk, WkT, D, D);
    transpose_k<<<dim3(8, 8), tb>>>(Wv, WvT, D, D);
    transpose_k<<<dim3(8, 16), tb>>>(Wm1, Wm1T, 2 * D, HID);
    transpose_k<<<dim3(8, 8), tb>>>(Wm2, Wm2T, HID, D);
    transpose_k<<<dim3(8, 8), tb>>>(cw, cwT, D, D);
    transpose_k<<<dim3(8, 8), tb>>>(Wc0, Wc0T, D, D);
    transpose_k<<<dim3(8, 8), tb>>>(Wc1, Wc1T, D, D);
    transpose_k<<<dim3(8, 8), tb>>>(Wt, WtT, D, D);

    ln_rows<<<N_NODES / 8, 256>>>(x, lnw, lnb, xin, N_NODES);
    edges_ln<<<NS / 8, 256>>>(enoise, emu, elog, lew, leb, e);

    // kk = relu(xin@Wk+bk), vv = relu(xin@Wv+bv), q2 = xin@Wq+bq
    gemm_nt<128, 128, 16, 8, 8, false, true, true, false, false>
        <<<dim3(D / 128, N_NODES / 128), 256>>>(xin, WkT, kkb, bk, nullptr, N_NODES, D, D, 1.f);
    gemm_nt<128, 128, 16, 8, 8, false, true, true, false, false>
        <<<dim3(D / 128, N_NODES / 128), 256>>>(xin, WvT, vvb, bv, nullptr, N_NODES, D, D, 1.f);
    gemm_nt<128, 128, 16, 8, 8, false, true, false, false, false>
        <<<dim3(D / 128, N_NODES / 128), 256>>>(xin, WqT, q2b, bq, nullptr, N_NODES, D, D, 1.f);

    // q = relu(e@Wq+bq)
    gemm_nt<64, 64, 16, 4, 4, false, true, true, false, false>
        <<<dim3(D / 64, NS / 64), 256>>>(e, WqT, qb, bq, nullptr, NS, D, D, 1.f);

    // dots1 = q @ kk^T * SCALE   -> S [NS, N]
    gemm_nt<128, 128, 16, 8, 8, true, false, false, false, false>
        <<<dim3(N_NODES / 128, NS / 128), 256>>>(qb, kkb, S, nullptr, nullptr, NS, N_NODES, D, SCALE_C);

    slot_attend<<<NS, 256>>>(S, vvb, e, e2cat);

    // slot MLP: h1 = relu(e2cat@Wm1+bm1); e2 = h1@Wm2+bm2
    gemm_nt<64, 64, 16, 4, 4, false, true, true, false, false>
        <<<dim3(HID / 64, NS / 64), 256>>>(e2cat, Wm1T, h1, bm1, nullptr, NS, HID, 2 * D, 1.f);
    gemm_nt<64, 64, 16, 4, 4, false, true, false, false, false>
        <<<dim3(D / 64, NS / 64), 256>>>(h1, Wm2T, e2, bm2, nullptr, NS, D, HID, 1.f);

    // k2 = relu(e2@Wk+bk); edg = e2@conv_w+conv_b
    gemm_nt<64, 64, 16, 4, 4, false, true, true, false, false>
        <<<dim3(D / 64, NS / 64), 256>>>(e2, WkT, k2, bk, nullptr, NS, D, D, 1.f);
    gemm_nt<64, 64, 16, 4, 4, false, true, false, false, false>
        <<<dim3(D / 64, NS / 64), 256>>>(e2, cwT, edg, cb, nullptr, NS, D, D, 1.f);

    // dots2 = q2 @ k2^T * SCALE  -> S [N, NS]
    gemm_nt<128, 128, 16, 8, 8, true, false, false, false, false>
        <<<dim3(NS / 128, N_NODES / 128), 256>>>(q2b, k2, S, nullptr, nullptr, N_NODES, NS, D, SCALE_C);

    node_attend<<<N_NODES / 8, 256>>>(S, edg, nodesb);

    // tmp = x@Wc0 + bc0
    gemm_nt<128, 128, 16, 8, 8, false, true, false, false, false>
        <<<dim3(D / 128, N_NODES / 128), 256>>>(x, Wc0T, tmp, bc0, nullptr, N_NODES, D, D, 1.f);
    // tmp = relu(tmp + nodes@Wc1 + bc1 + nodes)
    gemm_nt<128, 128, 16, 8, 8, false, true, true, true, true>
        <<<dim3(D / 128, N_NODES / 128), 256>>>(nodesb, Wc1T, tmp, bc1, nodesb, N_NODES, D, D, 1.f);
    // out = relu(tmp@Wt + bt)
    gemm_nt<128, 128, 16, 8, 8, false, true, true, false, false>
        <<<dim3(D / 128, N_NODES / 128), 256>>>(tmp, WtT, out, bt, nullptr, N_NODES, D, D, 1.f);
}

// round 3
// speedup vs baseline: 2.3442x; 2.3442x over previous
#include <cuda_runtime.h>
#include <math.h>
#include <stdint.h>

#define N_NODES 65536
#define D       256
#define NS      512
#define HID     256
#define KTOP    10
#define EPSC    1e-8f
#define SCALE_C 0.0625f  /* 256^-0.5 */

// ---------------------------------------------------------------------------
// Scratch (static __device__ arrays; no allocation anywhere)
// ---------------------------------------------------------------------------
__device__ float g_xin  [(size_t)N_NODES * D];
__device__ float g_kk   [(size_t)N_NODES * D];
__device__ float g_vv   [(size_t)N_NODES * D];
__device__ float g_q2   [(size_t)N_NODES * D];
__device__ float g_nodes[(size_t)N_NODES * D];
__device__ float g_tmp  [(size_t)N_NODES * D];
__device__ float g_S    [(size_t)N_NODES * NS];   // dots1 [NS,N] then dots2 [N,NS]

__device__ float g_e    [NS * D];
__device__ float g_q    [NS * D];
__device__ float g_e2cat[NS * 2 * D];
__device__ float g_h1   [NS * HID];
__device__ float g_e2   [NS * D];
__device__ float g_k2   [NS * D];
__device__ float g_edg  [NS * D];

__device__ float g_WqT [D * D];
__device__ float g_WkT [D * D];
__device__ float g_WvT [D * D];
__device__ float g_Wm1T[HID * 2 * D];
__device__ float g_Wm2T[D * HID];
__device__ float g_cwT [D * D];
__device__ float g_Wc0T[D * D];
__device__ float g_Wc1T[D * D];
__device__ float g_WtT [D * D];

// ---------------------------------------------------------------------------
// tf32 helpers
// ---------------------------------------------------------------------------
__device__ __forceinline__ uint32_t f2tf32(float f) {
    uint32_t r;
    asm("cvt.rna.tf32.f32 %0, %1;" : "=r"(r) : "f"(f));
    return r;
}
__device__ __forceinline__ void mma16n8k8(float& c0, float& c1, float& c2, float& c3,
                                          uint32_t a0, uint32_t a1, uint32_t a2, uint32_t a3,
                                          uint32_t b0, uint32_t b1) {
    asm volatile(
        "mma.sync.aligned.m16n8k8.row.col.f32.tf32.tf32.f32 "
        "{%0,%1,%2,%3}, {%4,%5,%6,%7}, {%8,%9}, {%0,%1,%2,%3};"
        : "+f"(c0), "+f"(c1), "+f"(c2), "+f"(c3)
        : "r"(a0), "r"(a1), "r"(a2), "r"(a3), "r"(b0), "r"(b1));
}

// ---------------------------------------------------------------------------
// Tensor-core tf32 NT GEMM: C[m,n] = epi( sum_k A[m,k]*B[n,k] )
// A:[M,K] rowmajor, B:[Ntot,K] rowmajor. 128x128x32 block tile, 8 warps.
// Warp tile 32(M) x 64(N) = 2x8 m16n8k8 fragments.
// EPI: 0 = *scale, 1 = +bias, 2 = relu(+bias), 3 = relu(+bias + C + aux)
// ---------------------------------------------------------------------------
#define LDA 36   // 32 + 4 pad
template <int EPI>
__global__ void __launch_bounds__(256) mma_gemm(
    const float* __restrict__ A, const float* __restrict__ B,
    float* __restrict__ C, const float* __restrict__ bias,
    const float* __restrict__ aux, int M, int Ntot, int K, float scale) {
    __shared__ uint32_t As[128 * LDA];
    __shared__ uint32_t Bs[128 * LDA];
    const int tid = threadIdx.x;
    const int wid = tid >> 5, lane = tid & 31;
    const int warp_m = wid & 3;        // 0..3  -> 32-row slice
    const int warp_n = wid >> 2;       // 0..1  -> 64-col slice
    const int bm = blockIdx.y * 128;
    const int bn = blockIdx.x * 128;
    const int grp = lane >> 2;         // 0..7
    const int tig = lane & 3;          // 0..3

    float acc[2][8][4];
#pragma unroll
    for (int i = 0; i < 2; i++)
#pragma unroll
        for (int j = 0; j < 8; j++)
#pragma unroll
            for (int r = 0; r < 4; r++) acc[i][j][r] = 0.f;

    for (int k0 = 0; k0 < K; k0 += 32) {
        // load 128x32 tiles, convert to tf32, store to padded SMEM
#pragma unroll
        for (int i = 0; i < 4; i++) {
            int s = tid + (i << 8);            // 0..1023
            int row = s >> 3, c4 = (s & 7) << 2;
            float4 v = *reinterpret_cast<const float4*>(A + (size_t)(bm + row) * K + k0 + c4);
            uint32_t* d = &As[row * LDA + c4];
            d[0] = f2tf32(v.x); d[1] = f2tf32(v.y); d[2] = f2tf32(v.z); d[3] = f2tf32(v.w);
        }
#pragma unroll
        for (int i = 0; i < 4; i++) {
            int s = tid + (i << 8);
            int row = s >> 3, c4 = (s & 7) << 2;
            float4 v = *reinterpret_cast<const float4*>(B + (size_t)(bn + row) * K + k0 + c4);
            uint32_t* d = &Bs[row * LDA + c4];
            d[0] = f2tf32(v.x); d[1] = f2tf32(v.y); d[2] = f2tf32(v.z); d[3] = f2tf32(v.w);
        }
        __syncthreads();
#pragma unroll
        for (int ks = 0; ks < 32; ks += 8) {
            uint32_t af[2][4];
#pragma unroll
            for (int mt = 0; mt < 2; mt++) {
                int m = warp_m * 32 + mt * 16 + grp;
                af[mt][0] = As[m * LDA + ks + tig];
                af[mt][1] = As[(m + 8) * LDA + ks + tig];
                af[mt][2] = As[m * LDA + ks + tig + 4];
                af[mt][3] = As[(m + 8) * LDA + ks + tig + 4];
            }
#pragma unroll
            for (int nt = 0; nt < 8; nt++) {
                int n = warp_n * 64 + nt * 8 + grp;
                uint32_t b0 = Bs[n * LDA + ks + tig];
                uint32_t b1 = Bs[n * LDA + ks + tig + 4];
#pragma unroll
                for (int mt = 0; mt < 2; mt++)
                    mma16n8k8(acc[mt][nt][0], acc[mt][nt][1], acc[mt][nt][2], acc[mt][nt][3],
                              af[mt][0], af[mt][1], af[mt][2], af[mt][3], b0, b1);
            }
        }
        __syncthreads();
    }

    // epilogue
#pragma unroll
    for (int mt = 0; mt < 2; mt++) {
        int r0 = bm + warp_m * 32 + mt * 16 + grp;
#pragma unroll
        for (int nt = 0; nt < 8; nt++) {
            int c0 = bn + warp_n * 64 + nt * 8 + 2 * tig;
#pragma unroll
            for (int half = 0; half < 2; half++) {
                int rr = r0 + half * 8;
                float vx = acc[mt][nt][2 * half + 0];
                float vy = acc[mt][nt][2 * half + 1];
                size_t idx = (size_t)rr * Ntot + c0;
                if constexpr (EPI == 0) {
                    vx *= scale; vy *= scale;
                } else {
                    vx += bias[c0]; vy += bias[c0 + 1];
                    if constexpr (EPI == 3) {
                        float2 cc = *reinterpret_cast<const float2*>(C + idx);
                        float2 aa = *reinterpret_cast<const float2*>(aux + idx);
                        vx += cc.x + aa.x; vy += cc.y + aa.y;
                    }
                    if constexpr (EPI >= 2) { vx = fmaxf(vx, 0.f); vy = fmaxf(vy, 0.f); }
                }
                float2 o; o.x = vx; o.y = vy;
                *reinterpret_cast<float2*>(C + idx) = o;
            }
        }
    }
}

// ---------------------------------------------------------------------------
// Transpose [R,C] -> [C,R]
// ---------------------------------------------------------------------------
__global__ void transpose_k(const float* __restrict__ in, float* __restrict__ out,
                            int R, int C) {
    __shared__ float tile[32][33];
    int bx = blockIdx.x * 32, by = blockIdx.y * 32;
    int x = threadIdx.x;
    for (int y = threadIdx.y; y < 32; y += 8)
        tile[y][x] = in[(size_t)(by + y) * C + bx + x];
    __syncthreads();
    for (int y = threadIdx.y; y < 32; y += 8)
        out[(size_t)(bx + y) * R + by + x] = tile[x][y];
}

// ---------------------------------------------------------------------------
// LayerNorm: one warp per row of 256
// ---------------------------------------------------------------------------
__global__ void ln_rows(const float* __restrict__ x, const float* __restrict__ w,
                        const float* __restrict__ b, float* __restrict__ o, int M) {
    int warp = (blockIdx.x * blockDim.x + threadIdx.x) >> 5;
    int lane = threadIdx.x & 31;
    if (warp >= M) return;
    const float* r = x + (size_t)warp * D;
    float v[8]; float s = 0.f;
#pragma unroll
    for (int j = 0; j < 8; j++) { v[j] = r[lane + 32 * j]; s += v[j]; }
#pragma unroll
    for (int st = 16; st; st >>= 1) s += __shfl_xor_sync(0xffffffffu, s, st);
    float mu = s * (1.f / 256.f);
    float q = 0.f;
#pragma unroll
    for (int j = 0; j < 8; j++) { float d = v[j] - mu; q += d * d; }
#pragma unroll
    for (int st = 16; st; st >>= 1) q += __shfl_xor_sync(0xffffffffu, q, st);
    float rinv = rsqrtf(q * (1.f / 256.f) + 1e-5f);
    float* po = o + (size_t)warp * D;
#pragma unroll
    for (int j = 0; j < 8; j++) {
        int c = lane + 32 * j;
        po[c] = (v[j] - mu) * rinv * w[c] + b[c];
    }
}

// edges = mu + exp(logsigma)*noise, then LN
__global__ void edges_ln(const float* __restrict__ noise, const float* __restrict__ emu,
                         const float* __restrict__ elog, const float* __restrict__ w,
                         const float* __restrict__ b, float* __restrict__ o) {
    int warp = (blockIdx.x * blockDim.x + threadIdx.x) >> 5;
    int lane = threadIdx.x & 31;
    if (warp >= NS) return;
    const float* r = noise + (size_t)warp * D;
    float v[8]; float s = 0.f;
#pragma unroll
    for (int j = 0; j < 8; j++) {
        int c = lane + 32 * j;
        v[j] = emu[c] + expf(elog[c]) * r[c];
        s += v[j];
    }
#pragma unroll
    for (int st = 16; st; st >>= 1) s += __shfl_xor_sync(0xffffffffu, s, st);
    float mu = s * (1.f / 256.f);
    float q = 0.f;
#pragma unroll
    for (int j = 0; j < 8; j++) { float d = v[j] - mu; q += d * d; }
#pragma unroll
    for (int st = 16; st; st >>= 1) q += __shfl_xor_sync(0xffffffffu, q, st);
    float rinv = rsqrtf(q * (1.f / 256.f) + 1e-5f);
    float* po = o + (size_t)warp * D;
#pragma unroll
    for (int j = 0; j < 8; j++) {
        int c = lane + 32 * j;
        po[c] = (v[j] - mu) * rinv * w[c] + b[c];
    }
}

// ---------------------------------------------------------------------------
// Small fp32 NT GEMM (NS-sized ops only): 64x64 tile
// ---------------------------------------------------------------------------
template <bool BIAS, bool RELU>
__global__ void gemm_small(const float* __restrict__ A, const float* __restrict__ B,
                           float* __restrict__ C, const float* __restrict__ bias,
                           int M, int N, int K) {
    constexpr int BM = 64, BN = 64, BK = 16, TM = 4, TN = 4;
    constexpr int THREADS = 256;
    __shared__ float As[BK][BM + 4];
    __shared__ float Bs[BK][BN + 4];
    const int bm = blockIdx.y * BM;
    const int bn = blockIdx.x * BN;
    const int tid = threadIdx.x;
    const int tx = tid % (BN / TN);
    const int ty = tid / (BN / TN);
    float acc[TM][TN];
#pragma unroll
    for (int i = 0; i < TM; i++)
#pragma unroll
        for (int j = 0; j < TN; j++) acc[i][j] = 0.f;

    constexpr int A_F4 = BM * BK / 4;
    for (int k0 = 0; k0 < K; k0 += BK) {
        for (int f = tid; f < A_F4; f += THREADS) {
            int row = f / (BK / 4);
            int kc = (f % (BK / 4)) * 4;
            float4 v = *reinterpret_cast<const float4*>(&A[(size_t)(bm + row) * K + k0 + kc]);
            As[kc + 0][row] = v.x; As[kc + 1][row] = v.y;
            As[kc + 2][row] = v.z; As[kc + 3][row] = v.w;
        }
        for (int f = tid; f < A_F4; f += THREADS) {
            int row = f / (BK / 4);
            int kc = (f % (BK / 4)) * 4;
            float4 v = *reinterpret_cast<const float4*>(&B[(size_t)(bn + row) * K + k0 + kc]);
            Bs[kc + 0][row] = v.x; Bs[kc + 1][row] = v.y;
            Bs[kc + 2][row] = v.z; Bs[kc + 3][row] = v.w;
        }
        __syncthreads();
#pragma unroll
        for (int kk = 0; kk < BK; kk++) {
            float af[TM], bf[TN];
#pragma unroll
            for (int i = 0; i < TM; i++) af[i] = As[kk][ty * TM + i];
#pragma unroll
            for (int j = 0; j < TN; j++) bf[j] = Bs[kk][tx * TN + j];
#pragma unroll
            for (int i = 0; i < TM; i++)
#pragma unroll
                for (int j = 0; j < TN; j++) acc[i][j] += af[i] * bf[j];
        }
        __syncthreads();
    }
#pragma unroll
    for (int i = 0; i < TM; i++) {
        int m = bm + ty * TM + i;
#pragma unroll
        for (int j = 0; j < TN; j++) {
            int n = bn + tx * TN + j;
            float v = acc[i][j];
            if (BIAS) v += bias[n];
            if (RELU) v = fmaxf(v, 0.f);
            C[(size_t)m * N + n] = v;
        }
    }
}

// ---------------------------------------------------------------------------
// Slot attention: per slot s (block): over 65536 logits -> max, Z, top-10 ->
// updates[s] = sum_i w_i * vv[idx_i]; e2cat[s] = concat(e[s], updates[s]).
// ---------------------------------------------------------------------------
__global__ void slot_attend(const float* __restrict__ S1, const float* __restrict__ vv,
                            const float* __restrict__ e, float* __restrict__ e2cat) {
    __shared__ float sv[256 * KTOP];
    __shared__ int   si[256 * KTOP];
    __shared__ float red[256];
    __shared__ float sw[KTOP];
    __shared__ int   sx[KTOP];
    int s = blockIdx.x, tid = threadIdx.x;
    const float* row = S1 + (size_t)s * N_NODES;
    float tv[KTOP]; int ti[KTOP];
#pragma unroll
    for (int i = 0; i < KTOP; i++) { tv[i] = -INFINITY; ti[i] = 0; }
    for (int n = tid; n < N_NODES; n += 256) {
        float v = row[n];
        if (v > tv[KTOP - 1]) {
            int ix = n;
#pragma unroll
            for (int p = 0; p < KTOP; p++)
                if (v > tv[p]) {
                    float tf = tv[p]; tv[p] = v; v = tf;
                    int tt = ti[p]; ti[p] = ix; ix = tt;
                }
        }
    }
#pragma unroll
    for (int i = 0; i < KTOP; i++) { sv[tid * KTOP + i] = tv[i]; si[tid * KTOP + i] = ti[i]; }
    __syncthreads();
    for (int stride = 128; stride >= 1; stride >>= 1) {
        if (tid < stride) {
#pragma unroll
            for (int i = 0; i < KTOP; i++) { tv[i] = sv[tid * KTOP + i]; ti[i] = si[tid * KTOP + i]; }
#pragma unroll
            for (int i = 0; i < KTOP; i++) {
                float v = sv[(tid + stride) * KTOP + i];
                int ix = si[(tid + stride) * KTOP + i];
                if (v > tv[KTOP - 1]) {
#pragma unroll
                    for (int p = 0; p < KTOP; p++)
                        if (v > tv[p]) {
                            float tf = tv[p]; tv[p] = v; v = tf;
                            int tt = ti[p]; ti[p] = ix; ix = tt;
                        }
                }
            }
#pragma unroll
            for (int i = 0; i < KTOP; i++) { sv[tid * KTOP + i] = tv[i]; si[tid * KTOP + i] = ti[i]; }
        }
        __syncthreads();
    }
    float maxv = sv[0];
    float z = 0.f;
    for (int n = tid; n < N_NODES; n += 256) z += expf(row[n] - maxv);
    red[tid] = z;
    __syncthreads();
    for (int st = 128; st >= 1; st >>= 1) {
        if (tid < st) red[tid] += red[tid + st];
        __syncthreads();
    }
    float Z = red[0];
    if (tid < KTOP) {
        float p = expf(sv[tid] - maxv) / Z;
        sw[tid] = (p + EPSC) / (1.f + (float)N_NODES * EPSC);
        sx[tid] = si[tid];
    }
    __syncthreads();
    float acc = 0.f;
#pragma unroll
    for (int i = 0; i < KTOP; i++) acc += sw[i] * vv[(size_t)sx[i] * D + tid];
    e2cat[(size_t)s * 2 * D + D + tid] = acc;
    e2cat[(size_t)s * 2 * D + tid] = e[(size_t)s * D + tid];
}

// ---------------------------------------------------------------------------
// Node attention: one warp per node. 512 logits -> max, Z, top-10 ->
// nodes[n] = sum_i softmax_i * edg[idx_i]
// ---------------------------------------------------------------------------
__global__ void node_attend(const float* __restrict__ S2, const float* __restrict__ edg,
                            float* __restrict__ nodes) {
    int warp = blockIdx.x * (blockDim.x >> 5) + (threadIdx.x >> 5);
    int lane = threadIdx.x & 31;
    const float* row = S2 + (size_t)warp * NS;
    float dv[16];
#pragma unroll
    for (int j = 0; j < 16; j++) dv[j] = row[lane + 32 * j];
    float tv[KTOP]; int ti[KTOP];
#pragma unroll
    for (int i = 0; i < KTOP; i++) { tv[i] = -INFINITY; ti[i] = 0; }
#pragma unroll
    for (int j = 0; j < 16; j++) {
        float v = dv[j]; int ix = lane + 32 * j;
        if (v > tv[KTOP - 1]) {
#pragma unroll
            for (int p = 0; p < KTOP; p++)
                if (v > tv[p]) {
                    float tf = tv[p]; tv[p] = v; v = tf;
                    int tt = ti[p]; ti[p] = ix; ix = tt;
                }
        }
    }
#pragma unroll
    for (int st = 16; st >= 1; st >>= 1) {
        float ov[KTOP]; int oi[KTOP];
#pragma unroll
        for (int i = 0; i < KTOP; i++) {
            ov[i] = __shfl_down_sync(0xffffffffu, tv[i], st);
            oi[i] = __shfl_down_sync(0xffffffffu, ti[i], st);
        }
#pragma unroll
        for (int i = 0; i < KTOP; i++) {
            float v = ov[i]; int ix = oi[i];
            if (v > tv[KTOP - 1]) {
#pragma unroll
                for (int p = 0; p < KTOP; p++)
                    if (v > tv[p]) {
                        float tf = tv[p]; tv[p] = v; v = tf;
                        int tt = ti[p]; ti[p] = ix; ix = tt;
                    }
            }
        }
    }
    float maxv = __shfl_sync(0xffffffffu, tv[0], 0);
    float z = 0.f;
#pragma unroll
    for (int j = 0; j < 16; j++) z += expf(dv[j] - maxv);
#pragma unroll
    for (int st = 16; st; st >>= 1) z += __shfl_xor_sync(0xffffffffu, z, st);
    float zin = 1.f / z;
    float w_[KTOP]; int ix_[KTOP];
#pragma unroll
    for (int i = 0; i < KTOP; i++) {
        float v = __shfl_sync(0xffffffffu, tv[i], 0);
        ix_[i] = __shfl_sync(0xffffffffu, ti[i], 0);
        w_[i] = expf(v - maxv) * zin;
    }
    float* po = nodes + (size_t)warp * D;
#pragma unroll
    for (int j = 0; j < 8; j++) {
        int c = lane + 32 * j;
        float acc = 0.f;
#pragma unroll
        for (int i = 0; i < KTOP; i++) acc += w_[i] * edg[(size_t)ix_[i] * D + c];
        po[c] = acc;
    }
}

// ---------------------------------------------------------------------------
// Launch
// ---------------------------------------------------------------------------
extern "C" void kernel_launch(void* const* d_in, const int* in_sizes, int n_in,
                              void* d_out, int out_size) {
    (void)in_sizes; (void)n_in; (void)out_size;
    const float* x      = (const float*)d_in[0];
    const float* enoise = (const float*)d_in[1];
    const float* emu    = (const float*)d_in[2];
    const float* elog   = (const float*)d_in[3];
    const float* lnw    = (const float*)d_in[4];
    const float* lnb    = (const float*)d_in[5];
    const float* lew    = (const float*)d_in[6];
    const float* leb    = (const float*)d_in[7];
    const float* Wq = (const float*)d_in[8];  const float* bq = (const float*)d_in[9];
    const float* Wk = (const float*)d_in[10]; const float* bk = (const float*)d_in[11];
    const float* Wv = (const float*)d_in[12]; const float* bv = (const float*)d_in[13];
    const float* Wm1 = (const float*)d_in[14]; const float* bm1 = (const float*)d_in[15];
    const float* Wm2 = (const float*)d_in[16]; const float* bm2 = (const float*)d_in[17];
    const float* cw = (const float*)d_in[18];  const float* cb = (const float*)d_in[19];
    const float* Wc0 = (const float*)d_in[20]; const float* bc0 = (const float*)d_in[21];
    const float* Wc1 = (const float*)d_in[22]; const float* bc1 = (const float*)d_in[23];
    const float* Wt = (const float*)d_in[24];  const float* bt = (const float*)d_in[25];
    float* out = (float*)d_out;

    void* p;
    cudaGetSymbolAddress(&p, g_xin);   float* xin = (float*)p;
    cudaGetSymbolAddress(&p, g_kk);    float* kkb = (float*)p;
    cudaGetSymbolAddress(&p, g_vv);    float* vvb = (float*)p;
    cudaGetSymbolAddress(&p, g_q2);    float* q2b = (float*)p;
    cudaGetSymbolAddress(&p, g_nodes); float* nodesb = (float*)p;
    cudaGetSymbolAddress(&p, g_tmp);   float* tmp = (float*)p;
    cudaGetSymbolAddress(&p, g_S);     float* S = (float*)p;
    cudaGetSymbolAddress(&p, g_e);     float* e = (float*)p;
    cudaGetSymbolAddress(&p, g_q);     float* qb = (float*)p;
    cudaGetSymbolAddress(&p, g_e2cat); float* e2cat = (float*)p;
    cudaGetSymbolAddress(&p, g_h1);    float* h1 = (float*)p;
    cudaGetSymbolAddress(&p, g_e2);    float* e2 = (float*)p;
    cudaGetSymbolAddress(&p, g_k2);    float* k2 = (float*)p;
    cudaGetSymbolAddress(&p, g_edg);   float* edg = (float*)p;
    cudaGetSymbolAddress(&p, g_WqT);   float* WqT = (float*)p;
    cudaGetSymbolAddress(&p, g_WkT);   float* WkT = (float*)p;
    cudaGetSymbolAddress(&p, g_WvT);   float* WvT = (float*)p;
    cudaGetSymbolAddress(&p, g_Wm1T);  float* Wm1T = (float*)p;
    cudaGetSymbolAddress(&p, g_Wm2T);  float* Wm2T = (float*)p;
    cudaGetSymbolAddress(&p, g_cwT);   float* cwT = (float*)p;
    cudaGetSymbolAddress(&p, g_Wc0T);  float* Wc0T = (float*)p;
    cudaGetSymbolAddress(&p, g_Wc1T);  float* Wc1T = (float*)p;
    cudaGetSymbolAddress(&p, g_WtT);   float* WtT = (float*)p;

    dim3 tb(32, 8);
    transpose_k<<<dim3(8, 8), tb>>>(Wq, WqT, D, D);
    transpose_k<<<dim3(8, 8), tb>>>(Wk, WkT, D, D);
    transpose_k<<<dim3(8, 8), tb>>>(Wv, WvT, D, D);
    transpose_k<<<dim3(8, 16), tb>>>(Wm1, Wm1T, 2 * D, HID);
    transpose_k<<<dim3(8, 8), tb>>>(Wm2, Wm2T, HID, D);
    transpose_k<<<dim3(8, 8), tb>>>(cw, cwT, D, D);
    transpose_k<<<dim3(8, 8), tb>>>(Wc0, Wc0T, D, D);
    transpose_k<<<dim3(8, 8), tb>>>(Wc1, Wc1T, D, D);
    transpose_k<<<dim3(8, 8), tb>>>(Wt, WtT, D, D);

    ln_rows<<<N_NODES / 8, 256>>>(x, lnw, lnb, xin, N_NODES);
    edges_ln<<<NS / 8, 256>>>(enoise, emu, elog, lew, leb, e);

    // kk = relu(xin@Wk+bk), vv = relu(xin@Wv+bv), q2 = xin@Wq+bq   [tf32 mma]
    mma_gemm<2><<<dim3(2, 512), 256>>>(xin, WkT, kkb, bk, nullptr, N_NODES, D, D, 1.f);
    mma_gemm<2><<<dim3(2, 512), 256>>>(xin, WvT, vvb, bv, nullptr, N_NODES, D, D, 1.f);
    mma_gemm<1><<<dim3(2, 512), 256>>>(xin, WqT, q2b, bq, nullptr, N_NODES, D, D, 1.f);

    // q = relu(e@Wq+bq)   [small]
    gemm_small<true, true><<<dim3(4, 8), 256>>>(e, WqT, qb, bq, NS, D, D);

    // dots1 = q @ kk^T * SCALE  -> S [NS, N]   [tf32 mma]
    mma_gemm<0><<<dim3(512, 4), 256>>>(qb, kkb, S, nullptr, nullptr, NS, N_NODES, D, SCALE_C);

    slot_attend<<<NS, 256>>>(S, vvb, e, e2cat);

    // slot MLP: h1 = relu(e2cat@Wm1+bm1); e2 = h1@Wm2+bm2   [small]
    gemm_small<true, true><<<dim3(4, 8), 256>>>(e2cat, Wm1T, h1, bm1, NS, HID, 2 * D);
    gemm_small<true, false><<<dim3(4, 8), 256>>>(h1, Wm2T, e2, bm2, NS, D, HID);

    // k2 = relu(e2@Wk+bk); edg = e2@conv_w+conv_b   [small]
    gemm_small<true, true><<<dim3(4, 8), 256>>>(e2, WkT, k2, bk, NS, D, D);
    gemm_small<true, false><<<dim3(4, 8), 256>>>(e2, cwT, edg, cb, NS, D, D);

    // dots2 = q2 @ k2^T * SCALE  -> S [N, NS]   [tf32 mma]
    mma_gemm<0><<<dim3(4, 512), 256>>>(q2b, k2, S, nullptr, nullptr, N_NODES, NS, D, SCALE_C);

    node_attend<<<N_NODES / 8, 256>>>(S, edg, nodesb);

    // tmp = x@Wc0 + bc0   [tf32 mma]
    mma_gemm<1><<<dim3(2, 512), 256>>>(x, Wc0T, tmp, bc0, nullptr, N_NODES, D, D, 1.f);
    // tmp = relu(tmp + nodes@Wc1 + bc1 + nodes)   [tf32 mma]
    mma_gemm<3><<<dim3(2, 512), 256>>>(nodesb, Wc1T, tmp, bc1, nodesb, N_NODES, D, D, 1.f);
    // out = relu(tmp@Wt + bt)   [tf32 mma]
    mma_gemm<2><<<dim3(2, 512), 256>>>(tmp, WtT, out, bt, nullptr, N_NODES, D, D, 1.f);
}

// round 4
// speedup vs baseline: 2.5068x; 1.0693x over previous
#include <cuda_runtime.h>
#include <math.h>
#include <stdint.h>

#define N_NODES 65536
#define D       256
#define NS      512
#define HID     256
#define KTOP    10
#define EPSC    1e-8f
#define SCALE_C 0.0625f  /* 256^-0.5 */

// ---------------------------------------------------------------------------
// Scratch (static __device__ arrays; no allocation anywhere)
// ---------------------------------------------------------------------------
__device__ float g_xin  [(size_t)N_NODES * D];
__device__ float g_kk   [(size_t)N_NODES * D];
__device__ float g_vv   [(size_t)N_NODES * D];
__device__ float g_q2   [(size_t)N_NODES * D];
__device__ float g_nodes[(size_t)N_NODES * D];
__device__ float g_tmp  [(size_t)N_NODES * D];
__device__ float g_S    [(size_t)N_NODES * NS];   // dots1 [NS,N] then dots2 [N,NS]

__device__ float g_e    [NS * D];
__device__ float g_q    [NS * D];
__device__ float g_e2cat[NS * 2 * D];
__device__ float g_h1   [NS * HID];
__device__ float g_e2   [NS * D];
__device__ float g_k2   [NS * D];
__device__ float g_edg  [NS * D];

__device__ float g_Wkvq[3 * D * D];   // rows 0-255 WkT, 256-511 WvT, 512-767 WqT
__device__ float g_bkvq[3 * D];
__device__ float g_Wm1T[HID * 2 * D];
__device__ float g_Wm2T[D * HID];
__device__ float g_cwT [D * D];
__device__ float g_Wc0T[D * D];
__device__ float g_Wc1T[D * D];
__device__ float g_WtT [D * D];

// ---------------------------------------------------------------------------
// helpers
// ---------------------------------------------------------------------------
__device__ __forceinline__ uint32_t f2tf32(float f) {
    uint32_t r;
    asm("cvt.rna.tf32.f32 %0, %1;" : "=r"(r) : "f"(f));
    return r;
}
__device__ __forceinline__ void mma16n8k8(float& c0, float& c1, float& c2, float& c3,
                                          uint32_t a0, uint32_t a1, uint32_t a2, uint32_t a3,
                                          uint32_t b0, uint32_t b1) {
    asm volatile(
        "mma.sync.aligned.m16n8k8.row.col.f32.tf32.tf32.f32 "
        "{%0,%1,%2,%3}, {%4,%5,%6,%7}, {%8,%9}, {%0,%1,%2,%3};"
        : "+f"(c0), "+f"(c1), "+f"(c2), "+f"(c3)
        : "r"(a0), "r"(a1), "r"(a2), "r"(a3), "r"(b0), "r"(b1));
}
__device__ __forceinline__ void cp_async16(void* smem_dst, const void* gmem_src) {
    uint32_t d = (uint32_t)__cvta_generic_to_shared(smem_dst);
    asm volatile("cp.async.cg.shared.global [%0], [%1], 16;" :: "r"(d), "l"(gmem_src));
}
__device__ __forceinline__ void cp_commit() { asm volatile("cp.async.commit_group;"); }
__device__ __forceinline__ void cp_wait1()  { asm volatile("cp.async.wait_group 1;"); }

// ---------------------------------------------------------------------------
// Pipelined tf32 NT GEMM: C[m,n] = epi( sum_k A[m,k]*B[n,k] )
// A:[M,K] rowmajor, B:[*,K] rowmajor. 128x128x32 block tile, 8 warps,
// cp.async double buffering. Warp tile 32x64 = 2x8 m16n8k8.
// EPI: 0 = *scale, 1 = +bias, 2 = relu(+bias), 3 = relu(+bias + C + aux),
//      4 = fused kvq split (cols 0-255 -> C relu, 256-511 -> C2 relu, 512-767 -> C3)
// ---------------------------------------------------------------------------
#define LDA   36                  // 32 + 4 pad (keeps 16B alignment: 144B rows)
#define BUFSZ (128 * LDA)         // floats per tile buffer
#define MMA_SMEM_BYTES (4 * BUFSZ * 4)   // 2 bufs x (A + B)

template <int EPI>
__global__ void __launch_bounds__(256) mma_gemm(
    const float* __restrict__ A, const float* __restrict__ B,
    float* __restrict__ C, const float* __restrict__ bias,
    const float* __restrict__ aux, float* __restrict__ C2, float* __restrict__ C3,
    int M, int Ntot, int K, float scale) {
    extern __shared__ float sm[];
    float* As = sm;                 // [2][BUFSZ]
    float* Bs = sm + 2 * BUFSZ;     // [2][BUFSZ]
    const int tid = threadIdx.x;
    const int wid = tid >> 5, lane = tid & 31;
    const int warp_m = wid & 3;
    const int warp_n = wid >> 2;
    const int bm = blockIdx.y * 128;
    const int bn = blockIdx.x * 128;
    const int grp = lane >> 2;
    const int tig = lane & 3;

    float acc[2][8][4];
#pragma unroll
    for (int i = 0; i < 2; i++)
#pragma unroll
        for (int j = 0; j < 8; j++)
#pragma unroll
            for (int r = 0; r < 4; r++) acc[i][j][r] = 0.f;

    const int NCH = K >> 5;

    auto load_tile = [&](int ch, int buf) {
        const float* Ag = A + (size_t)bm * K + ch * 32;
        const float* Bg = B + (size_t)bn * K + ch * 32;
        float* Ad = As + buf * BUFSZ;
        float* Bd = Bs + buf * BUFSZ;
#pragma unroll
        for (int i = 0; i < 4; i++) {
            int id = tid + (i << 8);
            int row = id >> 3, c4 = (id & 7) << 2;
            cp_async16(Ad + row * LDA + c4, Ag + (size_t)row * K + c4);
            cp_async16(Bd + row * LDA + c4, Bg + (size_t)row * K + c4);
        }
    };

    load_tile(0, 0);
    cp_commit();

    for (int ch = 0; ch < NCH; ch++) {
        if (ch + 1 < NCH) load_tile(ch + 1, (ch + 1) & 1);
        cp_commit();
        cp_wait1();
        __syncthreads();
        const float* Ab = As + (ch & 1) * BUFSZ;
        const float* Bb = Bs + (ch & 1) * BUFSZ;
#pragma unroll
        for (int ks = 0; ks < 32; ks += 8) {
            uint32_t af[2][4];
#pragma unroll
            for (int mt = 0; mt < 2; mt++) {
                int m = warp_m * 32 + mt * 16 + grp;
                af[mt][0] = f2tf32(Ab[m * LDA + ks + tig]);
                af[mt][1] = f2tf32(Ab[(m + 8) * LDA + ks + tig]);
                af[mt][2] = f2tf32(Ab[m * LDA + ks + tig + 4]);
                af[mt][3] = f2tf32(Ab[(m + 8) * LDA + ks + tig + 4]);
            }
#pragma unroll
            for (int nt = 0; nt < 8; nt++) {
                int n = warp_n * 64 + nt * 8 + grp;
                uint32_t b0 = f2tf32(Bb[n * LDA + ks + tig]);
                uint32_t b1 = f2tf32(Bb[n * LDA + ks + tig + 4]);
#pragma unroll
                for (int mt = 0; mt < 2; mt++)
                    mma16n8k8(acc[mt][nt][0], acc[mt][nt][1], acc[mt][nt][2], acc[mt][nt][3],
                              af[mt][0], af[mt][1], af[mt][2], af[mt][3], b0, b1);
            }
        }
        __syncthreads();
    }

    // epilogue
#pragma unroll
    for (int mt = 0; mt < 2; mt++) {
        int r0 = bm + warp_m * 32 + mt * 16 + grp;
#pragma unroll
        for (int nt = 0; nt < 8; nt++) {
            int c0 = bn + warp_n * 64 + nt * 8 + 2 * tig;
#pragma unroll
            for (int half = 0; half < 2; half++) {
                int rr = r0 + half * 8;
                float vx = acc[mt][nt][2 * half + 0];
                float vy = acc[mt][nt][2 * half + 1];
                if constexpr (EPI == 0) {
                    vx *= scale; vy *= scale;
                    size_t idx = (size_t)rr * Ntot + c0;
                    float2 o; o.x = vx; o.y = vy;
                    *reinterpret_cast<float2*>(C + idx) = o;
                } else if constexpr (EPI == 4) {
                    vx += bias[c0]; vy += bias[c0 + 1];
                    int seg = c0 >> 8;
                    float* dst = (seg == 0) ? C : (seg == 1) ? C2 : C3;
                    if (seg < 2) { vx = fmaxf(vx, 0.f); vy = fmaxf(vy, 0.f); }
                    size_t idx = (size_t)rr * D + (c0 & 255);
                    float2 o; o.x = vx; o.y = vy;
                    *reinterpret_cast<float2*>(dst + idx) = o;
                } else {
                    vx += bias[c0]; vy += bias[c0 + 1];
                    size_t idx = (size_t)rr * Ntot + c0;
                    if constexpr (EPI == 3) {
                        float2 cc = *reinterpret_cast<const float2*>(C + idx);
                        float2 aa = *reinterpret_cast<const float2*>(aux + idx);
                        vx += cc.x + aa.x; vy += cc.y + aa.y;
                    }
                    if constexpr (EPI >= 2) { vx = fmaxf(vx, 0.f); vy = fmaxf(vy, 0.f); }
                    float2 o; o.x = vx; o.y = vy;
                    *reinterpret_cast<float2*>(C + idx) = o;
                }
            }
        }
    }
}

// ---------------------------------------------------------------------------
// Transpose [R,C] -> [C,R]
// ---------------------------------------------------------------------------
__global__ void transpose_k(const float* __restrict__ in, float* __restrict__ out,
                            int R, int C) {
    __shared__ float tile[32][33];
    int bx = blockIdx.x * 32, by = blockIdx.y * 32;
    int x = threadIdx.x;
    for (int y = threadIdx.y; y < 32; y += 8)
        tile[y][x] = in[(size_t)(by + y) * C + bx + x];
    __syncthreads();
    for (int y = threadIdx.y; y < 32; y += 8)
        out[(size_t)(bx + y) * R + by + x] = tile[x][y];
}

__global__ void concat3(const float* __restrict__ a, const float* __restrict__ b,
                        const float* __restrict__ c, float* __restrict__ o) {
    int i = threadIdx.x;
    o[i] = a[i]; o[D + i] = b[i]; o[2 * D + i] = c[i];
}

// ---------------------------------------------------------------------------
// LayerNorm: one warp per row of 256
// ---------------------------------------------------------------------------
__global__ void ln_rows(const float* __restrict__ x, const float* __restrict__ w,
                        const float* __restrict__ b, float* __restrict__ o, int M) {
    int warp = (blockIdx.x * blockDim.x + threadIdx.x) >> 5;
    int lane = threadIdx.x & 31;
    if (warp >= M) return;
    const float* r = x + (size_t)warp * D;
    float v[8]; float s = 0.f;
#pragma unroll
    for (int j = 0; j < 8; j++) { v[j] = r[lane + 32 * j]; s += v[j]; }
#pragma unroll
    for (int st = 16; st; st >>= 1) s += __shfl_xor_sync(0xffffffffu, s, st);
    float mu = s * (1.f / 256.f);
    float q = 0.f;
#pragma unroll
    for (int j = 0; j < 8; j++) { float d = v[j] - mu; q += d * d; }
#pragma unroll
    for (int st = 16; st; st >>= 1) q += __shfl_xor_sync(0xffffffffu, q, st);
    float rinv = rsqrtf(q * (1.f / 256.f) + 1e-5f);
    float* po = o + (size_t)warp * D;
#pragma unroll
    for (int j = 0; j < 8; j++) {
        int c = lane + 32 * j;
        po[c] = (v[j] - mu) * rinv * w[c] + b[c];
    }
}

__global__ void edges_ln(const float* __restrict__ noise, const float* __restrict__ emu,
                         const float* __restrict__ elog, const float* __restrict__ w,
                         const float* __restrict__ b, float* __restrict__ o) {
    int warp = (blockIdx.x * blockDim.x + threadIdx.x) >> 5;
    int lane = threadIdx.x & 31;
    if (warp >= NS) return;
    const float* r = noise + (size_t)warp * D;
    float v[8]; float s = 0.f;
#pragma unroll
    for (int j = 0; j < 8; j++) {
        int c = lane + 32 * j;
        v[j] = emu[c] + expf(elog[c]) * r[c];
        s += v[j];
    }
#pragma unroll
    for (int st = 16; st; st >>= 1) s += __shfl_xor_sync(0xffffffffu, s, st);
    float mu = s * (1.f / 256.f);
    float q = 0.f;
#pragma unroll
    for (int j = 0; j < 8; j++) { float d = v[j] - mu; q += d * d; }
#pragma unroll
    for (int st = 16; st; st >>= 1) q += __shfl_xor_sync(0xffffffffu, q, st);
    float rinv = rsqrtf(q * (1.f / 256.f) + 1e-5f);
    float* po = o + (size_t)warp * D;
#pragma unroll
    for (int j = 0; j < 8; j++) {
        int c = lane + 32 * j;
        po[c] = (v[j] - mu) * rinv * w[c] + b[c];
    }
}

// ---------------------------------------------------------------------------
// Small fp32 NT GEMM (NS-sized ops only): 64x64 tile
// ---------------------------------------------------------------------------
template <bool BIAS, bool RELU>
__global__ void gemm_small(const float* __restrict__ A, const float* __restrict__ B,
                           float* __restrict__ C, const float* __restrict__ bias,
                           int M, int N, int K) {
    constexpr int BM = 64, BN = 64, BK = 16, TM = 4, TN = 4;
    constexpr int THREADS = 256;
    __shared__ float As[BK][BM + 4];
    __shared__ float Bs[BK][BN + 4];
    const int bm = blockIdx.y * BM;
    const int bn = blockIdx.x * BN;
    const int tid = threadIdx.x;
    const int tx = tid % (BN / TN);
    const int ty = tid / (BN / TN);
    float acc[TM][TN];
#pragma unroll
    for (int i = 0; i < TM; i++)
#pragma unroll
        for (int j = 0; j < TN; j++) acc[i][j] = 0.f;

    constexpr int A_F4 = BM * BK / 4;
    for (int k0 = 0; k0 < K; k0 += BK) {
        for (int f = tid; f < A_F4; f += THREADS) {
            int row = f / (BK / 4);
            int kc = (f % (BK / 4)) * 4;
            float4 v = *reinterpret_cast<const float4*>(&A[(size_t)(bm + row) * K + k0 + kc]);
            As[kc + 0][row] = v.x; As[kc + 1][row] = v.y;
            As[kc + 2][row] = v.z; As[kc + 3][row] = v.w;
        }
        for (int f = tid; f < A_F4; f += THREADS) {
            int row = f / (BK / 4);
            int kc = (f % (BK / 4)) * 4;
            float4 v = *reinterpret_cast<const float4*>(&B[(size_t)(bn + row) * K + k0 + kc]);
            Bs[kc + 0][row] = v.x; Bs[kc + 1][row] = v.y;
            Bs[kc + 2][row] = v.z; Bs[kc + 3][row] = v.w;
        }
        __syncthreads();
#pragma unroll
        for (int kk = 0; kk < BK; kk++) {
            float af[TM], bf[TN];
#pragma unroll
            for (int i = 0; i < TM; i++) af[i] = As[kk][ty * TM + i];
#pragma unroll
            for (int j = 0; j < TN; j++) bf[j] = Bs[kk][tx * TN + j];
#pragma unroll
            for (int i = 0; i < TM; i++)
#pragma unroll
                for (int j = 0; j < TN; j++) acc[i][j] += af[i] * bf[j];
        }
        __syncthreads();
    }
#pragma unroll
    for (int i = 0; i < TM; i++) {
        int m = bm + ty * TM + i;
#pragma unroll
        for (int j = 0; j < TN; j++) {
            int n = bn + tx * TN + j;
            float v = acc[i][j];
            if (BIAS) v += bias[n];
            if (RELU) v = fmaxf(v, 0.f);
            C[(size_t)m * N + n] = v;
        }
    }
}

// ---------------------------------------------------------------------------
// Slot attention, single pass: per slot (block) over 65536 logits compute
// online (max, sumexp) + top-10, then updates = sum w_i * vv[idx_i];
// e2cat[s] = concat(e[s], updates[s]).
// ---------------------------------------------------------------------------
__global__ void slot_attend(const float* __restrict__ S1, const float* __restrict__ vv,
                            const float* __restrict__ e, float* __restrict__ e2cat) {
    __shared__ float sv[256 * KTOP];
    __shared__ int   si[256 * KTOP];
    __shared__ float sm_m[256];
    __shared__ float sm_z[256];
    __shared__ float sw[KTOP];
    __shared__ int   sx[KTOP];
    int s = blockIdx.x, tid = threadIdx.x;
    const float* row = S1 + (size_t)s * N_NODES;
    float tv[KTOP]; int ti[KTOP];
#pragma unroll
    for (int i = 0; i < KTOP; i++) { tv[i] = -INFINITY; ti[i] = 0; }
    float m_loc = -INFINITY, z = 0.f;
    for (int n = tid; n < N_NODES; n += 256) {
        float v = row[n];
        if (v > m_loc) { z *= __expf(m_loc - v); m_loc = v; }
        z += __expf(v - m_loc);
        if (v > tv[KTOP - 1]) {
            int ix = n;
            float vt = v;
#pragma unroll
            for (int p = 0; p < KTOP; p++)
                if (vt > tv[p]) {
                    float tf = tv[p]; tv[p] = vt; vt = tf;
                    int tt = ti[p]; ti[p] = ix; ix = tt;
                }
        }
    }
#pragma unroll
    for (int i = 0; i < KTOP; i++) { sv[tid * KTOP + i] = tv[i]; si[tid * KTOP + i] = ti[i]; }
    sm_m[tid] = m_loc; sm_z[tid] = z;
    __syncthreads();
    for (int stride = 128; stride >= 1; stride >>= 1) {
        if (tid < stride) {
#pragma unroll
            for (int i = 0; i < KTOP; i++) { tv[i] = sv[tid * KTOP + i]; ti[i] = si[tid * KTOP + i]; }
#pragma unroll
            for (int i = 0; i < KTOP; i++) {
                float v = sv[(tid + stride) * KTOP + i];
                int ix = si[(tid + stride) * KTOP + i];
                if (v > tv[KTOP - 1]) {
#pragma unroll
                    for (int p = 0; p < KTOP; p++)
                        if (v > tv[p]) {
                            float tf = tv[p]; tv[p] = v; v = tf;
                            int tt = ti[p]; ti[p] = ix; ix = tt;
                        }
                }
            }
#pragma unroll
            for (int i = 0; i < KTOP; i++) { sv[tid * KTOP + i] = tv[i]; si[tid * KTOP + i] = ti[i]; }
            // merge (max, sumexp)
            float ma = sm_m[tid], za = sm_z[tid];
            float mb = sm_m[tid + stride], zb = sm_z[tid + stride];
            float mn = fmaxf(ma, mb);
            float zn = za * __expf(ma - mn) + zb * __expf(mb - mn);
            sm_m[tid] = mn; sm_z[tid] = zn;
        }
        __syncthreads();
    }
    float maxv = sm_m[0];
    float Z = sm_z[0];
    if (tid < KTOP) {
        float p = __expf(sv[tid] - maxv) / Z;
        sw[tid] = (p + EPSC) / (1.f + (float)N_NODES * EPSC);
        sx[tid] = si[tid];
    }
    __syncthreads();
    float acc = 0.f;
#pragma unroll
    for (int i = 0; i < KTOP; i++) acc += sw[i] * vv[(size_t)sx[i] * D + tid];
    e2cat[(size_t)s * 2 * D + D + tid] = acc;
    e2cat[(size_t)s * 2 * D + tid] = e[(size_t)s * D + tid];
}

// ---------------------------------------------------------------------------
// Node attention: one warp per node. 512 logits -> max, Z, top-10 ->
// nodes[n] = sum_i softmax_i * edg[idx_i]
// ---------------------------------------------------------------------------
__global__ void node_attend(const float* __restrict__ S2, const float* __restrict__ edg,
                            float* __restrict__ nodes) {
    int warp = blockIdx.x * (blockDim.x >> 5) + (threadIdx.x >> 5);
    int lane = threadIdx.x & 31;
    const float* row = S2 + (size_t)warp * NS;
    float dv[16];
#pragma unroll
    for (int j = 0; j < 16; j++) dv[j] = row[lane + 32 * j];
    float tv[KTOP]; int ti[KTOP];
#pragma unroll
    for (int i = 0; i < KTOP; i++) { tv[i] = -INFINITY; ti[i] = 0; }
#pragma unroll
    for (int j = 0; j < 16; j++) {
        float v = dv[j]; int ix = lane + 32 * j;
        if (v > tv[KTOP - 1]) {
#pragma unroll
            for (int p = 0; p < KTOP; p++)
                if (v > tv[p]) {
                    float tf = tv[p]; tv[p] = v; v = tf;
                    int tt = ti[p]; ti[p] = ix; ix = tt;
                }
        }
    }
#pragma unroll
    for (int st = 16; st >= 1; st >>= 1) {
        float ov[KTOP]; int oi[KTOP];
#pragma unroll
        for (int i = 0; i < KTOP; i++) {
            ov[i] = __shfl_down_sync(0xffffffffu, tv[i], st);
            oi[i] = __shfl_down_sync(0xffffffffu, ti[i], st);
        }
#pragma unroll
        for (int i = 0; i < KTOP; i++) {
            float v = ov[i]; int ix = oi[i];
            if (v > tv[KTOP - 1]) {
#pragma unroll
                for (int p = 0; p < KTOP; p++)
                    if (v > tv[p]) {
                        float tf = tv[p]; tv[p] = v; v = tf;
                        int tt = ti[p]; ti[p] = ix; ix = tt;
                    }
            }
        }
    }
    float maxv = __shfl_sync(0xffffffffu, tv[0], 0);
    float z = 0.f;
#pragma unroll
    for (int j = 0; j < 16; j++) z += __expf(dv[j] - maxv);
#pragma unroll
    for (int st = 16; st; st >>= 1) z += __shfl_xor_sync(0xffffffffu, z, st);
    float zin = 1.f / z;
    float w_[KTOP]; int ix_[KTOP];
#pragma unroll
    for (int i = 0; i < KTOP; i++) {
        float v = __shfl_sync(0xffffffffu, tv[i], 0);
        ix_[i] = __shfl_sync(0xffffffffu, ti[i], 0);
        w_[i] = __expf(v - maxv) * zin;
    }
    float* po = nodes + (size_t)warp * D;
#pragma unroll
    for (int j = 0; j < 8; j++) {
        int c = lane + 32 * j;
        float acc = 0.f;
#pragma unroll
        for (int i = 0; i < KTOP; i++) acc += w_[i] * edg[(size_t)ix_[i] * D + c];
        po[c] = acc;
    }
}

// ---------------------------------------------------------------------------
// Launch
// ---------------------------------------------------------------------------
extern "C" void kernel_launch(void* const* d_in, const int* in_sizes, int n_in,
                              void* d_out, int out_size) {
    (void)in_sizes; (void)n_in; (void)out_size;
    const float* x      = (const float*)d_in[0];
    const float* enoise = (const float*)d_in[1];
    const float* emu    = (const float*)d_in[2];
    const float* elog   = (const float*)d_in[3];
    const float* lnw    = (const float*)d_in[4];
    const float* lnb    = (const float*)d_in[5];
    const float* lew    = (const float*)d_in[6];
    const float* leb    = (const float*)d_in[7];
    const float* Wq = (const float*)d_in[8];  const float* bq = (const float*)d_in[9];
    const float* Wk = (const float*)d_in[10]; const float* bk = (const float*)d_in[11];
    const float* Wv = (const float*)d_in[12]; const float* bv = (const float*)d_in[13];
    const float* Wm1 = (const float*)d_in[14]; const float* bm1 = (const float*)d_in[15];
    const float* Wm2 = (const float*)d_in[16]; const float* bm2 = (const float*)d_in[17];
    const float* cw = (const float*)d_in[18];  const float* cb = (const float*)d_in[19];
    const float* Wc0 = (const float*)d_in[20]; const float* bc0 = (const float*)d_in[21];
    const float* Wc1 = (const float*)d_in[22]; const float* bc1 = (const float*)d_in[23];
    const float* Wt = (const float*)d_in[24];  const float* bt = (const float*)d_in[25];
    float* out = (float*)d_out;

    void* p;
    cudaGetSymbolAddress(&p, g_xin);   float* xin = (float*)p;
    cudaGetSymbolAddress(&p, g_kk);    float* kkb = (float*)p;
    cudaGetSymbolAddress(&p, g_vv);    float* vvb = (float*)p;
    cudaGetSymbolAddress(&p, g_q2);    float* q2b = (float*)p;
    cudaGetSymbolAddress(&p, g_nodes); float* nodesb = (float*)p;
    cudaGetSymbolAddress(&p, g_tmp);   float* tmp = (float*)p;
    cudaGetSymbolAddress(&p, g_S);     float* S = (float*)p;
    cudaGetSymbolAddress(&p, g_e);     float* e = (float*)p;
    cudaGetSymbolAddress(&p, g_q);     float* qb = (float*)p;
    cudaGetSymbolAddress(&p, g_e2cat); float* e2cat = (float*)p;
    cudaGetSymbolAddress(&p, g_h1);    float* h1 = (float*)p;
    cudaGetSymbolAddress(&p, g_e2);    float* e2 = (float*)p;
    cudaGetSymbolAddress(&p, g_k2);    float* k2 = (float*)p;
    cudaGetSymbolAddress(&p, g_edg);   float* edg = (float*)p;
    cudaGetSymbolAddress(&p, g_Wkvq);  float* Wkvq = (float*)p;
    cudaGetSymbolAddress(&p, g_bkvq);  float* bkvq = (float*)p;
    cudaGetSymbolAddress(&p, g_Wm1T);  float* Wm1T = (float*)p;
    cudaGetSymbolAddress(&p, g_Wm2T);  float* Wm2T = (float*)p;
    cudaGetSymbolAddress(&p, g_cwT);   float* cwT = (float*)p;
    cudaGetSymbolAddress(&p, g_Wc0T);  float* Wc0T = (float*)p;
    cudaGetSymbolAddress(&p, g_Wc1T);  float* Wc1T = (float*)p;
    cudaGetSymbolAddress(&p, g_WtT);   float* WtT = (float*)p;

    cudaFuncSetAttribute(mma_gemm<0>, cudaFuncAttributeMaxDynamicSharedMemorySize, MMA_SMEM_BYTES);
    cudaFuncSetAttribute(mma_gemm<1>, cudaFuncAttributeMaxDynamicSharedMemorySize, MMA_SMEM_BYTES);
    cudaFuncSetAttribute(mma_gemm<2>, cudaFuncAttributeMaxDynamicSharedMemorySize, MMA_SMEM_BYTES);
    cudaFuncSetAttribute(mma_gemm<3>, cudaFuncAttributeMaxDynamicSharedMemorySize, MMA_SMEM_BYTES);
    cudaFuncSetAttribute(mma_gemm<4>, cudaFuncAttributeMaxDynamicSharedMemorySize, MMA_SMEM_BYTES);

    float* WkT = Wkvq;                 // rows 0-255
    float* WvT = Wkvq + D * D;         // rows 256-511
    float* WqT = Wkvq + 2 * D * D;     // rows 512-767

    dim3 tb(32, 8);
    transpose_k<<<dim3(8, 8), tb>>>(Wk, WkT, D, D);
    transpose_k<<<dim3(8, 8), tb>>>(Wv, WvT, D, D);
    transpose_k<<<dim3(8, 8), tb>>>(Wq, WqT, D, D);
    transpose_k<<<dim3(8, 16), tb>>>(Wm1, Wm1T, 2 * D, HID);
    transpose_k<<<dim3(8, 8), tb>>>(Wm2, Wm2T, HID, D);
    transpose_k<<<dim3(8, 8), tb>>>(cw, cwT, D, D);
    transpose_k<<<dim3(8, 8), tb>>>(Wc0, Wc0T, D, D);
    transpose_k<<<dim3(8, 8), tb>>>(Wc1, Wc1T, D, D);
    transpose_k<<<dim3(8, 8), tb>>>(Wt, WtT, D, D);
    concat3<<<1, D>>>(bk, bv, bq, bkvq);

    ln_rows<<<N_NODES / 8, 256>>>(x, lnw, lnb, xin, N_NODES);
    edges_ln<<<NS / 8, 256>>>(enoise, emu, elog, lew, leb, e);

    // fused: kk = relu(xin@Wk+bk), vv = relu(xin@Wv+bv), q2 = xin@Wq+bq
    mma_gemm<4><<<dim3(6, 512), 256, MMA_SMEM_BYTES>>>(
        xin, Wkvq, kkb, bkvq, nullptr, vvb, q2b, N_NODES, 3 * D, D, 1.f);

    // q = relu(e@Wq+bq)
    gemm_small<true, true><<<dim3(4, 8), 256>>>(e, WqT, qb, bq, NS, D, D);

    // dots1 = q @ kk^T * SCALE  -> S [NS, N]
    mma_gemm<0><<<dim3(512, 4), 256, MMA_SMEM_BYTES>>>(
        qb, kkb, S, nullptr, nullptr, nullptr, nullptr, NS, N_NODES, D, SCALE_C);

    slot_attend<<<NS, 256>>>(S, vvb, e, e2cat);

    // slot MLP: h1 = relu(e2cat@Wm1+bm1); e2 = h1@Wm2+bm2
    gemm_small<true, true><<<dim3(4, 8), 256>>>(e2cat, Wm1T, h1, bm1, NS, HID, 2 * D);
    gemm_small<true, false><<<dim3(4, 8), 256>>>(h1, Wm2T, e2, bm2, NS, D, HID);

    // k2 = relu(e2@Wk+bk); edg = e2@conv_w+conv_b
    gemm_small<true, true><<<dim3(4, 8), 256>>>(e2, WkT, k2, bk, NS, D, D);
    gemm_small<true, false><<<dim3(4, 8), 256>>>(e2, cwT, edg, cb, NS, D, D);

    // dots2 = q2 @ k2^T * SCALE  -> S [N, NS]
    mma_gemm<0><<<dim3(4, 512), 256, MMA_SMEM_BYTES>>>(
        q2b, k2, S, nullptr, nullptr, nullptr, nullptr, N_NODES, NS, D, SCALE_C);

    node_attend<<<N_NODES / 8, 256>>>(S, edg, nodesb);

    // tmp = x@Wc0 + bc0
    mma_gemm<1><<<dim3(2, 512), 256, MMA_SMEM_BYTES>>>(
        x, Wc0T, tmp, bc0, nullptr, nullptr, nullptr, N_NODES, D, D, 1.f);
    // tmp = relu(tmp + nodes@Wc1 + bc1 + nodes)
    mma_gemm<3><<<dim3(2, 512), 256, MMA_SMEM_BYTES>>>(
        nodesb, Wc1T, tmp, bc1, nodesb, nullptr, nullptr, N_NODES, D, D, 1.f);
    // out = relu(tmp@Wt + bt)
    mma_gemm<2><<<dim3(2, 512), 256, MMA_SMEM_BYTES>>>(
        tmp, WtT, out, bt, nullptr, nullptr, nullptr, N_NODES, D, D, 1.f);
}

// round 5
// speedup vs baseline: 2.6348x; 1.0511x over previous
#include <cuda_runtime.h>
#include <math.h>
#include <stdint.h>

#define N_NODES 65536
#define D       256
#define NS      512
#define HID     256
#define KTOP    10
#define EPSC    1e-8f
#define SCALE_C 0.0625f  /* 256^-0.5 */

// ---------------------------------------------------------------------------
// Scratch
// ---------------------------------------------------------------------------
__device__ float g_xin  [(size_t)N_NODES * D];
__device__ float g_xr   [(size_t)N_NODES * D];
__device__ float g_kk   [(size_t)N_NODES * D];
__device__ float g_vv   [(size_t)N_NODES * D];
__device__ float g_q2   [(size_t)N_NODES * D];
__device__ float g_nodes[(size_t)N_NODES * D];
__device__ float g_noder[(size_t)N_NODES * D];
__device__ float g_tmp  [(size_t)N_NODES * D];
__device__ float g_S    [(size_t)N_NODES * NS];

__device__ float g_e    [NS * D];
__device__ float g_q    [NS * D];
__device__ float g_e2cat[NS * 2 * D];
__device__ float g_h1   [NS * HID];
__device__ float g_e2   [NS * D];
__device__ float g_k2   [NS * D];
__device__ float g_edg  [NS * D];

__device__ float g_Wkvq[3 * D * D];   // rows 0-255 WkT, 256-511 WvT, 512-767 WqT
__device__ float g_bkvq[3 * D];
__device__ float g_Wm1T[HID * 2 * D];
__device__ float g_Wm2T[D * HID];
__device__ float g_cwT [D * D];
__device__ float g_Wc0T[D * D];
__device__ float g_Wc1T[D * D];
__device__ float g_WtT [D * D];

// ---------------------------------------------------------------------------
// helpers
// ---------------------------------------------------------------------------
__device__ __forceinline__ uint32_t f2tf32(float f) {
    uint32_t r;
    asm("cvt.rna.tf32.f32 %0, %1;" : "=r"(r) : "f"(f));
    return r;
}
__device__ __forceinline__ float rndf(float f) { return __uint_as_float(f2tf32(f)); }

__device__ __forceinline__ void mma16n8k8(float& c0, float& c1, float& c2, float& c3,
                                          uint32_t a0, uint32_t a1, uint32_t a2, uint32_t a3,
                                          uint32_t b0, uint32_t b1) {
    asm volatile(
        "mma.sync.aligned.m16n8k8.row.col.f32.tf32.tf32.f32 "
        "{%0,%1,%2,%3}, {%4,%5,%6,%7}, {%8,%9}, {%0,%1,%2,%3};"
        : "+f"(c0), "+f"(c1), "+f"(c2), "+f"(c3)
        : "r"(a0), "r"(a1), "r"(a2), "r"(a3), "r"(b0), "r"(b1));
}
__device__ __forceinline__ void ldsm_x4(uint32_t& r0, uint32_t& r1, uint32_t& r2, uint32_t& r3,
                                        uint32_t addr) {
    asm volatile("ldmatrix.sync.aligned.m8n8.x4.shared.b16 {%0,%1,%2,%3}, [%4];"
                 : "=r"(r0), "=r"(r1), "=r"(r2), "=r"(r3) : "r"(addr));
}
__device__ __forceinline__ void cp_async16(void* smem_dst, const void* gmem_src) {
    uint32_t d = (uint32_t)__cvta_generic_to_shared(smem_dst);
    asm volatile("cp.async.cg.shared.global [%0], [%1], 16;" :: "r"(d), "l"(gmem_src));
}
__device__ __forceinline__ void cp_commit() { asm volatile("cp.async.commit_group;"); }
__device__ __forceinline__ void cp_wait1()  { asm volatile("cp.async.wait_group 1;"); }

// ---------------------------------------------------------------------------
// Pipelined tf32 NT GEMM with ldmatrix fragments.
// Operands must be PRE-ROUNDED to tf32 (low mantissa bits zero).
// A:[M,K] rowmajor, B:[*,K] rowmajor. 128x128x32 tile, 8 warps, 2-stage cp.async.
// EPI: 0 = *scale, 1 = +bias, 2 = relu(+bias), 3 = relu(+bias + C + aux),
//      4 = fused kvq split (seg0->C relu, seg1->C2 relu (vv, never rounded), seg2->C3)
// RND: tf32-round stored outputs (so consumers can skip cvt)
// ---------------------------------------------------------------------------
#define LDA   36
#define BUFSZ (128 * LDA)
#define MMA_SMEM_BYTES (4 * BUFSZ * 4)

template <int EPI, bool RND>
__global__ void __launch_bounds__(256) mma_gemm(
    const float* __restrict__ A, const float* __restrict__ B,
    float* __restrict__ C, const float* __restrict__ bias,
    const float* __restrict__ aux, float* __restrict__ C2, float* __restrict__ C3,
    int M, int Ntot, int K, float scale) {
    extern __shared__ float sm[];
    const int tid = threadIdx.x;
    const int wid = tid >> 5, lane = tid & 31;
    const int warp_m = wid & 3;
    const int warp_n = wid >> 2;
    const int bm = blockIdx.y * 128;
    const int bn = blockIdx.x * 128;
    const int grp = lane >> 2;
    const int tig = lane & 3;

    const uint32_t smb = (uint32_t)__cvta_generic_to_shared(sm);
    const uint32_t Abase[2] = { smb, smb + BUFSZ * 4 };
    const uint32_t Bbase[2] = { smb + 2 * BUFSZ * 4, smb + 3 * BUFSZ * 4 };

    // ldmatrix per-lane offsets (bytes)
    const int a_row = (lane & 7) + ((lane >> 3) & 1) * 8;
    const int a_col = (lane >> 4) * 4;
    uint32_t a_off[2];
#pragma unroll
    for (int mt = 0; mt < 2; mt++)
        a_off[mt] = ((warp_m * 32 + mt * 16 + a_row) * LDA + a_col) * 4;
    const int b_row = (lane & 7) + (lane >> 4) * 8;
    const int b_col = ((lane >> 3) & 1) * 4;
    uint32_t b_off[4];
#pragma unroll
    for (int p = 0; p < 4; p++)
        b_off[p] = ((warp_n * 64 + p * 16 + b_row) * LDA + b_col) * 4;

    float acc[2][8][4];
#pragma unroll
    for (int i = 0; i < 2; i++)
#pragma unroll
        for (int j = 0; j < 8; j++)
#pragma unroll
            for (int r = 0; r < 4; r++) acc[i][j][r] = 0.f;

    const int NCH = K >> 5;

    auto load_tile = [&](int ch, int buf) {
        const float* Ag = A + (size_t)bm * K + ch * 32;
        const float* Bg = B + (size_t)bn * K + ch * 32;
        float* Ad = sm + buf * BUFSZ;
        float* Bd = sm + (2 + buf) * BUFSZ;
#pragma unroll
        for (int i = 0; i < 4; i++) {
            int id = tid + (i << 8);
            int row = id >> 3, c4 = (id & 7) << 2;
            cp_async16(Ad + row * LDA + c4, Ag + (size_t)row * K + c4);
            cp_async16(Bd + row * LDA + c4, Bg + (size_t)row * K + c4);
        }
    };

    load_tile(0, 0);
    cp_commit();

    for (int ch = 0; ch < NCH; ch++) {
        if (ch + 1 < NCH) load_tile(ch + 1, (ch + 1) & 1);
        cp_commit();
        cp_wait1();
        __syncthreads();
        const uint32_t Ab = Abase[ch & 1];
        const uint32_t Bb = Bbase[ch & 1];
#pragma unroll
        for (int ks = 0; ks < 32; ks += 8) {
            uint32_t ra[2][4], rb[4][4];
#pragma unroll
            for (int mt = 0; mt < 2; mt++)
                ldsm_x4(ra[mt][0], ra[mt][1], ra[mt][2], ra[mt][3], Ab + a_off[mt] + ks * 4);
#pragma unroll
            for (int p = 0; p < 4; p++)
                ldsm_x4(rb[p][0], rb[p][1], rb[p][2], rb[p][3], Bb + b_off[p] + ks * 4);
#pragma unroll
            for (int p = 0; p < 4; p++)
#pragma unroll
                for (int mt = 0; mt < 2; mt++) {
                    mma16n8k8(acc[mt][2 * p][0], acc[mt][2 * p][1],
                              acc[mt][2 * p][2], acc[mt][2 * p][3],
                              ra[mt][0], ra[mt][1], ra[mt][2], ra[mt][3],
                              rb[p][0], rb[p][1]);
                    mma16n8k8(acc[mt][2 * p + 1][0], acc[mt][2 * p + 1][1],
                              acc[mt][2 * p + 1][2], acc[mt][2 * p + 1][3],
                              ra[mt][0], ra[mt][1], ra[mt][2], ra[mt][3],
                              rb[p][2], rb[p][3]);
                }
        }
        __syncthreads();
    }

    // epilogue
#pragma unroll
    for (int mt = 0; mt < 2; mt++) {
        int r0 = bm + warp_m * 32 + mt * 16 + grp;
#pragma unroll
        for (int nt = 0; nt < 8; nt++) {
            int c0 = bn + warp_n * 64 + nt * 8 + 2 * tig;
#pragma unroll
            for (int half = 0; half < 2; half++) {
                int rr = r0 + half * 8;
                float vx = acc[mt][nt][2 * half + 0];
                float vy = acc[mt][nt][2 * half + 1];
                if constexpr (EPI == 0) {
                    vx *= scale; vy *= scale;
                    if (RND) { vx = rndf(vx); vy = rndf(vy); }
                    size_t idx = (size_t)rr * Ntot + c0;
                    float2 o; o.x = vx; o.y = vy;
                    *reinterpret_cast<float2*>(C + idx) = o;
                } else if constexpr (EPI == 4) {
                    vx += bias[c0]; vy += bias[c0 + 1];
                    int seg = c0 >> 8;
                    float* dst = (seg == 0) ? C : (seg == 1) ? C2 : C3;
                    if (seg < 2) { vx = fmaxf(vx, 0.f); vy = fmaxf(vy, 0.f); }
                    if (RND && seg != 1) { vx = rndf(vx); vy = rndf(vy); }  // vv stays exact
                    size_t idx = (size_t)rr * D + (c0 & 255);
                    float2 o; o.x = vx; o.y = vy;
                    *reinterpret_cast<float2*>(dst + idx) = o;
                } else {
                    vx += bias[c0]; vy += bias[c0 + 1];
                    size_t idx = (size_t)rr * Ntot + c0;
                    if constexpr (EPI == 3) {
                        float2 cc = *reinterpret_cast<const float2*>(C + idx);
                        float2 aa = *reinterpret_cast<const float2*>(aux + idx);
                        vx += cc.x + aa.x; vy += cc.y + aa.y;
                    }
                    if constexpr (EPI >= 2) { vx = fmaxf(vx, 0.f); vy = fmaxf(vy, 0.f); }
                    if (RND) { vx = rndf(vx); vy = rndf(vy); }
                    float2 o; o.x = vx; o.y = vy;
                    *reinterpret_cast<float2*>(C + idx) = o;
                }
            }
        }
    }
}

// ---------------------------------------------------------------------------
// Transpose [R,C] -> [C,R], optional tf32 rounding
// ---------------------------------------------------------------------------
template <bool RND>
__global__ void transpose_k(const float* __restrict__ in, float* __restrict__ out,
                            int R, int C) {
    __shared__ float tile[32][33];
    int bx = blockIdx.x * 32, by = blockIdx.y * 32;
    int x = threadIdx.x;
    for (int y = threadIdx.y; y < 32; y += 8) {
        float v = in[(size_t)(by + y) * C + bx + x];
        tile[y][x] = RND ? rndf(v) : v;
    }
    __syncthreads();
    for (int y = threadIdx.y; y < 32; y += 8)
        out[(size_t)(bx + y) * R + by + x] = tile[x][y];
}

__global__ void concat3(const float* __restrict__ a, const float* __restrict__ b,
                        const float* __restrict__ c, float* __restrict__ o) {
    int i = threadIdx.x;
    o[i] = a[i]; o[D + i] = b[i]; o[2 * D + i] = c[i];
}

__global__ void copy_round(const float4* __restrict__ in, float4* __restrict__ out, int n4) {
    int i = blockIdx.x * blockDim.x + threadIdx.x;
    if (i < n4) {
        float4 v = in[i];
        v.x = rndf(v.x); v.y = rndf(v.y); v.z = rndf(v.z); v.w = rndf(v.w);
        out[i] = v;
    }
}

// ---------------------------------------------------------------------------
// LayerNorm (output tf32-rounded: only consumed as GEMM operand)
// ---------------------------------------------------------------------------
__global__ void ln_rows(const float* __restrict__ x, const float* __restrict__ w,
                        const float* __restrict__ b, float* __restrict__ o, int M) {
    int warp = (blockIdx.x * blockDim.x + threadIdx.x) >> 5;
    int lane = threadIdx.x & 31;
    if (warp >= M) return;
    const float* r = x + (size_t)warp * D;
    float v[8]; float s = 0.f;
#pragma unroll
    for (int j = 0; j < 8; j++) { v[j] = r[lane + 32 * j]; s += v[j]; }
#pragma unroll
    for (int st = 16; st; st >>= 1) s += __shfl_xor_sync(0xffffffffu, s, st);
    float mu = s * (1.f / 256.f);
    float q = 0.f;
#pragma unroll
    for (int j = 0; j < 8; j++) { float d = v[j] - mu; q += d * d; }
#pragma unroll
    for (int st = 16; st; st >>= 1) q += __shfl_xor_sync(0xffffffffu, q, st);
    float rinv = rsqrtf(q * (1.f / 256.f) + 1e-5f);
    float* po = o + (size_t)warp * D;
#pragma unroll
    for (int j = 0; j < 8; j++) {
        int c = lane + 32 * j;
        po[c] = rndf((v[j] - mu) * rinv * w[c] + b[c]);
    }
}

// edges = mu + exp(logsigma)*noise, then LN (exact: feeds fp32 small gemms + concat)
__global__ void edges_ln(const float* __restrict__ noise, const float* __restrict__ emu,
                         const float* __restrict__ elog, const float* __restrict__ w,
                         const float* __restrict__ b, float* __restrict__ o) {
    int warp = (blockIdx.x * blockDim.x + threadIdx.x) >> 5;
    int lane = threadIdx.x & 31;
    if (warp >= NS) return;
    const float* r = noise + (size_t)warp * D;
    float v[8]; float s = 0.f;
#pragma unroll
    for (int j = 0; j < 8; j++) {
        int c = lane + 32 * j;
        v[j] = emu[c] + expf(elog[c]) * r[c];
        s += v[j];
    }
#pragma unroll
    for (int st = 16; st; st >>= 1) s += __shfl_xor_sync(0xffffffffu, s, st);
    float mu = s * (1.f / 256.f);
    float q = 0.f;
#pragma unroll
    for (int j = 0; j < 8; j++) { float d = v[j] - mu; q += d * d; }
#pragma unroll
    for (int st = 16; st; st >>= 1) q += __shfl_xor_sync(0xffffffffu, q, st);
    float rinv = rsqrtf(q * (1.f / 256.f) + 1e-5f);
    float* po = o + (size_t)warp * D;
#pragma unroll
    for (int j = 0; j < 8; j++) {
        int c = lane + 32 * j;
        po[c] = (v[j] - mu) * rinv * w[c] + b[c];
    }
}

// ---------------------------------------------------------------------------
// Small fp32 NT GEMM (NS-sized ops): 64x64 tile; optional tf32-rounded store
// ---------------------------------------------------------------------------
template <bool BIAS, bool RELU, bool RND>
__global__ void gemm_small(const float* __restrict__ A, const float* __restrict__ B,
                           float* __restrict__ C, const float* __restrict__ bias,
                           int M, int N, int K) {
    constexpr int BM = 64, BN = 64, BK = 16, TM = 4, TN = 4;
    constexpr int THREADS = 256;
    __shared__ float As[BK][BM + 4];
    __shared__ float Bs[BK][BN + 4];
    const int bm = blockIdx.y * BM;
    const int bn = blockIdx.x * BN;
    const int tid = threadIdx.x;
    const int tx = tid % (BN / TN);
    const int ty = tid / (BN / TN);
    float acc[TM][TN];
#pragma unroll
    for (int i = 0; i < TM; i++)
#pragma unroll
        for (int j = 0; j < TN; j++) acc[i][j] = 0.f;

    constexpr int A_F4 = BM * BK / 4;
    for (int k0 = 0; k0 < K; k0 += BK) {
        for (int f = tid; f < A_F4; f += THREADS) {
            int row = f / (BK / 4);
            int kc = (f % (BK / 4)) * 4;
            float4 v = *reinterpret_cast<const float4*>(&A[(size_t)(bm + row) * K + k0 + kc]);
            As[kc + 0][row] = v.x; As[kc + 1][row] = v.y;
            As[kc + 2][row] = v.z; As[kc + 3][row] = v.w;
        }
        for (int f = tid; f < A_F4; f += THREADS) {
            int row = f / (BK / 4);
            int kc = (f % (BK / 4)) * 4;
            float4 v = *reinterpret_cast<const float4*>(&B[(size_t)(bn + row) * K + k0 + kc]);
            Bs[kc + 0][row] = v.x; Bs[kc + 1][row] = v.y;
            Bs[kc + 2][row] = v.z; Bs[kc + 3][row] = v.w;
        }
        __syncthreads();
#pragma unroll
        for (int kk = 0; kk < BK; kk++) {
            float af[TM], bf[TN];
#pragma unroll
            for (int i = 0; i < TM; i++) af[i] = As[kk][ty * TM + i];
#pragma unroll
            for (int j = 0; j < TN; j++) bf[j] = Bs[kk][tx * TN + j];
#pragma unroll
            for (int i = 0; i < TM; i++)
#pragma unroll
                for (int j = 0; j < TN; j++) acc[i][j] += af[i] * bf[j];
        }
        __syncthreads();
    }
#pragma unroll
    for (int i = 0; i < TM; i++) {
        int m = bm + ty * TM + i;
#pragma unroll
        for (int j = 0; j < TN; j++) {
            int n = bn + tx * TN + j;
            float v = acc[i][j];
            if (BIAS) v += bias[n];
            if (RELU) v = fmaxf(v, 0.f);
            if (RND)  v = rndf(v);
            C[(size_t)m * N + n] = v;
        }
    }
}

// ---------------------------------------------------------------------------
// Slot attention, single pass (online max/sumexp + top-10)
// ---------------------------------------------------------------------------
__global__ void slot_attend(const float* __restrict__ S1, const float* __restrict__ vv,
                            const float* __restrict__ e, float* __restrict__ e2cat) {
    __shared__ float sv[256 * KTOP];
    __shared__ int   si[256 * KTOP];
    __shared__ float sm_m[256];
    __shared__ float sm_z[256];
    __shared__ float sw[KTOP];
    __shared__ int   sx[KTOP];
    int s = blockIdx.x, tid = threadIdx.x;
    const float* row = S1 + (size_t)s * N_NODES;
    float tv[KTOP]; int ti[KTOP];
#pragma unroll
    for (int i = 0; i < KTOP; i++) { tv[i] = -INFINITY; ti[i] = 0; }
    float m_loc = -INFINITY, z = 0.f;
    for (int n = tid; n < N_NODES; n += 256) {
        float v = row[n];
        if (v > m_loc) { z *= __expf(m_loc - v); m_loc = v; }
        z += __expf(v - m_loc);
        if (v > tv[KTOP - 1]) {
            int ix = n;
            float vt = v;
#pragma unroll
            for (int p = 0; p < KTOP; p++)
                if (vt > tv[p]) {
                    float tf = tv[p]; tv[p] = vt; vt = tf;
                    int tt = ti[p]; ti[p] = ix; ix = tt;
                }
        }
    }
#pragma unroll
    for (int i = 0; i < KTOP; i++) { sv[tid * KTOP + i] = tv[i]; si[tid * KTOP + i] = ti[i]; }
    sm_m[tid] = m_loc; sm_z[tid] = z;
    __syncthreads();
    for (int stride = 128; stride >= 1; stride >>= 1) {
        if (tid < stride) {
#pragma unroll
            for (int i = 0; i < KTOP; i++) { tv[i] = sv[tid * KTOP + i]; ti[i] = si[tid * KTOP + i]; }
#pragma unroll
            for (int i = 0; i < KTOP; i++) {
                float v = sv[(tid + stride) * KTOP + i];
                int ix = si[(tid + stride) * KTOP + i];
                if (v > tv[KTOP - 1]) {
#pragma unroll
                    for (int p = 0; p < KTOP; p++)
                        if (v > tv[p]) {
                            float tf = tv[p]; tv[p] = v; v = tf;
                            int tt = ti[p]; ti[p] = ix; ix = tt;
                        }
                }
            }
#pragma unroll
            for (int i = 0; i < KTOP; i++) { sv[tid * KTOP + i] = tv[i]; si[tid * KTOP + i] = ti[i]; }
            float ma = sm_m[tid], za = sm_z[tid];
            float mb = sm_m[tid + stride], zb = sm_z[tid + stride];
            float mn = fmaxf(ma, mb);
            float zn = za * __expf(ma - mn) + zb * __expf(mb - mn);
            sm_m[tid] = mn; sm_z[tid] = zn;
        }
        __syncthreads();
    }
    float maxv = sm_m[0];
    float Z = sm_z[0];
    if (tid < KTOP) {
        float p = __expf(sv[tid] - maxv) / Z;
        sw[tid] = (p + EPSC) / (1.f + (float)N_NODES * EPSC);
        sx[tid] = si[tid];
    }
    __syncthreads();
    float acc = 0.f;
#pragma unroll
    for (int i = 0; i < KTOP; i++) acc += sw[i] * vv[(size_t)sx[i] * D + tid];
    e2cat[(size_t)s * 2 * D + D + tid] = acc;
    e2cat[(size_t)s * 2 * D + tid] = e[(size_t)s * D + tid];
}

// ---------------------------------------------------------------------------
// Node attention: one warp per node; dual write (exact + tf32-rounded)
// ---------------------------------------------------------------------------
__global__ void node_attend(const float* __restrict__ S2, const float* __restrict__ edg,
                            float* __restrict__ nodes, float* __restrict__ nodesr) {
    int warp = blockIdx.x * (blockDim.x >> 5) + (threadIdx.x >> 5);
    int lane = threadIdx.x & 31;
    const float* row = S2 + (size_t)warp * NS;
    float dv[16];
#pragma unroll
    for (int j = 0; j < 16; j++) dv[j] = row[lane + 32 * j];
    float tv[KTOP]; int ti[KTOP];
#pragma unroll
    for (int i = 0; i < KTOP; i++) { tv[i] = -INFINITY; ti[i] = 0; }
#pragma unroll
    for (int j = 0; j < 16; j++) {
        float v = dv[j]; int ix = lane + 32 * j;
        if (v > tv[KTOP - 1]) {
#pragma unroll
            for (int p = 0; p < KTOP; p++)
                if (v > tv[p]) {
                    float tf = tv[p]; tv[p] = v; v = tf;
                    int tt = ti[p]; ti[p] = ix; ix = tt;
                }
        }
    }
#pragma unroll
    for (int st = 16; st >= 1; st >>= 1) {
        float ov[KTOP]; int oi[KTOP];
#pragma unroll
        for (int i = 0; i < KTOP; i++) {
            ov[i] = __shfl_down_sync(0xffffffffu, tv[i], st);
            oi[i] = __shfl_down_sync(0xffffffffu, ti[i], st);
        }
#pragma unroll
        for (int i = 0; i < KTOP; i++) {
            float v = ov[i]; int ix = oi[i];
            if (v > tv[KTOP - 1]) {
#pragma unroll
                for (int p = 0; p < KTOP; p++)
                    if (v > tv[p]) {
                        float tf = tv[p]; tv[p] = v; v = tf;
                        int tt = ti[p]; ti[p] = ix; ix = tt;
                    }
            }
        }
    }
    float maxv = __shfl_sync(0xffffffffu, tv[0], 0);
    float z = 0.f;
#pragma unroll
    for (int j = 0; j < 16; j++) z += __expf(dv[j] - maxv);
#pragma unroll
    for (int st = 16; st; st >>= 1) z += __shfl_xor_sync(0xffffffffu, z, st);
    float zin = 1.f / z;
    float w_[KTOP]; int ix_[KTOP];
#pragma unroll
    for (int i = 0; i < KTOP; i++) {
        float v = __shfl_sync(0xffffffffu, tv[i], 0);
        ix_[i] = __shfl_sync(0xffffffffu, ti[i], 0);
        w_[i] = __expf(v - maxv) * zin;
    }
    float* po = nodes + (size_t)warp * D;
    float* pr = nodesr + (size_t)warp * D;
#pragma unroll
    for (int j = 0; j < 8; j++) {
        int c = lane + 32 * j;
        float acc = 0.f;
#pragma unroll
        for (int i = 0; i < KTOP; i++) acc += w_[i] * edg[(size_t)ix_[i] * D + c];
        po[c] = acc;
        pr[c] = rndf(acc);
    }
}

// ---------------------------------------------------------------------------
// Launch
// ---------------------------------------------------------------------------
extern "C" void kernel_launch(void* const* d_in, const int* in_sizes, int n_in,
                              void* d_out, int out_size) {
    (void)in_sizes; (void)n_in; (void)out_size;
    const float* x      = (const float*)d_in[0];
    const float* enoise = (const float*)d_in[1];
    const float* emu    = (const float*)d_in[2];
    const float* elog   = (const float*)d_in[3];
    const float* lnw    = (const float*)d_in[4];
    const float* lnb    = (const float*)d_in[5];
    const float* lew    = (const float*)d_in[6];
    const float* leb    = (const float*)d_in[7];
    const float* Wq = (const float*)d_in[8];  const float* bq = (const float*)d_in[9];
    const float* Wk = (const float*)d_in[10]; const float* bk = (const float*)d_in[11];
    const float* Wv = (const float*)d_in[12]; const float* bv = (const float*)d_in[13];
    const float* Wm1 = (const float*)d_in[14]; const float* bm1 = (const float*)d_in[15];
    const float* Wm2 = (const float*)d_in[16]; const float* bm2 = (const float*)d_in[17];
    const float* cw = (const float*)d_in[18];  const float* cb = (const float*)d_in[19];
    const float* Wc0 = (const float*)d_in[20]; const float* bc0 = (const float*)d_in[21];
    const float* Wc1 = (const float*)d_in[22]; const float* bc1 = (const float*)d_in[23];
    const float* Wt = (const float*)d_in[24];  const float* bt = (const float*)d_in[25];
    float* out = (float*)d_out;

    void* p;
    cudaGetSymbolAddress(&p, g_xin);   float* xin = (float*)p;
    cudaGetSymbolAddress(&p, g_xr);    float* xr = (float*)p;
    cudaGetSymbolAddress(&p, g_kk);    float* kkb = (float*)p;
    cudaGetSymbolAddress(&p, g_vv);    float* vvb = (float*)p;
    cudaGetSymbolAddress(&p, g_q2);    float* q2b = (float*)p;
    cudaGetSymbolAddress(&p, g_nodes); float* nodesb = (float*)p;
    cudaGetSymbolAddress(&p, g_noder); float* nodesr = (float*)p;
    cudaGetSymbolAddress(&p, g_tmp);   float* tmp = (float*)p;
    cudaGetSymbolAddress(&p, g_S);     float* S = (float*)p;
    cudaGetSymbolAddress(&p, g_e);     float* e = (float*)p;
    cudaGetSymbolAddress(&p, g_q);     float* qb = (float*)p;
    cudaGetSymbolAddress(&p, g_e2cat); float* e2cat = (float*)p;
    cudaGetSymbolAddress(&p, g_h1);    float* h1 = (float*)p;
    cudaGetSymbolAddress(&p, g_e2);    float* e2 = (float*)p;
    cudaGetSymbolAddress(&p, g_k2);    float* k2 = (float*)p;
    cudaGetSymbolAddress(&p, g_edg);   float* edg = (float*)p;
    cudaGetSymbolAddress(&p, g_Wkvq);  float* Wkvq = (float*)p;
    cudaGetSymbolAddress(&p, g_bkvq);  float* bkvq = (float*)p;
    cudaGetSymbolAddress(&p, g_Wm1T);  float* Wm1T = (float*)p;
    cudaGetSymbolAddress(&p, g_Wm2T);  float* Wm2T = (float*)p;
    cudaGetSymbolAddress(&p, g_cwT);   float* cwT = (float*)p;
    cudaGetSymbolAddress(&p, g_Wc0T);  float* Wc0T = (float*)p;
    cudaGetSymbolAddress(&p, g_Wc1T);  float* Wc1T = (float*)p;
    cudaGetSymbolAddress(&p, g_WtT);   float* WtT = (float*)p;

    cudaFuncSetAttribute(mma_gemm<0, false>, cudaFuncAttributeMaxDynamicSharedMemorySize, MMA_SMEM_BYTES);
    cudaFuncSetAttribute(mma_gemm<1, false>, cudaFuncAttributeMaxDynamicSharedMemorySize, MMA_SMEM_BYTES);
    cudaFuncSetAttribute(mma_gemm<2, false>, cudaFuncAttributeMaxDynamicSharedMemorySize, MMA_SMEM_BYTES);
    cudaFuncSetAttribute(mma_gemm<3, true>,  cudaFuncAttributeMaxDynamicSharedMemorySize, MMA_SMEM_BYTES);
    cudaFuncSetAttribute(mma_gemm<4, true>,  cudaFuncAttributeMaxDynamicSharedMemorySize, MMA_SMEM_BYTES);

    float* WkT = Wkvq;
    float* WvT = Wkvq + D * D;
    float* WqT = Wkvq + 2 * D * D;

    dim3 tb(32, 8);
    transpose_k<true><<<dim3(8, 8), tb>>>(Wk, WkT, D, D);
    transpose_k<true><<<dim3(8, 8), tb>>>(Wv, WvT, D, D);
    transpose_k<true><<<dim3(8, 8), tb>>>(Wq, WqT, D, D);
    transpose_k<false><<<dim3(8, 16), tb>>>(Wm1, Wm1T, 2 * D, HID);
    transpose_k<false><<<dim3(8, 8), tb>>>(Wm2, Wm2T, HID, D);
    transpose_k<false><<<dim3(8, 8), tb>>>(cw, cwT, D, D);
    transpose_k<true><<<dim3(8, 8), tb>>>(Wc0, Wc0T, D, D);
    transpose_k<true><<<dim3(8, 8), tb>>>(Wc1, Wc1T, D, D);
    transpose_k<true><<<dim3(8, 8), tb>>>(Wt, WtT, D, D);
    concat3<<<1, D>>>(bk, bv, bq, bkvq);

    copy_round<<<(N_NODES * D / 4 + 255) / 256, 256>>>(
        (const float4*)x, (float4*)xr, N_NODES * D / 4);

    ln_rows<<<N_NODES / 8, 256>>>(x, lnw, lnb, xin, N_NODES);
    edges_ln<<<NS / 8, 256>>>(enoise, emu, elog, lew, leb, e);

    // fused: kk = relu(xin@Wk+bk) [rnd], vv = relu(xin@Wv+bv) [exact], q2 = xin@Wq+bq [rnd]
    mma_gemm<4, true><<<dim3(6, 512), 256, MMA_SMEM_BYTES>>>(
        xin, Wkvq, kkb, bkvq, nullptr, vvb, q2b, N_NODES, 3 * D, D, 1.f);

    // q = relu(e@Wq+bq)  [rnd: feeds dots1 A]
    gemm_small<true, true, true><<<dim3(4, 8), 256>>>(e, WqT, qb, bq, NS, D, D);

    // dots1 = q @ kk^T * SCALE  -> S [NS, N]
    mma_gemm<0, false><<<dim3(512, 4), 256, MMA_SMEM_BYTES>>>(
        qb, kkb, S, nullptr, nullptr, nullptr, nullptr, NS, N_NODES, D, SCALE_C);

    slot_attend<<<NS, 256>>>(S, vvb, e, e2cat);

    // slot MLP
    gemm_small<true, true, false><<<dim3(4, 8), 256>>>(e2cat, Wm1T, h1, bm1, NS, HID, 2 * D);
    gemm_small<true, false, false><<<dim3(4, 8), 256>>>(h1, Wm2T, e2, bm2, NS, D, HID);

    // k2 = relu(e2@Wk+bk) [rnd: feeds dots2 B]; edg = e2@conv_w+conv_b [exact]
    gemm_small<true, true, true><<<dim3(4, 8), 256>>>(e2, WkT, k2, bk, NS, D, D);
    gemm_small<true, false, false><<<dim3(4, 8), 256>>>(e2, cwT, edg, cb, NS, D, D);

    // dots2 = q2 @ k2^T * SCALE  -> S [N, NS]
    mma_gemm<0, false><<<dim3(4, 512), 256, MMA_SMEM_BYTES>>>(
        q2b, k2, S, nullptr, nullptr, nullptr, nullptr, N_NODES, NS, D, SCALE_C);

    node_attend<<<N_NODES / 8, 256>>>(S, edg, nodesb, nodesr);

    // tmp = x@Wc0 + bc0   (exact store; consumed as C-addend)
    mma_gemm<1, false><<<dim3(2, 512), 256, MMA_SMEM_BYTES>>>(
        xr, Wc0T, tmp, bc0, nullptr, nullptr, nullptr, N_NODES, D, D, 1.f);
    // tmp = relu(tmp + nodesr@Wc1 + bc1 + nodes)  [rnd: feeds Wt A]
    mma_gemm<3, true><<<dim3(2, 512), 256, MMA_SMEM_BYTES>>>(
        nodesr, Wc1T, tmp, bc1, nodesb, nullptr, nullptr, N_NODES, D, D, 1.f);
    // out = relu(tmp@Wt + bt)   (final, exact)
    mma_gemm<2, false><<<dim3(2, 512), 256, MMA_SMEM_BYTES>>>(
        tmp, WtT, out, bt, nullptr, nullptr, nullptr, N_NODES, D, D, 1.f);
}

// round 7
// speedup vs baseline: 3.0951x; 1.1747x over previous
#include <cuda_runtime.h>
#include <cuda_fp16.h>
#include <math.h>
#include <stdint.h>

#define N_NODES 65536
#define D       256
#define NS      512
#define HID     256
#define KTOP    10
#define EPSC    1e-8f
#define SCALE_C 0.0625f  /* 256^-0.5 */

// ---------------------------------------------------------------------------
// Scratch
// ---------------------------------------------------------------------------
__device__ __half g_xh  [(size_t)N_NODES * D];   // LN(x), half
__device__ __half g_xrh [(size_t)N_NODES * D];   // x rounded to half
__device__ __half g_kkh [(size_t)N_NODES * D];
__device__ __half g_q2h [(size_t)N_NODES * D];
__device__ __half g_ndh [(size_t)N_NODES * D];   // nodes half
__device__ __half g_tmph[(size_t)N_NODES * D];
__device__ float  g_vv  [(size_t)N_NODES * D];   // exact
__device__ float  g_nodes[(size_t)N_NODES * D];  // exact
__device__ float  g_tmp [(size_t)N_NODES * D];   // exact addend
__device__ float  g_S   [(size_t)N_NODES * NS];

__device__ float  g_e    [NS * D];
__device__ __half g_qh   [NS * D];
__device__ __half g_k2h  [NS * D];
__device__ float  g_e2cat[NS * 2 * D];
__device__ float  g_h1   [NS * HID];
__device__ float  g_e2   [NS * D];
__device__ float  g_edg  [NS * D];

__device__ __half g_Wkvqh[3 * D * D];  // half weights for big GEMMs
__device__ __half g_Wc0h [D * D];
__device__ __half g_Wc1h [D * D];
__device__ __half g_Wth  [D * D];
__device__ float  g_bkvq [3 * D];
__device__ float  g_WqTf [D * D];      // fp32 transposed weights for small GEMMs
__device__ float  g_WkTf [D * D];
__device__ float  g_Wm1T [HID * 2 * D];
__device__ float  g_Wm2T [D * HID];
__device__ float  g_cwT  [D * D];

// ---------------------------------------------------------------------------
// helpers
// ---------------------------------------------------------------------------
__device__ __forceinline__ void mma16n8k16(float& c0, float& c1, float& c2, float& c3,
                                           uint32_t a0, uint32_t a1, uint32_t a2, uint32_t a3,
                                           uint32_t b0, uint32_t b1) {
    asm volatile(
        "mma.sync.aligned.m16n8k16.row.col.f32.f16.f16.f32 "
        "{%0,%1,%2,%3}, {%4,%5,%6,%7}, {%8,%9}, {%0,%1,%2,%3};"
        : "+f"(c0), "+f"(c1), "+f"(c2), "+f"(c3)
        : "r"(a0), "r"(a1), "r"(a2), "r"(a3), "r"(b0), "r"(b1));
}
__device__ __forceinline__ void ldsm_x4(uint32_t& r0, uint32_t& r1, uint32_t& r2, uint32_t& r3,
                                        uint32_t addr) {
    asm volatile("ldmatrix.sync.aligned.m8n8.x4.shared.b16 {%0,%1,%2,%3}, [%4];"
                 : "=r"(r0), "=r"(r1), "=r"(r2), "=r"(r3) : "r"(addr));
}
__device__ __forceinline__ void cp_async16(void* smem_dst, const void* gmem_src) {
    uint32_t d = (uint32_t)__cvta_generic_to_shared(smem_dst);
    asm volatile("cp.async.cg.shared.global [%0], [%1], 16;" :: "r"(d), "l"(gmem_src));
}
__device__ __forceinline__ void cp_commit() { asm volatile("cp.async.commit_group;"); }
__device__ __forceinline__ void cp_wait1()  { asm volatile("cp.async.wait_group 1;"); }

// ---------------------------------------------------------------------------
// Pipelined fp16 NT GEMM (fp32 accumulate), ldmatrix fragments.
// A:[M,K] half rowmajor, B:[*,K] half rowmajor. 128x128x32 tile, 8 warps.
// EPI: 0 = C=acc*scale           (fp32)
//      1 = C=acc+bias            (fp32)
//      2 = C=relu(acc+bias)      (fp32)
//      3 = Ch=relu(acc+bias+C+aux) (half out, fp32 C/aux in)
//      4 = kvq: seg0 Ch=relu(+b), seg1 Cf2=relu(+b) fp32, seg2 Ch2=+b
// ---------------------------------------------------------------------------
#define LDH   40                         // halves per SMEM row (80 B)
#define HBUF  (128 * LDH)                // halves per tile buffer
#define MMA_SMEM_BYTES (4 * HBUF * 2)    // 2 bufs x (A+B) = 40960 B

template <int EPI>
__global__ void __launch_bounds__(256) mma_gemm(
    const __half* __restrict__ A, const __half* __restrict__ B,
    float* __restrict__ C, const float* __restrict__ bias,
    const float* __restrict__ aux, float* __restrict__ Cf2,
    __half* __restrict__ Ch, __half* __restrict__ Ch2,
    int M, int Ntot, int K, float scale) {
    extern __shared__ __half smh[];
    const int tid = threadIdx.x;
    const int wid = tid >> 5, lane = tid & 31;
    const int warp_m = wid & 3;
    const int warp_n = wid >> 2;
    const int bm = blockIdx.y * 128;
    const int bn = blockIdx.x * 128;
    const int grp = lane >> 2;
    const int tig = lane & 3;

    const uint32_t smb = (uint32_t)__cvta_generic_to_shared(smh);
    // buffers (half offsets): A0=0, A1=HBUF, B0=2*HBUF, B1=3*HBUF

    // ldmatrix lane offsets (bytes)
    uint32_t a_off[2];
#pragma unroll
    for (int mt = 0; mt < 2; mt++)
        a_off[mt] = ((warp_m * 32 + mt * 16 + (lane & 15)) * LDH + (lane >> 4) * 8) * 2;
    const int b_row = (lane & 7) + ((lane >> 4) & 1) * 8;
    const int b_koff = ((lane >> 3) & 1) * 8;
    uint32_t b_off[4];
#pragma unroll
    for (int p = 0; p < 4; p++)
        b_off[p] = ((warp_n * 64 + p * 16 + b_row) * LDH + b_koff) * 2;

    float acc[2][8][4];
#pragma unroll
    for (int i = 0; i < 2; i++)
#pragma unroll
        for (int j = 0; j < 8; j++)
#pragma unroll
            for (int r = 0; r < 4; r++) acc[i][j][r] = 0.f;

    const int NCH = K >> 5;

    auto load_tile = [&](int ch, int buf) {
        const __half* Ag = A + (size_t)bm * K + ch * 32;
        const __half* Bg = B + (size_t)bn * K + ch * 32;
        __half* Ad = smh + buf * HBUF;
        __half* Bd = smh + (2 + buf) * HBUF;
#pragma unroll
        for (int i = 0; i < 2; i++) {
            int id = tid + (i << 8);            // 0..511 chunks of 16B
            int row = id >> 2, c8 = (id & 3) << 3;
            cp_async16(Ad + row * LDH + c8, Ag + (size_t)row * K + c8);
            cp_async16(Bd + row * LDH + c8, Bg + (size_t)row * K + c8);
        }
    };

    load_tile(0, 0);
    cp_commit();

    for (int ch = 0; ch < NCH; ch++) {
        if (ch + 1 < NCH) load_tile(ch + 1, (ch + 1) & 1);
        cp_commit();
        cp_wait1();
        __syncthreads();
        const uint32_t Ab = smb + (ch & 1) * HBUF * 2;
        const uint32_t Bb = smb + (2 + (ch & 1)) * HBUF * 2;
#pragma unroll
        for (int ks = 0; ks < 32; ks += 16) {
            uint32_t ra[2][4], rb[4][4];
#pragma unroll
            for (int mt = 0; mt < 2; mt++)
                ldsm_x4(ra[mt][0], ra[mt][1], ra[mt][2], ra[mt][3], Ab + a_off[mt] + ks * 2);
#pragma unroll
            for (int p = 0; p < 4; p++)
                ldsm_x4(rb[p][0], rb[p][1], rb[p][2], rb[p][3], Bb + b_off[p] + ks * 2);
#pragma unroll
            for (int p = 0; p < 4; p++)
#pragma unroll
                for (int mt = 0; mt < 2; mt++) {
                    mma16n8k16(acc[mt][2 * p][0], acc[mt][2 * p][1],
                               acc[mt][2 * p][2], acc[mt][2 * p][3],
                               ra[mt][0], ra[mt][1], ra[mt][2], ra[mt][3],
                               rb[p][0], rb[p][1]);
                    mma16n8k16(acc[mt][2 * p + 1][0], acc[mt][2 * p + 1][1],
                               acc[mt][2 * p + 1][2], acc[mt][2 * p + 1][3],
                               ra[mt][0], ra[mt][1], ra[mt][2], ra[mt][3],
                               rb[p][2], rb[p][3]);
                }
        }
        __syncthreads();
    }

    // epilogue: acc[mt][nt][{0,1}] = rows g / cols 2tig,2tig+1; [{2,3}] = row g+8
#pragma unroll
    for (int mt = 0; mt < 2; mt++) {
        int r0 = bm + warp_m * 32 + mt * 16 + grp;
#pragma unroll
        for (int nt = 0; nt < 8; nt++) {
            int c0 = bn + warp_n * 64 + nt * 8 + 2 * tig;
#pragma unroll
            for (int half_ = 0; half_ < 2; half_++) {
                int rr = r0 + half_ * 8;
                float vx = acc[mt][nt][2 * half_ + 0];
                float vy = acc[mt][nt][2 * half_ + 1];
                if constexpr (EPI == 0) {
                    size_t idx = (size_t)rr * Ntot + c0;
                    float2 o; o.x = vx * scale; o.y = vy * scale;
                    *reinterpret_cast<float2*>(C + idx) = o;
                } else if constexpr (EPI == 4) {
                    vx += bias[c0]; vy += bias[c0 + 1];
                    int seg = c0 >> 8;
                    size_t idx = (size_t)rr * D + (c0 & 255);
                    if (seg == 0) {
                        vx = fmaxf(vx, 0.f); vy = fmaxf(vy, 0.f);
                        *reinterpret_cast<__half2*>(Ch + idx) = __floats2half2_rn(vx, vy);
                    } else if (seg == 1) {
                        vx = fmaxf(vx, 0.f); vy = fmaxf(vy, 0.f);
                        float2 o; o.x = vx; o.y = vy;
                        *reinterpret_cast<float2*>(Cf2 + idx) = o;
                    } else {
                        *reinterpret_cast<__half2*>(Ch2 + idx) = __floats2half2_rn(vx, vy);
                    }
                } else if constexpr (EPI == 3) {
                    size_t idx = (size_t)rr * Ntot + c0;
                    float2 cc = *reinterpret_cast<const float2*>(C + idx);
                    float2 aa = *reinterpret_cast<const float2*>(aux + idx);
                    vx += bias[c0] + cc.x + aa.x;
                    vy += bias[c0 + 1] + cc.y + aa.y;
                    vx = fmaxf(vx, 0.f); vy = fmaxf(vy, 0.f);
                    *reinterpret_cast<__half2*>(Ch + idx) = __floats2half2_rn(vx, vy);
                } else {
                    vx += bias[c0]; vy += bias[c0 + 1];
                    if constexpr (EPI == 2) { vx = fmaxf(vx, 0.f); vy = fmaxf(vy, 0.f); }
                    size_t idx = (size_t)rr * Ntot + c0;
                    float2 o; o.x = vx; o.y = vy;
                    *reinterpret_cast<float2*>(C + idx) = o;
                }
            }
        }
    }
}

// ---------------------------------------------------------------------------
// Transpose [R,C] -> [C,R]; OUT=float or __half
// ---------------------------------------------------------------------------
template <typename OUT>
__global__ void transpose_k(const float* __restrict__ in, OUT* __restrict__ out,
                            int R, int C) {
    __shared__ float tile[32][33];
    int bx = blockIdx.x * 32, by = blockIdx.y * 32;
    int x = threadIdx.x;
    for (int y = threadIdx.y; y < 32; y += 8)
        tile[y][x] = in[(size_t)(by + y) * C + bx + x];
    __syncthreads();
    for (int y = threadIdx.y; y < 32; y += 8)
        out[(size_t)(bx + y) * R + by + x] = (OUT)tile[x][y];
}

__global__ void concat3(const float* __restrict__ a, const float* __restrict__ b,
                        const float* __restrict__ c, float* __restrict__ o) {
    int i = threadIdx.x;
    o[i] = a[i]; o[D + i] = b[i]; o[2 * D + i] = c[i];
}

__global__ void copy_half(const float2* __restrict__ in, __half2* __restrict__ out, int n2) {
    int i = blockIdx.x * blockDim.x + threadIdx.x;
    if (i < n2) {
        float2 v = in[i];
        out[i] = __floats2half2_rn(v.x, v.y);
    }
}

// ---------------------------------------------------------------------------
// LayerNorm -> half output (only consumed as GEMM operand)
// ---------------------------------------------------------------------------
__global__ void ln_rows(const float* __restrict__ x, const float* __restrict__ w,
                        const float* __restrict__ b, __half* __restrict__ o, int M) {
    int warp = (blockIdx.x * blockDim.x + threadIdx.x) >> 5;
    int lane = threadIdx.x & 31;
    if (warp >= M) return;
    const float* r = x + (size_t)warp * D;
    float v[8]; float s = 0.f;
#pragma unroll
    for (int j = 0; j < 8; j++) { v[j] = r[lane + 32 * j]; s += v[j]; }
#pragma unroll
    for (int st = 16; st; st >>= 1) s += __shfl_xor_sync(0xffffffffu, s, st);
    float mu = s * (1.f / 256.f);
    float q = 0.f;
#pragma unroll
    for (int j = 0; j < 8; j++) { float d = v[j] - mu; q += d * d; }
#pragma unroll
    for (int st = 16; st; st >>= 1) q += __shfl_xor_sync(0xffffffffu, q, st);
    float rinv = rsqrtf(q * (1.f / 256.f) + 1e-5f);
    __half* po = o + (size_t)warp * D;
#pragma unroll
    for (int j = 0; j < 8; j++) {
        int c = lane + 32 * j;
        po[c] = __float2half_rn((v[j] - mu) * rinv * w[c] + b[c]);
    }
}

// edges LN (exact fp32: feeds small gemms + concat)
__global__ void edges_ln(const float* __restrict__ noise, const float* __restrict__ emu,
                         const float* __restrict__ elog, const float* __restrict__ w,
                         const float* __restrict__ b, float* __restrict__ o) {
    int warp = (blockIdx.x * blockDim.x + threadIdx.x) >> 5;
    int lane = threadIdx.x & 31;
    if (warp >= NS) return;
    const float* r = noise + (size_t)warp * D;
    float v[8]; float s = 0.f;
#pragma unroll
    for (int j = 0; j < 8; j++) {
        int c = lane + 32 * j;
        v[j] = emu[c] + expf(elog[c]) * r[c];
        s += v[j];
    }
#pragma unroll
    for (int st = 16; st; st >>= 1) s += __shfl_xor_sync(0xffffffffu, s, st);
    float mu = s * (1.f / 256.f);
    float q = 0.f;
#pragma unroll
    for (int j = 0; j < 8; j++) { float d = v[j] - mu; q += d * d; }
#pragma unroll
    for (int st = 16; st; st >>= 1) q += __shfl_xor_sync(0xffffffffu, q, st);
    float rinv = rsqrtf(q * (1.f / 256.f) + 1e-5f);
    float* po = o + (size_t)warp * D;
#pragma unroll
    for (int j = 0; j < 8; j++) {
        int c = lane + 32 * j;
        po[c] = (v[j] - mu) * rinv * w[c] + b[c];
    }
}

// ---------------------------------------------------------------------------
// Small fp32 NT GEMM (NS-sized): 64x64 tile; optional half output
// ---------------------------------------------------------------------------
template <bool BIAS, bool RELU, bool OUTH>
__global__ void gemm_small(const float* __restrict__ A, const float* __restrict__ B,
                           float* __restrict__ C, __half* __restrict__ Ch,
                           const float* __restrict__ bias, int M, int N, int K) {
    constexpr int BM = 64, BN = 64, BK = 16, TM = 4, TN = 4;
    constexpr int THREADS = 256;
    __shared__ float As[BK][BM + 4];
    __shared__ float Bs[BK][BN + 4];
    const int bm = blockIdx.y * BM;
    const int bn = blockIdx.x * BN;
    const int tid = threadIdx.x;
    const int tx = tid % (BN / TN);
    const int ty = tid / (BN / TN);
    float acc[TM][TN];
#pragma unroll
    for (int i = 0; i < TM; i++)
#pragma unroll
        for (int j = 0; j < TN; j++) acc[i][j] = 0.f;

    constexpr int A_F4 = BM * BK / 4;
    for (int k0 = 0; k0 < K; k0 += BK) {
        for (int f = tid; f < A_F4; f += THREADS) {
            int row = f / (BK / 4);
            int kc = (f % (BK / 4)) * 4;
            float4 v = *reinterpret_cast<const float4*>(&A[(size_t)(bm + row) * K + k0 + kc]);
            As[kc + 0][row] = v.x; As[kc + 1][row] = v.y;
            As[kc + 2][row] = v.z; As[kc + 3][row] = v.w;
        }
        for (int f = tid; f < A_F4; f += THREADS) {
            int row = f / (BK / 4);
            int kc = (f % (BK / 4)) * 4;
            float4 v = *reinterpret_cast<const float4*>(&B[(size_t)(bn + row) * K + k0 + kc]);
            Bs[kc + 0][row] = v.x; Bs[kc + 1][row] = v.y;
            Bs[kc + 2][row] = v.z; Bs[kc + 3][row] = v.w;
        }
        __syncthreads();
#pragma unroll
        for (int kk = 0; kk < BK; kk++) {
            float af[TM], bf[TN];
#pragma unroll
            for (int i = 0; i < TM; i++) af[i] = As[kk][ty * TM + i];
#pragma unroll
            for (int j = 0; j < TN; j++) bf[j] = Bs[kk][tx * TN + j];
#pragma unroll
            for (int i = 0; i < TM; i++)
#pragma unroll
                for (int j = 0; j < TN; j++) acc[i][j] += af[i] * bf[j];
        }
        __syncthreads();
    }
#pragma unroll
    for (int i = 0; i < TM; i++) {
        int m = bm + ty * TM + i;
#pragma unroll
        for (int j = 0; j < TN; j++) {
            int n = bn + tx * TN + j;
            float v = acc[i][j];
            if (BIAS) v += bias[n];
            if (RELU) v = fmaxf(v, 0.f);
            if (OUTH) Ch[(size_t)m * N + n] = __float2half_rn(v);
            else      C [(size_t)m * N + n] = v;
        }
    }
}

// ---------------------------------------------------------------------------
// Slot attention (single pass, exact fp32)
// ---------------------------------------------------------------------------
__global__ void slot_attend(const float* __restrict__ S1, const float* __restrict__ vv,
                            const float* __restrict__ e, float* __restrict__ e2cat) {
    __shared__ float sv[256 * KTOP];
    __shared__ int   si[256 * KTOP];
    __shared__ float sm_m[256];
    __shared__ float sm_z[256];
    __shared__ float sw[KTOP];
    __shared__ int   sx[KTOP];
    int s = blockIdx.x, tid = threadIdx.x;
    const float* row = S1 + (size_t)s * N_NODES;
    float tv[KTOP]; int ti[KTOP];
#pragma unroll
    for (int i = 0; i < KTOP; i++) { tv[i] = -INFINITY; ti[i] = 0; }
    float m_loc = -INFINITY, z = 0.f;
    for (int n = tid; n < N_NODES; n += 256) {
        float v = row[n];
        if (v > m_loc) { z *= __expf(m_loc - v); m_loc = v; }
        z += __expf(v - m_loc);
        if (v > tv[KTOP - 1]) {
            int ix = n;
            float vt = v;
#pragma unroll
            for (int p = 0; p < KTOP; p++)
                if (vt > tv[p]) {
                    float tf = tv[p]; tv[p] = vt; vt = tf;
                    int tt = ti[p]; ti[p] = ix; ix = tt;
                }
        }
    }
#pragma unroll
    for (int i = 0; i < KTOP; i++) { sv[tid * KTOP + i] = tv[i]; si[tid * KTOP + i] = ti[i]; }
    sm_m[tid] = m_loc; sm_z[tid] = z;
    __syncthreads();
    for (int stride = 128; stride >= 1; stride >>= 1) {
        if (tid < stride) {
#pragma unroll
            for (int i = 0; i < KTOP; i++) { tv[i] = sv[tid * KTOP + i]; ti[i] = si[tid * KTOP + i]; }
#pragma unroll
            for (int i = 0; i < KTOP; i++) {
                float v = sv[(tid + stride) * KTOP + i];
                int ix = si[(tid + stride) * KTOP + i];
                if (v > tv[KTOP - 1]) {
#pragma unroll
                    for (int p = 0; p < KTOP; p++)
                        if (v > tv[p]) {
                            float tf = tv[p]; tv[p] = v; v = tf;
                            int tt = ti[p]; ti[p] = ix; ix = tt;
                        }
                }
            }
#pragma unroll
            for (int i = 0; i < KTOP; i++) { sv[tid * KTOP + i] = tv[i]; si[tid * KTOP + i] = ti[i]; }
            float ma = sm_m[tid], za = sm_z[tid];
            float mb = sm_m[tid + stride], zb = sm_z[tid + stride];
            float mn = fmaxf(ma, mb);
            float zn = za * __expf(ma - mn) + zb * __expf(mb - mn);
            sm_m[tid] = mn; sm_z[tid] = zn;
        }
        __syncthreads();
    }
    float maxv = sm_m[0];
    float Z = sm_z[0];
    if (tid < KTOP) {
        float p = __expf(sv[tid] - maxv) / Z;
        sw[tid] = (p + EPSC) / (1.f + (float)N_NODES * EPSC);
        sx[tid] = si[tid];
    }
    __syncthreads();
    float acc = 0.f;
#pragma unroll
    for (int i = 0; i < KTOP; i++) acc += sw[i] * vv[(size_t)sx[i] * D + tid];
    e2cat[(size_t)s * 2 * D + D + tid] = acc;
    e2cat[(size_t)s * 2 * D + tid] = e[(size_t)s * D + tid];
}

// ---------------------------------------------------------------------------
// Node attention: dual write (fp32 exact + half)
// ---------------------------------------------------------------------------
__global__ void node_attend(const float* __restrict__ S2, const float* __restrict__ edg,
                            float* __restrict__ nodes, __half* __restrict__ nodesh) {
    int warp = blockIdx.x * (blockDim.x >> 5) + (threadIdx.x >> 5);
    int lane = threadIdx.x & 31;
    const float* row = S2 + (size_t)warp * NS;
    float dv[16];
#pragma unroll
    for (int j = 0; j < 16; j++) dv[j] = row[lane + 32 * j];
    float tv[KTOP]; int ti[KTOP];
#pragma unroll
    for (int i = 0; i < KTOP; i++) { tv[i] = -INFINITY; ti[i] = 0; }
#pragma unroll
    for (int j = 0; j < 16; j++) {
        float v = dv[j]; int ix = lane + 32 * j;
        if (v > tv[KTOP - 1]) {
#pragma unroll
            for (int p = 0; p < KTOP; p++)
                if (v > tv[p]) {
                    float tf = tv[p]; tv[p] = v; v = tf;
                    int tt = ti[p]; ti[p] = ix; ix = tt;
                }
        }
    }
#pragma unroll
    for (int st = 16; st >= 1; st >>= 1) {
        float ov[KTOP]; int oi[KTOP];
#pragma unroll
        for (int i = 0; i < KTOP; i++) {
            ov[i] = __shfl_down_sync(0xffffffffu, tv[i], st);
            oi[i] = __shfl_down_sync(0xffffffffu, ti[i], st);
        }
#pragma unroll
        for (int i = 0; i < KTOP; i++) {
            float v = ov[i]; int ix = oi[i];
            if (v > tv[KTOP - 1]) {
#pragma unroll
                for (int p = 0; p < KTOP; p++)
                    if (v > tv[p]) {
                        float tf = tv[p]; tv[p] = v; v = tf;
                        int tt = ti[p]; ti[p] = ix; ix = tt;
                    }
            }
        }
    }
    float maxv = __shfl_sync(0xffffffffu, tv[0], 0);
    float z = 0.f;
#pragma unroll
    for (int j = 0; j < 16; j++) z += __expf(dv[j] - maxv);
#pragma unroll
    for (int st = 16; st; st >>= 1) z += __shfl_xor_sync(0xffffffffu, z, st);
    float zin = 1.f / z;
    float w_[KTOP]; int ix_[KTOP];
#pragma unroll
    for (int i = 0; i < KTOP; i++) {
        float v = __shfl_sync(0xffffffffu, tv[i], 0);
        ix_[i] = __shfl_sync(0xffffffffu, ti[i], 0);
        w_[i] = __expf(v - maxv) * zin;
    }
    float* po = nodes + (size_t)warp * D;
    __half* ph = nodesh + (size_t)warp * D;
#pragma unroll
    for (int j = 0; j < 8; j++) {
        int c = lane + 32 * j;
        float acc = 0.f;
#pragma unroll
        for (int i = 0; i < KTOP; i++) acc += w_[i] * edg[(size_t)ix_[i] * D + c];
        po[c] = acc;
        ph[c] = __float2half_rn(acc);
    }
}

// ---------------------------------------------------------------------------
// Launch
// ---------------------------------------------------------------------------
extern "C" void kernel_launch(void* const* d_in, const int* in_sizes, int n_in,
                              void* d_out, int out_size) {
    (void)in_sizes; (void)n_in; (void)out_size;
    const float* x      = (const float*)d_in[0];
    const float* enoise = (const float*)d_in[1];
    const float* emu    = (const float*)d_in[2];
    const float* elog   = (const float*)d_in[3];
    const float* lnw    = (const float*)d_in[4];
    const float* lnb    = (const float*)d_in[5];
    const float* lew    = (const float*)d_in[6];
    const float* leb    = (const float*)d_in[7];
    const float* Wq = (const float*)d_in[8];  const float* bq = (const float*)d_in[9];
    const float* Wk = (const float*)d_in[10]; const float* bk = (const float*)d_in[11];
    const float* Wv = (const float*)d_in[12]; const float* bv = (const float*)d_in[13];
    const float* Wm1 = (const float*)d_in[14]; const float* bm1 = (const float*)d_in[15];
    const float* Wm2 = (const float*)d_in[16]; const float* bm2 = (const float*)d_in[17];
    const float* cw = (const float*)d_in[18];  const float* cb = (const float*)d_in[19];
    const float* Wc0 = (const float*)d_in[20]; const float* bc0 = (const float*)d_in[21];
    const float* Wc1 = (const float*)d_in[22]; const float* bc1 = (const float*)d_in[23];
    const float* Wt = (const float*)d_in[24];  const float* bt = (const float*)d_in[25];
    float* out = (float*)d_out;

    void* p;
    cudaGetSymbolAddress(&p, g_xh);    __half* xh = (__half*)p;
    cudaGetSymbolAddress(&p, g_xrh);   __half* xrh = (__half*)p;
    cudaGetSymbolAddress(&p, g_kkh);   __half* kkh = (__half*)p;
    cudaGetSymbolAddress(&p, g_q2h);   __half* q2h = (__half*)p;
    cudaGetSymbolAddress(&p, g_ndh);   __half* ndh = (__half*)p;
    cudaGetSymbolAddress(&p, g_tmph);  __half* tmph = (__half*)p;
    cudaGetSymbolAddress(&p, g_vv);    float* vvb = (float*)p;
    cudaGetSymbolAddress(&p, g_nodes); float* nodesb = (float*)p;
    cudaGetSymbolAddress(&p, g_tmp);   float* tmp = (float*)p;
    cudaGetSymbolAddress(&p, g_S);     float* S = (float*)p;
    cudaGetSymbolAddress(&p, g_e);     float* e = (float*)p;
    cudaGetSymbolAddress(&p, g_qh);    __half* qh = (__half*)p;
    cudaGetSymbolAddress(&p, g_k2h);   __half* k2h = (__half*)p;
    cudaGetSymbolAddress(&p, g_e2cat); float* e2cat = (float*)p;
    cudaGetSymbolAddress(&p, g_h1);    float* h1 = (float*)p;
    cudaGetSymbolAddress(&p, g_e2);    float* e2 = (float*)p;
    cudaGetSymbolAddress(&p, g_edg);   float* edg = (float*)p;
    cudaGetSymbolAddress(&p, g_Wkvqh); __half* Wkvqh = (__half*)p;
    cudaGetSymbolAddress(&p, g_Wc0h);  __half* Wc0h = (__half*)p;
    cudaGetSymbolAddress(&p, g_Wc1h);  __half* Wc1h = (__half*)p;
    cudaGetSymbolAddress(&p, g_Wth);   __half* Wth = (__half*)p;
    cudaGetSymbolAddress(&p, g_bkvq);  float* bkvq = (float*)p;
    cudaGetSymbolAddress(&p, g_WqTf);  float* WqTf = (float*)p;
    cudaGetSymbolAddress(&p, g_WkTf);  float* WkTf = (float*)p;
    cudaGetSymbolAddress(&p, g_Wm1T);  float* Wm1T = (float*)p;
    cudaGetSymbolAddress(&p, g_Wm2T);  float* Wm2T = (float*)p;
    cudaGetSymbolAddress(&p, g_cwT);   float* cwT = (float*)p;

    cudaFuncSetAttribute(mma_gemm<0>, cudaFuncAttributeMaxDynamicSharedMemorySize, MMA_SMEM_BYTES);
    cudaFuncSetAttribute(mma_gemm<1>, cudaFuncAttributeMaxDynamicSharedMemorySize, MMA_SMEM_BYTES);
    cudaFuncSetAttribute(mma_gemm<2>, cudaFuncAttributeMaxDynamicSharedMemorySize, MMA_SMEM_BYTES);
    cudaFuncSetAttribute(mma_gemm<3>, cudaFuncAttributeMaxDynamicSharedMemorySize, MMA_SMEM_BYTES);
    cudaFuncSetAttribute(mma_gemm<4>, cudaFuncAttributeMaxDynamicSharedMemorySize, MMA_SMEM_BYTES);

    dim3 tb(32, 8);
    // half weights for big GEMMs
    transpose_k<__half><<<dim3(8, 8), tb>>>(Wk, Wkvqh, D, D);
    transpose_k<__half><<<dim3(8, 8), tb>>>(Wv, Wkvqh + D * D, D, D);
    transpose_k<__half><<<dim3(8, 8), tb>>>(Wq, Wkvqh + 2 * D * D, D, D);
    transpose_k<__half><<<dim3(8, 8), tb>>>(Wc0, Wc0h, D, D);
    transpose_k<__half><<<dim3(8, 8), tb>>>(Wc1, Wc1h, D, D);
    transpose_k<__half><<<dim3(8, 8), tb>>>(Wt, Wth, D, D);
    // fp32 weights for small GEMMs
    transpose_k<float><<<dim3(8, 8), tb>>>(Wq, WqTf, D, D);
    transpose_k<float><<<dim3(8, 8), tb>>>(Wk, WkTf, D, D);
    transpose_k<float><<<dim3(8, 16), tb>>>(Wm1, Wm1T, 2 * D, HID);
    transpose_k<float><<<dim3(8, 8), tb>>>(Wm2, Wm2T, HID, D);
    transpose_k<float><<<dim3(8, 8), tb>>>(cw, cwT, D, D);
    concat3<<<1, D>>>(bk, bv, bq, bkvq);

    copy_half<<<(N_NODES * D / 2 + 255) / 256, 256>>>(
        (const float2*)x, (__half2*)xrh, N_NODES * D / 2);

    ln_rows<<<N_NODES / 8, 256>>>(x, lnw, lnb, xh, N_NODES);
    edges_ln<<<NS / 8, 256>>>(enoise, emu, elog, lew, leb, e);

    // fused: kk(half,relu), vv(fp32,relu), q2(half)
    mma_gemm<4><<<dim3(6, 512), 256, MMA_SMEM_BYTES>>>(
        xh, Wkvqh, nullptr, bkvq, nullptr, vvb, kkh, q2h, N_NODES, 3 * D, D, 1.f);

    // q = relu(e@Wq+bq) -> half
    gemm_small<true, true, true><<<dim3(4, 8), 256>>>(e, WqTf, nullptr, qh, bq, NS, D, D);

    // dots1 = q @ kk^T * SCALE -> S [NS, N]
    mma_gemm<0><<<dim3(512, 4), 256, MMA_SMEM_BYTES>>>(
        qh, kkh, S, nullptr, nullptr, nullptr, nullptr, nullptr, NS, N_NODES, D, SCALE_C);

    slot_attend<<<NS, 256>>>(S, vvb, e, e2cat);

    // slot MLP (fp32)
    gemm_small<true, true, false><<<dim3(4, 8), 256>>>(e2cat, Wm1T, h1, nullptr, bm1, NS, HID, 2 * D);
    gemm_small<true, false, false><<<dim3(4, 8), 256>>>(h1, Wm2T, e2, nullptr, bm2, NS, D, HID);

    // k2 = relu(e2@Wk+bk) -> half; edg = e2@conv_w+conv_b (fp32)
    gemm_small<true, true, true><<<dim3(4, 8), 256>>>(e2, WkTf, nullptr, k2h, bk, NS, D, D);
    gemm_small<true, false, false><<<dim3(4, 8), 256>>>(e2, cwT, edg, nullptr, cb, NS, D, D);

    // dots2 = q2 @ k2^T * SCALE -> S [N, NS]
    mma_gemm<0><<<dim3(4, 512), 256, MMA_SMEM_BYTES>>>(
        q2h, k2h, S, nullptr, nullptr, nullptr, nullptr, nullptr, N_NODES, NS, D, SCALE_C);

    node_attend<<<N_NODES / 8, 256>>>(S, edg, nodesb, ndh);

    // tmp = x@Wc0 + bc0 (fp32)
    mma_gemm<1><<<dim3(2, 512), 256, MMA_SMEM_BYTES>>>(
        xrh, Wc0h, tmp, bc0, nullptr, nullptr, nullptr, nullptr, N_NODES, D, D, 1.f);
    // tmph = relu(tmp + nodes@Wc1 + bc1 + nodes) -> half
    mma_gemm<3><<<dim3(2, 512), 256, MMA_SMEM_BYTES>>>(
        ndh, Wc1h, tmp, bc1, nodesb, nullptr, tmph, nullptr, N_NODES, D, D, 1.f);
    // out = relu(tmph@Wt + bt) (fp32 final)
    mma_gemm<2><<<dim3(2, 512), 256, MMA_SMEM_BYTES>>>(
        tmph, Wth, out, bt, nullptr, nullptr, nullptr, nullptr, N_NODES, D, D, 1.f);
}

// round 8
// speedup vs baseline: 4.1761x; 1.3493x over previous
#include <cuda_runtime.h>
#include <cuda_fp16.h>
#include <math.h>
#include <stdint.h>

#define N_NODES 65536
#define D       256
#define NS      512
#define HID     256
#define KTOP    10
#define EPSC    1e-8f
#define SCALE_C 0.0625f  /* 256^-0.5 */

// ---------------------------------------------------------------------------
// Scratch
// ---------------------------------------------------------------------------
__device__ __half g_xh  [(size_t)N_NODES * D];   // LN(x), half
__device__ __half g_xrh [(size_t)N_NODES * D];   // x rounded to half
__device__ __half g_kkh [(size_t)N_NODES * D];
__device__ __half g_q2h [(size_t)N_NODES * D];
__device__ __half g_ndh [(size_t)N_NODES * D];   // nodes half
__device__ __half g_tmph[(size_t)N_NODES * D];
__device__ float  g_vv  [(size_t)N_NODES * D];   // exact
__device__ float  g_nodes[(size_t)N_NODES * D];  // exact
__device__ float  g_tmp [(size_t)N_NODES * D];   // exact addend
__device__ float  g_S   [(size_t)N_NODES * NS];  // dots1 only now

__device__ float  g_e    [NS * D];
__device__ __half g_qh   [NS * D];
__device__ __half g_k2h  [NS * D];
__device__ float  g_e2cat[NS * 2 * D];
__device__ float  g_h1   [NS * HID];
__device__ float  g_e2   [NS * D];
__device__ float  g_edg  [NS * D];

__device__ __half g_Wkvqh[3 * D * D];
__device__ __half g_Wc0h [D * D];
__device__ __half g_Wc1h [D * D];
__device__ __half g_Wth  [D * D];
__device__ float  g_bkvq [3 * D];
__device__ float  g_WqTf [D * D];
__device__ float  g_WkTf [D * D];
__device__ float  g_Wm1T [HID * 2 * D];
__device__ float  g_Wm2T [D * HID];
__device__ float  g_cwT  [D * D];

// ---------------------------------------------------------------------------
// helpers
// ---------------------------------------------------------------------------
__device__ __forceinline__ void mma16n8k16(float& c0, float& c1, float& c2, float& c3,
                                           uint32_t a0, uint32_t a1, uint32_t a2, uint32_t a3,
                                           uint32_t b0, uint32_t b1) {
    asm volatile(
        "mma.sync.aligned.m16n8k16.row.col.f32.f16.f16.f32 "
        "{%0,%1,%2,%3}, {%4,%5,%6,%7}, {%8,%9}, {%0,%1,%2,%3};"
        : "+f"(c0), "+f"(c1), "+f"(c2), "+f"(c3)
        : "r"(a0), "r"(a1), "r"(a2), "r"(a3), "r"(b0), "r"(b1));
}
__device__ __forceinline__ void ldsm_x4(uint32_t& r0, uint32_t& r1, uint32_t& r2, uint32_t& r3,
                                        uint32_t addr) {
    asm volatile("ldmatrix.sync.aligned.m8n8.x4.shared.b16 {%0,%1,%2,%3}, [%4];"
                 : "=r"(r0), "=r"(r1), "=r"(r2), "=r"(r3) : "r"(addr));
}
__device__ __forceinline__ void cp_async16(void* smem_dst, const void* gmem_src) {
    uint32_t d = (uint32_t)__cvta_generic_to_shared(smem_dst);
    asm volatile("cp.async.cg.shared.global [%0], [%1], 16;" :: "r"(d), "l"(gmem_src));
}
__device__ __forceinline__ void cp_commit() { asm volatile("cp.async.commit_group;"); }
__device__ __forceinline__ void cp_wait1()  { asm volatile("cp.async.wait_group 1;"); }

#define LDH   40                         // halves per SMEM row (80 B)
#define HBUF  (128 * LDH)                // halves per tile buffer
#define MMA_SMEM_BYTES (4 * HBUF * 2)    // 40960 B

// ---------------------------------------------------------------------------
// Pipelined fp16 NT GEMM (fp32 accumulate)
// EPI: 0 = C=acc*scale (fp32), 1 = C=acc+bias, 2 = C=relu(acc+bias),
//      3 = Ch=relu(acc+bias+C+aux) (half out), 4 = kvq split
// ---------------------------------------------------------------------------
template <int EPI>
__global__ void __launch_bounds__(256) mma_gemm(
    const __half* __restrict__ A, const __half* __restrict__ B,
    float* __restrict__ C, const float* __restrict__ bias,
    const float* __restrict__ aux, float* __restrict__ Cf2,
    __half* __restrict__ Ch, __half* __restrict__ Ch2,
    int M, int Ntot, int K, float scale) {
    extern __shared__ __half smh[];
    const int tid = threadIdx.x;
    const int wid = tid >> 5, lane = tid & 31;
    const int warp_m = wid & 3;
    const int warp_n = wid >> 2;
    const int bm = blockIdx.y * 128;
    const int bn = blockIdx.x * 128;
    const int grp = lane >> 2;
    const int tig = lane & 3;

    const uint32_t smb = (uint32_t)__cvta_generic_to_shared(smh);

    uint32_t a_off[2];
#pragma unroll
    for (int mt = 0; mt < 2; mt++)
        a_off[mt] = ((warp_m * 32 + mt * 16 + (lane & 15)) * LDH + (lane >> 4) * 8) * 2;
    const int b_row = (lane & 7) + ((lane >> 4) & 1) * 8;
    const int b_koff = ((lane >> 3) & 1) * 8;
    uint32_t b_off[4];
#pragma unroll
    for (int p = 0; p < 4; p++)
        b_off[p] = ((warp_n * 64 + p * 16 + b_row) * LDH + b_koff) * 2;

    float acc[2][8][4];
#pragma unroll
    for (int i = 0; i < 2; i++)
#pragma unroll
        for (int j = 0; j < 8; j++)
#pragma unroll
            for (int r = 0; r < 4; r++) acc[i][j][r] = 0.f;

    const int NCH = K >> 5;

    auto load_tile = [&](int ch, int buf) {
        const __half* Ag = A + (size_t)bm * K + ch * 32;
        const __half* Bg = B + (size_t)bn * K + ch * 32;
        __half* Ad = smh + buf * HBUF;
        __half* Bd = smh + (2 + buf) * HBUF;
#pragma unroll
        for (int i = 0; i < 2; i++) {
            int id = tid + (i << 8);
            int row = id >> 2, c8 = (id & 3) << 3;
            cp_async16(Ad + row * LDH + c8, Ag + (size_t)row * K + c8);
            cp_async16(Bd + row * LDH + c8, Bg + (size_t)row * K + c8);
        }
    };

    load_tile(0, 0);
    cp_commit();

    for (int ch = 0; ch < NCH; ch++) {
        if (ch + 1 < NCH) load_tile(ch + 1, (ch + 1) & 1);
        cp_commit();
        cp_wait1();
        __syncthreads();
        const uint32_t Ab = smb + (ch & 1) * HBUF * 2;
        const uint32_t Bb = smb + (2 + (ch & 1)) * HBUF * 2;
#pragma unroll
        for (int ks = 0; ks < 32; ks += 16) {
            uint32_t ra[2][4], rb[4][4];
#pragma unroll
            for (int mt = 0; mt < 2; mt++)
                ldsm_x4(ra[mt][0], ra[mt][1], ra[mt][2], ra[mt][3], Ab + a_off[mt] + ks * 2);
#pragma unroll
            for (int p = 0; p < 4; p++)
                ldsm_x4(rb[p][0], rb[p][1], rb[p][2], rb[p][3], Bb + b_off[p] + ks * 2);
#pragma unroll
            for (int p = 0; p < 4; p++)
#pragma unroll
                for (int mt = 0; mt < 2; mt++) {
                    mma16n8k16(acc[mt][2 * p][0], acc[mt][2 * p][1],
                               acc[mt][2 * p][2], acc[mt][2 * p][3],
                               ra[mt][0], ra[mt][1], ra[mt][2], ra[mt][3],
                               rb[p][0], rb[p][1]);
                    mma16n8k16(acc[mt][2 * p + 1][0], acc[mt][2 * p + 1][1],
                               acc[mt][2 * p + 1][2], acc[mt][2 * p + 1][3],
                               ra[mt][0], ra[mt][1], ra[mt][2], ra[mt][3],
                               rb[p][2], rb[p][3]);
                }
        }
        __syncthreads();
    }

#pragma unroll
    for (int mt = 0; mt < 2; mt++) {
        int r0 = bm + warp_m * 32 + mt * 16 + grp;
#pragma unroll
        for (int nt = 0; nt < 8; nt++) {
            int c0 = bn + warp_n * 64 + nt * 8 + 2 * tig;
#pragma unroll
            for (int half_ = 0; half_ < 2; half_++) {
                int rr = r0 + half_ * 8;
                float vx = acc[mt][nt][2 * half_ + 0];
                float vy = acc[mt][nt][2 * half_ + 1];
                if constexpr (EPI == 0) {
                    size_t idx = (size_t)rr * Ntot + c0;
                    float2 o; o.x = vx * scale; o.y = vy * scale;
                    *reinterpret_cast<float2*>(C + idx) = o;
                } else if constexpr (EPI == 4) {
                    vx += bias[c0]; vy += bias[c0 + 1];
                    int seg = c0 >> 8;
                    size_t idx = (size_t)rr * D + (c0 & 255);
                    if (seg == 0) {
                        vx = fmaxf(vx, 0.f); vy = fmaxf(vy, 0.f);
                        *reinterpret_cast<__half2*>(Ch + idx) = __floats2half2_rn(vx, vy);
                    } else if (seg == 1) {
                        vx = fmaxf(vx, 0.f); vy = fmaxf(vy, 0.f);
                        float2 o; o.x = vx; o.y = vy;
                        *reinterpret_cast<float2*>(Cf2 + idx) = o;
                    } else {
                        *reinterpret_cast<__half2*>(Ch2 + idx) = __floats2half2_rn(vx, vy);
                    }
                } else if constexpr (EPI == 3) {
                    size_t idx = (size_t)rr * Ntot + c0;
                    float2 cc = *reinterpret_cast<const float2*>(C + idx);
                    float2 aa = *reinterpret_cast<const float2*>(aux + idx);
                    vx += bias[c0] + cc.x + aa.x;
                    vy += bias[c0 + 1] + cc.y + aa.y;
                    vx = fmaxf(vx, 0.f); vy = fmaxf(vy, 0.f);
                    *reinterpret_cast<__half2*>(Ch + idx) = __floats2half2_rn(vx, vy);
                } else {
                    vx += bias[c0]; vy += bias[c0 + 1];
                    if constexpr (EPI == 2) { vx = fmaxf(vx, 0.f); vy = fmaxf(vy, 0.f); }
                    size_t idx = (size_t)rr * Ntot + c0;
                    float2 o; o.x = vx; o.y = vy;
                    *reinterpret_cast<float2*>(C + idx) = o;
                }
            }
        }
    }
}

// ---------------------------------------------------------------------------
// FUSED dots2 + node attention.
// Grid 512 CTAs x 256 thr. CTA owns 128 nodes (rows of q2h). Loops 4 slot-
// chunks of 128 (k2h rows). Per chunk: fp16 mma -> logits[128][133] SMEM ->
// per-thread online (max, sumexp, top-10) -> final gather from edg.
// SMEM: logits 68096B (tile buffers overlay) + weights 5120 + idx 5120.
// ---------------------------------------------------------------------------
#define LGD 133
#define FUS_SMEM_BYTES (128 * LGD * 4 + 128 * KTOP * 4 + 128 * KTOP * 4)

__global__ void __launch_bounds__(256) dots2_node_fused(
    const __half* __restrict__ A,     // q2h [N,256]
    const __half* __restrict__ Bk,    // k2h [512,256]
    const float* __restrict__ edg,
    float* __restrict__ nodes, __half* __restrict__ nodesh) {
    extern __shared__ __half smh[];
    float* logits = reinterpret_cast<float*>(smh);
    float* wv_s = logits + 128 * LGD;
    int*   wi_s = reinterpret_cast<int*>(wv_s + 128 * KTOP);

    const int tid = threadIdx.x;
    const int wid = tid >> 5, lane = tid & 31;
    const int warp_m = wid & 3;
    const int warp_n = wid >> 2;
    const int bm = blockIdx.x * 128;
    const int grp = lane >> 2;
    const int tig = lane & 3;
    const int K = D;

    const uint32_t smb = (uint32_t)__cvta_generic_to_shared(smh);
    uint32_t a_off[2];
#pragma unroll
    for (int mt = 0; mt < 2; mt++)
        a_off[mt] = ((warp_m * 32 + mt * 16 + (lane & 15)) * LDH + (lane >> 4) * 8) * 2;
    const int b_row = (lane & 7) + ((lane >> 4) & 1) * 8;
    const int b_koff = ((lane >> 3) & 1) * 8;
    uint32_t b_off[4];
#pragma unroll
    for (int p = 0; p < 4; p++)
        b_off[p] = ((warp_n * 64 + p * 16 + b_row) * LDH + b_koff) * 2;

    // per-thread online state (thread t<128 owns node row t)
    float m_run = -INFINITY, z_run = 0.f;
    float tv[KTOP]; int ti[KTOP];
#pragma unroll
    for (int i = 0; i < KTOP; i++) { tv[i] = -INFINITY; ti[i] = 0; }

    for (int sc = 0; sc < 4; sc++) {
        float acc[2][8][4];
#pragma unroll
        for (int i = 0; i < 2; i++)
#pragma unroll
            for (int j = 0; j < 8; j++)
#pragma unroll
                for (int r = 0; r < 4; r++) acc[i][j][r] = 0.f;

        const __half* Bg_base = Bk + (size_t)(sc * 128) * K;
        auto load_tile = [&](int ch, int buf) {
            const __half* Ag = A + (size_t)bm * K + ch * 32;
            const __half* Bg = Bg_base + ch * 32;
            __half* Ad = smh + buf * HBUF;
            __half* Bd = smh + (2 + buf) * HBUF;
#pragma unroll
            for (int i = 0; i < 2; i++) {
                int id = tid + (i << 8);
                int row = id >> 2, c8 = (id & 3) << 3;
                cp_async16(Ad + row * LDH + c8, Ag + (size_t)row * K + c8);
                cp_async16(Bd + row * LDH + c8, Bg + (size_t)row * K + c8);
            }
        };

        load_tile(0, 0);
        cp_commit();
        for (int ch = 0; ch < 8; ch++) {
            if (ch + 1 < 8) load_tile(ch + 1, (ch + 1) & 1);
            cp_commit();
            cp_wait1();
            __syncthreads();
            const uint32_t Ab = smb + (ch & 1) * HBUF * 2;
            const uint32_t Bb = smb + (2 + (ch & 1)) * HBUF * 2;
#pragma unroll
            for (int ks = 0; ks < 32; ks += 16) {
                uint32_t ra[2][4], rb[4][4];
#pragma unroll
                for (int mt = 0; mt < 2; mt++)
                    ldsm_x4(ra[mt][0], ra[mt][1], ra[mt][2], ra[mt][3], Ab + a_off[mt] + ks * 2);
#pragma unroll
                for (int p = 0; p < 4; p++)
                    ldsm_x4(rb[p][0], rb[p][1], rb[p][2], rb[p][3], Bb + b_off[p] + ks * 2);
#pragma unroll
                for (int p = 0; p < 4; p++)
#pragma unroll
                    for (int mt = 0; mt < 2; mt++) {
                        mma16n8k16(acc[mt][2 * p][0], acc[mt][2 * p][1],
                                   acc[mt][2 * p][2], acc[mt][2 * p][3],
                                   ra[mt][0], ra[mt][1], ra[mt][2], ra[mt][3],
                                   rb[p][0], rb[p][1]);
                        mma16n8k16(acc[mt][2 * p + 1][0], acc[mt][2 * p + 1][1],
                                   acc[mt][2 * p + 1][2], acc[mt][2 * p + 1][3],
                                   ra[mt][0], ra[mt][1], ra[mt][2], ra[mt][3],
                                   rb[p][2], rb[p][3]);
                    }
            }
            __syncthreads();
        }
        // store scaled logits to SMEM (overwrites tile buffers; all ldsm done)
#pragma unroll
        for (int mt = 0; mt < 2; mt++) {
            int r0 = warp_m * 32 + mt * 16 + grp;
#pragma unroll
            for (int nt = 0; nt < 8; nt++) {
                int c0 = warp_n * 64 + nt * 8 + 2 * tig;
#pragma unroll
                for (int half_ = 0; half_ < 2; half_++) {
                    int rr = r0 + half_ * 8;
                    logits[rr * LGD + c0]     = acc[mt][nt][2 * half_ + 0] * SCALE_C;
                    logits[rr * LGD + c0 + 1] = acc[mt][nt][2 * half_ + 1] * SCALE_C;
                }
            }
        }
        __syncthreads();
        // online update (thread t<128 owns row t)
        if (tid < 128) {
            const float* lr = logits + tid * LGD;
            for (int j = 0; j < 128; j++) {
                float v = lr[j];
                if (v > m_run) { z_run *= __expf(m_run - v); m_run = v; }
                z_run += __expf(v - m_run);
                if (v > tv[KTOP - 1]) {
                    int ix = sc * 128 + j;
                    float vt = v;
#pragma unroll
                    for (int p = 0; p < KTOP; p++)
                        if (vt > tv[p]) {
                            float tf = tv[p]; tv[p] = vt; vt = tf;
                            int tt = ti[p]; ti[p] = ix; ix = tt;
                        }
                }
            }
        }
        __syncthreads();
    }
    // finalize weights
    if (tid < 128) {
        float zin = 1.f / z_run;
#pragma unroll
        for (int i = 0; i < KTOP; i++) {
            wv_s[tid * KTOP + i] = __expf(tv[i] - m_run) * zin;
            wi_s[tid * KTOP + i] = ti[i];
        }
    }
    __syncthreads();
    // cooperative gather: warp wid handles rows wid*16..+16
    for (int rr = 0; rr < 16; rr++) {
        int r = wid * 16 + rr;
        float w_[KTOP]; int ix_[KTOP];
#pragma unroll
        for (int i = 0; i < KTOP; i++) { w_[i] = wv_s[r * KTOP + i]; ix_[i] = wi_s[r * KTOP + i]; }
        float* po = nodes + (size_t)(bm + r) * D;
        __half* ph = nodesh + (size_t)(bm + r) * D;
#pragma unroll
        for (int j = 0; j < 8; j++) {
            int c = lane + 32 * j;
            float a2 = 0.f;
#pragma unroll
            for (int i = 0; i < KTOP; i++) a2 += w_[i] * edg[(size_t)ix_[i] * D + c];
            po[c] = a2;
            ph[c] = __float2half_rn(a2);
        }
    }
}

// ---------------------------------------------------------------------------
// One prep kernel: 12 weight-transpose tasks + bias concat + edges LN.
// grid (64, 14), block (32,8)
// ---------------------------------------------------------------------------
__device__ __forceinline__ void tr_tile(const float* in, float* outF, __half* outH,
                                        int R, int C, int bx, float (*tile)[33]) {
    int tx = threadIdx.x, tyw = threadIdx.y;
    int xt = bx & (C / 32 - 1), yt = bx / (C / 32);
    int bxc = xt * 32, byr = yt * 32;
    for (int y = tyw; y < 32; y += 8)
        tile[y][tx] = in[(size_t)(byr + y) * C + bxc + tx];
    __syncthreads();
    if (outH) {
        for (int y = tyw; y < 32; y += 8)
            outH[(size_t)(bxc + y) * R + byr + tx] = __float2half_rn(tile[tx][y]);
    } else {
        for (int y = tyw; y < 32; y += 8)
            outF[(size_t)(bxc + y) * R + byr + tx] = tile[tx][y];
    }
}

__global__ void prep(
    const float* Wk, const float* Wv, const float* Wq, const float* Wc0,
    const float* Wc1, const float* Wt, const float* cw, const float* Wm1,
    const float* Wm2,
    __half* Wkvqh, __half* Wc0h, __half* Wc1h, __half* Wth,
    float* WqTf, float* WkTf, float* cwT, float* Wm1T, float* Wm2T,
    const float* bk, const float* bv, const float* bq, float* bkvq,
    const float* noise, const float* emu, const float* elog,
    const float* lew, const float* leb, float* e) {
    __shared__ float tile[32][33];
    int task = blockIdx.y, bx = blockIdx.x;
    switch (task) {
    case 0: tr_tile(Wk,  nullptr, Wkvqh,             D, D, bx, tile); break;
    case 1: tr_tile(Wv,  nullptr, Wkvqh + D * D,     D, D, bx, tile); break;
    case 2: tr_tile(Wq,  nullptr, Wkvqh + 2 * D * D, D, D, bx, tile); break;
    case 3: tr_tile(Wc0, nullptr, Wc0h, D, D, bx, tile); break;
    case 4: tr_tile(Wc1, nullptr, Wc1h, D, D, bx, tile); break;
    case 5: tr_tile(Wt,  nullptr, Wth,  D, D, bx, tile); break;
    case 6: tr_tile(Wq,  WqTf, nullptr, D, D, bx, tile); break;
    case 7: tr_tile(Wk,  WkTf, nullptr, D, D, bx, tile); break;
    case 8: tr_tile(cw,  cwT,  nullptr, D, D, bx, tile); break;
    case 9: tr_tile(Wm2, Wm2T, nullptr, HID, D, bx, tile); break;
    case 10: tr_tile(Wm1, Wm1T, nullptr, 2 * D, HID, bx, tile); break;
    case 11: tr_tile(Wm1, Wm1T, nullptr, 2 * D, HID, bx + 64, tile); break;
    case 12: {
        if (bx == 0) {
            int i = threadIdx.y * 32 + threadIdx.x;
            bkvq[i] = bk[i]; bkvq[D + i] = bv[i]; bkvq[2 * D + i] = bq[i];
        }
        break;
    }
    default: {  // 13: edges LN
        int warp = bx * 8 + threadIdx.y;
        int lane = threadIdx.x;
        const float* r = noise + (size_t)warp * D;
        float v[8]; float s = 0.f;
#pragma unroll
        for (int j = 0; j < 8; j++) {
            int c = lane + 32 * j;
            v[j] = emu[c] + expf(elog[c]) * r[c];
            s += v[j];
        }
#pragma unroll
        for (int st = 16; st; st >>= 1) s += __shfl_xor_sync(0xffffffffu, s, st);
        float mu = s * (1.f / 256.f);
        float q = 0.f;
#pragma unroll
        for (int j = 0; j < 8; j++) { float d2 = v[j] - mu; q += d2 * d2; }
#pragma unroll
        for (int st = 16; st; st >>= 1) q += __shfl_xor_sync(0xffffffffu, q, st);
        float rinv = rsqrtf(q * (1.f / 256.f) + 1e-5f);
        float* po = e + (size_t)warp * D;
#pragma unroll
        for (int j = 0; j < 8; j++) {
            int c = lane + 32 * j;
            po[c] = (v[j] - mu) * rinv * lew[c] + leb[c];
        }
        break;
    }
    }
}

// ---------------------------------------------------------------------------
// LayerNorm -> half, also writes x rounded to half
// ---------------------------------------------------------------------------
__global__ void ln_rows(const float* __restrict__ x, const float* __restrict__ w,
                        const float* __restrict__ b, __half* __restrict__ o,
                        __half* __restrict__ xrh, int M) {
    int warp = (blockIdx.x * blockDim.x + threadIdx.x) >> 5;
    int lane = threadIdx.x & 31;
    if (warp >= M) return;
    const float* r = x + (size_t)warp * D;
    float v[8]; float s = 0.f;
#pragma unroll
    for (int j = 0; j < 8; j++) { v[j] = r[lane + 32 * j]; s += v[j]; }
#pragma unroll
    for (int st = 16; st; st >>= 1) s += __shfl_xor_sync(0xffffffffu, s, st);
    float mu = s * (1.f / 256.f);
    float q = 0.f;
#pragma unroll
    for (int j = 0; j < 8; j++) { float d = v[j] - mu; q += d * d; }
#pragma unroll
    for (int st = 16; st; st >>= 1) q += __shfl_xor_sync(0xffffffffu, q, st);
    float rinv = rsqrtf(q * (1.f / 256.f) + 1e-5f);
    __half* po = o + (size_t)warp * D;
    __half* px = xrh + (size_t)warp * D;
#pragma unroll
    for (int j = 0; j < 8; j++) {
        int c = lane + 32 * j;
        po[c] = __float2half_rn((v[j] - mu) * rinv * w[c] + b[c]);
        px[c] = __float2half_rn(v[j]);
    }
}

// ---------------------------------------------------------------------------
// Small fp32 NT GEMM, register-prefetch double buffered
// ---------------------------------------------------------------------------
template <bool BIAS, bool RELU, bool OUTH>
__global__ void gemm_small(const float* __restrict__ A, const float* __restrict__ B,
                           float* __restrict__ C, __half* __restrict__ Ch,
                           const float* __restrict__ bias, int M, int N, int K) {
    constexpr int BM = 64, BN = 64, BK = 16, TM = 4, TN = 4;
    __shared__ float As[BK][BM + 4];
    __shared__ float Bs[BK][BN + 4];
    const int bm = blockIdx.y * BM;
    const int bn = blockIdx.x * BN;
    const int tid = threadIdx.x;
    const int tx = tid % (BN / TN);
    const int ty = tid / (BN / TN);
    const int row = tid >> 2;
    const int kc = (tid & 3) << 2;
    float acc[TM][TN];
#pragma unroll
    for (int i = 0; i < TM; i++)
#pragma unroll
        for (int j = 0; j < TN; j++) acc[i][j] = 0.f;

    float4 ra = *reinterpret_cast<const float4*>(&A[(size_t)(bm + row) * K + kc]);
    float4 rb = *reinterpret_cast<const float4*>(&B[(size_t)(bn + row) * K + kc]);

    for (int k0 = 0; k0 < K; k0 += BK) {
        As[kc + 0][row] = ra.x; As[kc + 1][row] = ra.y;
        As[kc + 2][row] = ra.z; As[kc + 3][row] = ra.w;
        Bs[kc + 0][row] = rb.x; Bs[kc + 1][row] = rb.y;
        Bs[kc + 2][row] = rb.z; Bs[kc + 3][row] = rb.w;
        __syncthreads();
        if (k0 + BK < K) {
            ra = *reinterpret_cast<const float4*>(&A[(size_t)(bm + row) * K + k0 + BK + kc]);
            rb = *reinterpret_cast<const float4*>(&B[(size_t)(bn + row) * K + k0 + BK + kc]);
        }
#pragma unroll
        for (int kk = 0; kk < BK; kk++) {
            float af[TM], bf[TN];
#pragma unroll
            for (int i = 0; i < TM; i++) af[i] = As[kk][ty * TM + i];
#pragma unroll
            for (int j = 0; j < TN; j++) bf[j] = Bs[kk][tx * TN + j];
#pragma unroll
            for (int i = 0; i < TM; i++)
#pragma unroll
                for (int j = 0; j < TN; j++) acc[i][j] += af[i] * bf[j];
        }
        __syncthreads();
    }
#pragma unroll
    for (int i = 0; i < TM; i++) {
        int m = bm + ty * TM + i;
#pragma unroll
        for (int j = 0; j < TN; j++) {
            int n = bn + tx * TN + j;
            float v = acc[i][j];
            if (BIAS) v += bias[n];
            if (RELU) v = fmaxf(v, 0.f);
            if (OUTH) Ch[(size_t)m * N + n] = __float2half_rn(v);
            else      C [(size_t)m * N + n] = v;
        }
    }
}

// ---------------------------------------------------------------------------
// Slot attention (single pass, exact fp32)
// ---------------------------------------------------------------------------
__global__ void slot_attend(const float* __restrict__ S1, const float* __restrict__ vv,
                            const float* __restrict__ e, float* __restrict__ e2cat) {
    __shared__ float sv[256 * KTOP];
    __shared__ int   si[256 * KTOP];
    __shared__ float sm_m[256];
    __shared__ float sm_z[256];
    __shared__ float sw[KTOP];
    __shared__ int   sx[KTOP];
    int s = blockIdx.x, tid = threadIdx.x;
    const float* row = S1 + (size_t)s * N_NODES;
    float tv[KTOP]; int ti[KTOP];
#pragma unroll
    for (int i = 0; i < KTOP; i++) { tv[i] = -INFINITY; ti[i] = 0; }
    float m_loc = -INFINITY, z = 0.f;
    for (int n = tid; n < N_NODES; n += 256) {
        float v = row[n];
        if (v > m_loc) { z *= __expf(m_loc - v); m_loc = v; }
        z += __expf(v - m_loc);
        if (v > tv[KTOP - 1]) {
            int ix = n;
            float vt = v;
#pragma unroll
            for (int p = 0; p < KTOP; p++)
                if (vt > tv[p]) {
                    float tf = tv[p]; tv[p] = vt; vt = tf;
                    int tt = ti[p]; ti[p] = ix; ix = tt;
                }
        }
    }
#pragma unroll
    for (int i = 0; i < KTOP; i++) { sv[tid * KTOP + i] = tv[i]; si[tid * KTOP + i] = ti[i]; }
    sm_m[tid] = m_loc; sm_z[tid] = z;
    __syncthreads();
    for (int stride = 128; stride >= 1; stride >>= 1) {
        if (tid < stride) {
#pragma unroll
            for (int i = 0; i < KTOP; i++) { tv[i] = sv[tid * KTOP + i]; ti[i] = si[tid * KTOP + i]; }
#pragma unroll
            for (int i = 0; i < KTOP; i++) {
                float v = sv[(tid + stride) * KTOP + i];
                int ix = si[(tid + stride) * KTOP + i];
                if (v > tv[KTOP - 1]) {
#pragma unroll
                    for (int p = 0; p < KTOP; p++)
                        if (v > tv[p]) {
                            float tf = tv[p]; tv[p] = v; v = tf;
                            int tt = ti[p]; ti[p] = ix; ix = tt;
                        }
                }
            }
#pragma unroll
            for (int i = 0; i < KTOP; i++) { sv[tid * KTOP + i] = tv[i]; si[tid * KTOP + i] = ti[i]; }
            float ma = sm_m[tid], za = sm_z[tid];
            float mb = sm_m[tid + stride], zb = sm_z[tid + stride];
            float mn = fmaxf(ma, mb);
            float zn = za * __expf(ma - mn) + zb * __expf(mb - mn);
            sm_m[tid] = mn; sm_z[tid] = zn;
        }
        __syncthreads();
    }
    float maxv = sm_m[0];
    float Z = sm_z[0];
    if (tid < KTOP) {
        float p = __expf(sv[tid] - maxv) / Z;
        sw[tid] = (p + EPSC) / (1.f + (float)N_NODES * EPSC);
        sx[tid] = si[tid];
    }
    __syncthreads();
    float acc = 0.f;
#pragma unroll
    for (int i = 0; i < KTOP; i++) acc += sw[i] * vv[(size_t)sx[i] * D + tid];
    e2cat[(size_t)s * 2 * D + D + tid] = acc;
    e2cat[(size_t)s * 2 * D + tid] = e[(size_t)s * D + tid];
}

// ---------------------------------------------------------------------------
// Launch
// ---------------------------------------------------------------------------
extern "C" void kernel_launch(void* const* d_in, const int* in_sizes, int n_in,
                              void* d_out, int out_size) {
    (void)in_sizes; (void)n_in; (void)out_size;
    const float* x      = (const float*)d_in[0];
    const float* enoise = (const float*)d_in[1];
    const float* emu    = (const float*)d_in[2];
    const float* elog   = (const float*)d_in[3];
    const float* lnw    = (const float*)d_in[4];
    const float* lnb    = (const float*)d_in[5];
    const float* lew    = (const float*)d_in[6];
    const float* leb    = (const float*)d_in[7];
    const float* Wq = (const float*)d_in[8];  const float* bq = (const float*)d_in[9];
    const float* Wk = (const float*)d_in[10]; const float* bk = (const float*)d_in[11];
    const float* Wv = (const float*)d_in[12]; const float* bv = (const float*)d_in[13];
    const float* Wm1 = (const float*)d_in[14]; const float* bm1 = (const float*)d_in[15];
    const float* Wm2 = (const float*)d_in[16]; const float* bm2 = (const float*)d_in[17];
    const float* cw = (const float*)d_in[18];  const float* cb = (const float*)d_in[19];
    const float* Wc0 = (const float*)d_in[20]; const float* bc0 = (const float*)d_in[21];
    const float* Wc1 = (const float*)d_in[22]; const float* bc1 = (const float*)d_in[23];
    const float* Wt = (const float*)d_in[24];  const float* bt = (const float*)d_in[25];
    float* out = (float*)d_out;

    void* p;
    cudaGetSymbolAddress(&p, g_xh);    __half* xh = (__half*)p;
    cudaGetSymbolAddress(&p, g_xrh);   __half* xrh = (__half*)p;
    cudaGetSymbolAddress(&p, g_kkh);   __half* kkh = (__half*)p;
    cudaGetSymbolAddress(&p, g_q2h);   __half* q2h = (__half*)p;
    cudaGetSymbolAddress(&p, g_ndh);   __half* ndh = (__half*)p;
    cudaGetSymbolAddress(&p, g_tmph);  __half* tmph = (__half*)p;
    cudaGetSymbolAddress(&p, g_vv);    float* vvb = (float*)p;
    cudaGetSymbolAddress(&p, g_nodes); float* nodesb = (float*)p;
    cudaGetSymbolAddress(&p, g_tmp);   float* tmp = (float*)p;
    cudaGetSymbolAddress(&p, g_S);     float* S = (float*)p;
    cudaGetSymbolAddress(&p, g_e);     float* e = (float*)p;
    cudaGetSymbolAddress(&p, g_qh);    __half* qh = (__half*)p;
    cudaGetSymbolAddress(&p, g_k2h);   __half* k2h = (__half*)p;
    cudaGetSymbolAddress(&p, g_e2cat); float* e2cat = (float*)p;
    cudaGetSymbolAddress(&p, g_h1);    float* h1 = (float*)p;
    cudaGetSymbolAddress(&p, g_e2);    float* e2 = (float*)p;
    cudaGetSymbolAddress(&p, g_edg);   float* edg = (float*)p;
    cudaGetSymbolAddress(&p, g_Wkvqh); __half* Wkvqh = (__half*)p;
    cudaGetSymbolAddress(&p, g_Wc0h);  __half* Wc0h = (__half*)p;
    cudaGetSymbolAddress(&p, g_Wc1h);  __half* Wc1h = (__half*)p;
    cudaGetSymbolAddress(&p, g_Wth);   __half* Wth = (__half*)p;
    cudaGetSymbolAddress(&p, g_bkvq);  float* bkvq = (float*)p;
    cudaGetSymbolAddress(&p, g_WqTf);  float* WqTf = (float*)p;
    cudaGetSymbolAddress(&p, g_WkTf);  float* WkTf = (float*)p;
    cudaGetSymbolAddress(&p, g_Wm1T);  float* Wm1T = (float*)p;
    cudaGetSymbolAddress(&p, g_Wm2T);  float* Wm2T = (float*)p;
    cudaGetSymbolAddress(&p, g_cwT);   float* cwT = (float*)p;

    cudaFuncSetAttribute(mma_gemm<0>, cudaFuncAttributeMaxDynamicSharedMemorySize, MMA_SMEM_BYTES);
    cudaFuncSetAttribute(mma_gemm<1>, cudaFuncAttributeMaxDynamicSharedMemorySize, MMA_SMEM_BYTES);
    cudaFuncSetAttribute(mma_gemm<2>, cudaFuncAttributeMaxDynamicSharedMemorySize, MMA_SMEM_BYTES);
    cudaFuncSetAttribute(mma_gemm<3>, cudaFuncAttributeMaxDynamicSharedMemorySize, MMA_SMEM_BYTES);
    cudaFuncSetAttribute(mma_gemm<4>, cudaFuncAttributeMaxDynamicSharedMemorySize, MMA_SMEM_BYTES);
    cudaFuncSetAttribute(dots2_node_fused, cudaFuncAttributeMaxDynamicSharedMemorySize, FUS_SMEM_BYTES);

    // prep: all weight transposes + bias concat + edges LN in one launch
    prep<<<dim3(64, 14), dim3(32, 8)>>>(
        Wk, Wv, Wq, Wc0, Wc1, Wt, cw, Wm1, Wm2,
        Wkvqh, Wc0h, Wc1h, Wth, WqTf, WkTf, cwT, Wm1T, Wm2T,
        bk, bv, bq, bkvq, enoise, emu, elog, lew, leb, e);

    ln_rows<<<N_NODES / 8, 256>>>(x, lnw, lnb, xh, xrh, N_NODES);

    // fused: kk(half,relu), vv(fp32,relu), q2(half)
    mma_gemm<4><<<dim3(6, 512), 256, MMA_SMEM_BYTES>>>(
        xh, Wkvqh, nullptr, bkvq, nullptr, vvb, kkh, q2h, N_NODES, 3 * D, D, 1.f);

    // q = relu(e@Wq+bq) -> half
    gemm_small<true, true, true><<<dim3(4, 8), 256>>>(e, WqTf, nullptr, qh, bq, NS, D, D);

    // dots1 = q @ kk^T * SCALE -> S [NS, N]
    mma_gemm<0><<<dim3(512, 4), 256, MMA_SMEM_BYTES>>>(
        qh, kkh, S, nullptr, nullptr, nullptr, nullptr, nullptr, NS, N_NODES, D, SCALE_C);

    slot_attend<<<NS, 256>>>(S, vvb, e, e2cat);

    // slot MLP (fp32)
    gemm_small<true, true, false><<<dim3(4, 8), 256>>>(e2cat, Wm1T, h1, nullptr, bm1, NS, HID, 2 * D);
    gemm_small<true, false, false><<<dim3(4, 8), 256>>>(h1, Wm2T, e2, nullptr, bm2, NS, D, HID);

    // k2 = relu(e2@Wk+bk) -> half; edg = e2@conv_w+conv_b (fp32)
    gemm_small<true, true, true><<<dim3(4, 8), 256>>>(e2, WkTf, nullptr, k2h, bk, NS, D, D);
    gemm_small<true, false, false><<<dim3(4, 8), 256>>>(e2, cwT, edg, nullptr, cb, NS, D, D);

    // FUSED dots2 + node attention (no S materialization)
    dots2_node_fused<<<512, 256, FUS_SMEM_BYTES>>>(q2h, k2h, edg, nodesb, ndh);

    // tmp = x@Wc0 + bc0 (fp32)
    mma_gemm<1><<<dim3(2, 512), 256, MMA_SMEM_BYTES>>>(
        xrh, Wc0h, tmp, bc0, nullptr, nullptr, nullptr, nullptr, N_NODES, D, D, 1.f);
    // tmph = relu(tmp + nodes@Wc1 + bc1 + nodes) -> half
    mma_gemm<3><<<dim3(2, 512), 256, MMA_SMEM_BYTES>>>(
        ndh, Wc1h, tmp, bc1, nodesb, nullptr, tmph, nullptr, N_NODES, D, D, 1.f);
    // out = relu(tmph@Wt + bt) (fp32 final)
    mma_gemm<2><<<dim3(2, 512), 256, MMA_SMEM_BYTES>>>(
        tmph, Wth, out, bt, nullptr, nullptr, nullptr, nullptr, N_NODES, D, D, 1.f);
}

// round 9
// speedup vs baseline: 4.3275x; 1.0363x over previous
#include <cuda_runtime.h>
#include <cuda_fp16.h>
#include <math.h>
#include <stdint.h>

#define N_NODES 65536
#define D       256
#define NS      512
#define HID     256
#define KTOP    10
#define EPSC    1e-8f
#define SCALE_C 0.0625f  /* 256^-0.5 */

// ---------------------------------------------------------------------------
// Scratch
// ---------------------------------------------------------------------------
__device__ __half g_xh  [(size_t)N_NODES * D];
__device__ __half g_xrh [(size_t)N_NODES * D];
__device__ __half g_kkh [(size_t)N_NODES * D];
__device__ __half g_q2h [(size_t)N_NODES * D];
__device__ __half g_ndh [(size_t)N_NODES * D];
__device__ __half g_tmph[(size_t)N_NODES * D];
__device__ float  g_vv  [(size_t)N_NODES * D];
__device__ float  g_nodes[(size_t)N_NODES * D];
__device__ float  g_tmp [(size_t)N_NODES * D];
__device__ float  g_part[(size_t)NS * 512 * 24];   // dots1 partials

__device__ float  g_e    [NS * D];
__device__ __half g_qh   [NS * D];
__device__ __half g_k2h  [NS * D];
__device__ float  g_e2cat[NS * 2 * D];
__device__ float  g_h1   [NS * HID];
__device__ float  g_e2   [NS * D];
__device__ float  g_edg  [NS * D];

__device__ __half g_Wkvqh[3 * D * D];
__device__ __half g_Wc0h [D * D];
__device__ __half g_Wc1h [D * D];
__device__ __half g_Wth  [D * D];
__device__ float  g_bkvq [3 * D];
__device__ float  g_WqTf [D * D];
__device__ float  g_WkTf [D * D];
__device__ float  g_Wm1T [HID * 2 * D];
__device__ float  g_Wm2T [D * HID];
__device__ float  g_cwT  [D * D];

// ---------------------------------------------------------------------------
// helpers
// ---------------------------------------------------------------------------
__device__ __forceinline__ void mma16n8k16(float& c0, float& c1, float& c2, float& c3,
                                           uint32_t a0, uint32_t a1, uint32_t a2, uint32_t a3,
                                           uint32_t b0, uint32_t b1) {
    asm volatile(
        "mma.sync.aligned.m16n8k16.row.col.f32.f16.f16.f32 "
        "{%0,%1,%2,%3}, {%4,%5,%6,%7}, {%8,%9}, {%0,%1,%2,%3};"
        : "+f"(c0), "+f"(c1), "+f"(c2), "+f"(c3)
        : "r"(a0), "r"(a1), "r"(a2), "r"(a3), "r"(b0), "r"(b1));
}
__device__ __forceinline__ void ldsm_x4(uint32_t& r0, uint32_t& r1, uint32_t& r2, uint32_t& r3,
                                        uint32_t addr) {
    asm volatile("ldmatrix.sync.aligned.m8n8.x4.shared.b16 {%0,%1,%2,%3}, [%4];"
                 : "=r"(r0), "=r"(r1), "=r"(r2), "=r"(r3) : "r"(addr));
}
__device__ __forceinline__ void cp_async16(void* smem_dst, const void* gmem_src) {
    uint32_t d = (uint32_t)__cvta_generic_to_shared(smem_dst);
    asm volatile("cp.async.cg.shared.global [%0], [%1], 16;" :: "r"(d), "l"(gmem_src));
}
__device__ __forceinline__ void cp_commit() { asm volatile("cp.async.commit_group;"); }
__device__ __forceinline__ void cp_wait1()  { asm volatile("cp.async.wait_group 1;"); }
__device__ __forceinline__ void cp_wait0()  { asm volatile("cp.async.wait_group 0;"); }

#define LDH   40
#define HBUF  (128 * LDH)
#define MMA_SMEM_BYTES (4 * HBUF * 2)

// ---------------------------------------------------------------------------
// Pipelined fp16 NT GEMM (fp32 accumulate)
// EPI: 1 = C=acc+bias, 2 = C=relu(acc+bias), 3 = Ch=relu(acc+bias+C+aux),
//      4 = kvq split
// ---------------------------------------------------------------------------
template <int EPI>
__global__ void __launch_bounds__(256) mma_gemm(
    const __half* __restrict__ A, const __half* __restrict__ B,
    float* __restrict__ C, const float* __restrict__ bias,
    const float* __restrict__ aux, float* __restrict__ Cf2,
    __half* __restrict__ Ch, __half* __restrict__ Ch2,
    int M, int Ntot, int K, float scale) {
    extern __shared__ __half smh[];
    const int tid = threadIdx.x;
    const int wid = tid >> 5, lane = tid & 31;
    const int warp_m = wid & 3;
    const int warp_n = wid >> 2;
    const int bm = blockIdx.y * 128;
    const int bn = blockIdx.x * 128;
    const int grp = lane >> 2;
    const int tig = lane & 3;

    const uint32_t smb = (uint32_t)__cvta_generic_to_shared(smh);
    uint32_t a_off[2];
#pragma unroll
    for (int mt = 0; mt < 2; mt++)
        a_off[mt] = ((warp_m * 32 + mt * 16 + (lane & 15)) * LDH + (lane >> 4) * 8) * 2;
    const int b_row = (lane & 7) + ((lane >> 4) & 1) * 8;
    const int b_koff = ((lane >> 3) & 1) * 8;
    uint32_t b_off[4];
#pragma unroll
    for (int p = 0; p < 4; p++)
        b_off[p] = ((warp_n * 64 + p * 16 + b_row) * LDH + b_koff) * 2;

    float acc[2][8][4];
#pragma unroll
    for (int i = 0; i < 2; i++)
#pragma unroll
        for (int j = 0; j < 8; j++)
#pragma unroll
            for (int r = 0; r < 4; r++) acc[i][j][r] = 0.f;

    const int NCH = K >> 5;
    auto load_tile = [&](int ch, int buf) {
        const __half* Ag = A + (size_t)bm * K + ch * 32;
        const __half* Bg = B + (size_t)bn * K + ch * 32;
        __half* Ad = smh + buf * HBUF;
        __half* Bd = smh + (2 + buf) * HBUF;
#pragma unroll
        for (int i = 0; i < 2; i++) {
            int id = tid + (i << 8);
            int row = id >> 2, c8 = (id & 3) << 3;
            cp_async16(Ad + row * LDH + c8, Ag + (size_t)row * K + c8);
            cp_async16(Bd + row * LDH + c8, Bg + (size_t)row * K + c8);
        }
    };

    load_tile(0, 0);
    cp_commit();
    for (int ch = 0; ch < NCH; ch++) {
        if (ch + 1 < NCH) load_tile(ch + 1, (ch + 1) & 1);
        cp_commit();
        cp_wait1();
        __syncthreads();
        const uint32_t Ab = smb + (ch & 1) * HBUF * 2;
        const uint32_t Bb = smb + (2 + (ch & 1)) * HBUF * 2;
#pragma unroll
        for (int ks = 0; ks < 32; ks += 16) {
            uint32_t ra[2][4], rb[4][4];
#pragma unroll
            for (int mt = 0; mt < 2; mt++)
                ldsm_x4(ra[mt][0], ra[mt][1], ra[mt][2], ra[mt][3], Ab + a_off[mt] + ks * 2);
#pragma unroll
            for (int p = 0; p < 4; p++)
                ldsm_x4(rb[p][0], rb[p][1], rb[p][2], rb[p][3], Bb + b_off[p] + ks * 2);
#pragma unroll
            for (int p = 0; p < 4; p++)
#pragma unroll
                for (int mt = 0; mt < 2; mt++) {
                    mma16n8k16(acc[mt][2 * p][0], acc[mt][2 * p][1],
                               acc[mt][2 * p][2], acc[mt][2 * p][3],
                               ra[mt][0], ra[mt][1], ra[mt][2], ra[mt][3],
                               rb[p][0], rb[p][1]);
                    mma16n8k16(acc[mt][2 * p + 1][0], acc[mt][2 * p + 1][1],
                               acc[mt][2 * p + 1][2], acc[mt][2 * p + 1][3],
                               ra[mt][0], ra[mt][1], ra[mt][2], ra[mt][3],
                               rb[p][2], rb[p][3]);
                }
        }
        __syncthreads();
    }

#pragma unroll
    for (int mt = 0; mt < 2; mt++) {
        int r0 = bm + warp_m * 32 + mt * 16 + grp;
#pragma unroll
        for (int nt = 0; nt < 8; nt++) {
            int c0 = bn + warp_n * 64 + nt * 8 + 2 * tig;
#pragma unroll
            for (int half_ = 0; half_ < 2; half_++) {
                int rr = r0 + half_ * 8;
                float vx = acc[mt][nt][2 * half_ + 0];
                float vy = acc[mt][nt][2 * half_ + 1];
                if constexpr (EPI == 4) {
                    vx += bias[c0]; vy += bias[c0 + 1];
                    int seg = c0 >> 8;
                    size_t idx = (size_t)rr * D + (c0 & 255);
                    if (seg == 0) {
                        vx = fmaxf(vx, 0.f); vy = fmaxf(vy, 0.f);
                        *reinterpret_cast<__half2*>(Ch + idx) = __floats2half2_rn(vx, vy);
                    } else if (seg == 1) {
                        vx = fmaxf(vx, 0.f); vy = fmaxf(vy, 0.f);
                        float2 o; o.x = vx; o.y = vy;
                        *reinterpret_cast<float2*>(Cf2 + idx) = o;
                    } else {
                        *reinterpret_cast<__half2*>(Ch2 + idx) = __floats2half2_rn(vx, vy);
                    }
                } else if constexpr (EPI == 3) {
                    size_t idx = (size_t)rr * Ntot + c0;
                    float2 cc = *reinterpret_cast<const float2*>(C + idx);
                    float2 aa = *reinterpret_cast<const float2*>(aux + idx);
                    vx += bias[c0] + cc.x + aa.x;
                    vy += bias[c0 + 1] + cc.y + aa.y;
                    vx = fmaxf(vx, 0.f); vy = fmaxf(vy, 0.f);
                    *reinterpret_cast<__half2*>(Ch + idx) = __floats2half2_rn(vx, vy);
                } else {
                    vx += bias[c0]; vy += bias[c0 + 1];
                    if constexpr (EPI == 2) { vx = fmaxf(vx, 0.f); vy = fmaxf(vy, 0.f); }
                    size_t idx = (size_t)rr * Ntot + c0;
                    float2 o; o.x = vx; o.y = vy;
                    *reinterpret_cast<float2*>(C + idx) = o;
                }
            }
        }
    }
}

// ---------------------------------------------------------------------------
// FUSED dots2 + node attention (unchanged from R8)
// ---------------------------------------------------------------------------
#define LGD 133
#define FUS_SMEM_BYTES (128 * LGD * 4 + 128 * KTOP * 4 + 128 * KTOP * 4)

__global__ void __launch_bounds__(256) dots2_node_fused(
    const __half* __restrict__ A, const __half* __restrict__ Bk,
    const float* __restrict__ edg,
    float* __restrict__ nodes, __half* __restrict__ nodesh) {
    extern __shared__ __half smh[];
    float* logits = reinterpret_cast<float*>(smh);
    float* wv_s = logits + 128 * LGD;
    int*   wi_s = reinterpret_cast<int*>(wv_s + 128 * KTOP);

    const int tid = threadIdx.x;
    const int wid = tid >> 5, lane = tid & 31;
    const int warp_m = wid & 3;
    const int warp_n = wid >> 2;
    const int bm = blockIdx.x * 128;
    const int grp = lane >> 2;
    const int tig = lane & 3;
    const int K = D;

    const uint32_t smb = (uint32_t)__cvta_generic_to_shared(smh);
    uint32_t a_off[2];
#pragma unroll
    for (int mt = 0; mt < 2; mt++)
        a_off[mt] = ((warp_m * 32 + mt * 16 + (lane & 15)) * LDH + (lane >> 4) * 8) * 2;
    const int b_row = (lane & 7) + ((lane >> 4) & 1) * 8;
    const int b_koff = ((lane >> 3) & 1) * 8;
    uint32_t b_off[4];
#pragma unroll
    for (int p = 0; p < 4; p++)
        b_off[p] = ((warp_n * 64 + p * 16 + b_row) * LDH + b_koff) * 2;

    float m_run = -INFINITY, z_run = 0.f;
    float tv[KTOP]; int ti[KTOP];
#pragma unroll
    for (int i = 0; i < KTOP; i++) { tv[i] = -INFINITY; ti[i] = 0; }

    for (int sc = 0; sc < 4; sc++) {
        float acc[2][8][4];
#pragma unroll
        for (int i = 0; i < 2; i++)
#pragma unroll
            for (int j = 0; j < 8; j++)
#pragma unroll
                for (int r = 0; r < 4; r++) acc[i][j][r] = 0.f;

        const __half* Bg_base = Bk + (size_t)(sc * 128) * K;
        auto load_tile = [&](int ch, int buf) {
            const __half* Ag = A + (size_t)bm * K + ch * 32;
            const __half* Bg = Bg_base + ch * 32;
            __half* Ad = smh + buf * HBUF;
            __half* Bd = smh + (2 + buf) * HBUF;
#pragma unroll
            for (int i = 0; i < 2; i++) {
                int id = tid + (i << 8);
                int row = id >> 2, c8 = (id & 3) << 3;
                cp_async16(Ad + row * LDH + c8, Ag + (size_t)row * K + c8);
                cp_async16(Bd + row * LDH + c8, Bg + (size_t)row * K + c8);
            }
        };

        load_tile(0, 0);
        cp_commit();
        for (int ch = 0; ch < 8; ch++) {
            if (ch + 1 < 8) load_tile(ch + 1, (ch + 1) & 1);
            cp_commit();
            cp_wait1();
            __syncthreads();
            const uint32_t Ab = smb + (ch & 1) * HBUF * 2;
            const uint32_t Bb = smb + (2 + (ch & 1)) * HBUF * 2;
#pragma unroll
            for (int ks = 0; ks < 32; ks += 16) {
                uint32_t ra[2][4], rb[4][4];
#pragma unroll
                for (int mt = 0; mt < 2; mt++)
                    ldsm_x4(ra[mt][0], ra[mt][1], ra[mt][2], ra[mt][3], Ab + a_off[mt] + ks * 2);
#pragma unroll
                for (int p = 0; p < 4; p++)
                    ldsm_x4(rb[p][0], rb[p][1], rb[p][2], rb[p][3], Bb + b_off[p] + ks * 2);
#pragma unroll
                for (int p = 0; p < 4; p++)
#pragma unroll
                    for (int mt = 0; mt < 2; mt++) {
                        mma16n8k16(acc[mt][2 * p][0], acc[mt][2 * p][1],
                                   acc[mt][2 * p][2], acc[mt][2 * p][3],
                                   ra[mt][0], ra[mt][1], ra[mt][2], ra[mt][3],
                                   rb[p][0], rb[p][1]);
                        mma16n8k16(acc[mt][2 * p + 1][0], acc[mt][2 * p + 1][1],
                                   acc[mt][2 * p + 1][2], acc[mt][2 * p + 1][3],
                                   ra[mt][0], ra[mt][1], ra[mt][2], ra[mt][3],
                                   rb[p][2], rb[p][3]);
                    }
            }
            __syncthreads();
        }
#pragma unroll
        for (int mt = 0; mt < 2; mt++) {
            int r0 = warp_m * 32 + mt * 16 + grp;
#pragma unroll
            for (int nt = 0; nt < 8; nt++) {
                int c0 = warp_n * 64 + nt * 8 + 2 * tig;
#pragma unroll
                for (int half_ = 0; half_ < 2; half_++) {
                    int rr = r0 + half_ * 8;
                    logits[rr * LGD + c0]     = acc[mt][nt][2 * half_ + 0] * SCALE_C;
                    logits[rr * LGD + c0 + 1] = acc[mt][nt][2 * half_ + 1] * SCALE_C;
                }
            }
        }
        __syncthreads();
        if (tid < 128) {
            const float* lr = logits + tid * LGD;
            for (int j = 0; j < 128; j++) {
                float v = lr[j];
                if (v > m_run) { z_run *= __expf(m_run - v); m_run = v; }
                z_run += __expf(v - m_run);
                if (v > tv[KTOP - 1]) {
                    int ix = sc * 128 + j;
                    float vt = v;
#pragma unroll
                    for (int p = 0; p < KTOP; p++)
                        if (vt > tv[p]) {
                            float tf = tv[p]; tv[p] = vt; vt = tf;
                            int tt = ti[p]; ti[p] = ix; ix = tt;
                        }
                }
            }
        }
        __syncthreads();
    }
    if (tid < 128) {
        float zin = 1.f / z_run;
#pragma unroll
        for (int i = 0; i < KTOP; i++) {
            wv_s[tid * KTOP + i] = __expf(tv[i] - m_run) * zin;
            wi_s[tid * KTOP + i] = ti[i];
        }
    }
    __syncthreads();
    for (int rr = 0; rr < 16; rr++) {
        int r = wid * 16 + rr;
        float w_[KTOP]; int ix_[KTOP];
#pragma unroll
        for (int i = 0; i < KTOP; i++) { w_[i] = wv_s[r * KTOP + i]; ix_[i] = wi_s[r * KTOP + i]; }
        float* po = nodes + (size_t)(bm + r) * D;
        __half* ph = nodesh + (size_t)(bm + r) * D;
#pragma unroll
        for (int j = 0; j < 8; j++) {
            int c = lane + 32 * j;
            float a2 = 0.f;
#pragma unroll
            for (int i = 0; i < KTOP; i++) a2 += w_[i] * edg[(size_t)ix_[i] * D + c];
            po[c] = a2;
            ph[c] = __float2half_rn(a2);
        }
    }
}

// ---------------------------------------------------------------------------
// dots1 Phase A: per (slot-chunk, node-chunk) partials {m, z, top10}
// grid (512 node-chunks, 4 slot-chunks), 256 thr. SMEM: logits 128x133 f32.
// record stride 24 floats: [m, z, v0..v9, i0..i9 (as float bits), pad]
// ---------------------------------------------------------------------------
#define FUS1_SMEM_BYTES (128 * LGD * 4)

__global__ void __launch_bounds__(256) dots1_partial(
    const __half* __restrict__ A,   // qh [512,256]
    const __half* __restrict__ Bk,  // kkh [65536,256]
    float* __restrict__ part) {
    extern __shared__ __half smh[];
    float* logits = reinterpret_cast<float*>(smh);

    const int tid = threadIdx.x;
    const int wid = tid >> 5, lane = tid & 31;
    const int warp_m = wid & 3;
    const int warp_n = wid >> 2;
    const int bm = blockIdx.y * 128;       // slot offset
    const int bnc = blockIdx.x;            // node chunk
    const int grp = lane >> 2;
    const int tig = lane & 3;
    const int K = D;

    const uint32_t smb = (uint32_t)__cvta_generic_to_shared(smh);
    uint32_t a_off[2];
#pragma unroll
    for (int mt = 0; mt < 2; mt++)
        a_off[mt] = ((warp_m * 32 + mt * 16 + (lane & 15)) * LDH + (lane >> 4) * 8) * 2;
    const int b_row = (lane & 7) + ((lane >> 4) & 1) * 8;
    const int b_koff = ((lane >> 3) & 1) * 8;
    uint32_t b_off[4];
#pragma unroll
    for (int p = 0; p < 4; p++)
        b_off[p] = ((warp_n * 64 + p * 16 + b_row) * LDH + b_koff) * 2;

    float acc[2][8][4];
#pragma unroll
    for (int i = 0; i < 2; i++)
#pragma unroll
        for (int j = 0; j < 8; j++)
#pragma unroll
            for (int r = 0; r < 4; r++) acc[i][j][r] = 0.f;

    const __half* Bg_base = Bk + (size_t)bnc * 128 * K;
    auto load_tile = [&](int ch, int buf) {
        const __half* Ag = A + (size_t)bm * K + ch * 32;
        const __half* Bg = Bg_base + ch * 32;
        __half* Ad = smh + buf * HBUF;
        __half* Bd = smh + (2 + buf) * HBUF;
#pragma unroll
        for (int i = 0; i < 2; i++) {
            int id = tid + (i << 8);
            int row = id >> 2, c8 = (id & 3) << 3;
            cp_async16(Ad + row * LDH + c8, Ag + (size_t)row * K + c8);
            cp_async16(Bd + row * LDH + c8, Bg + (size_t)row * K + c8);
        }
    };

    load_tile(0, 0);
    cp_commit();
    for (int ch = 0; ch < 8; ch++) {
        if (ch + 1 < 8) load_tile(ch + 1, (ch + 1) & 1);
        cp_commit();
        cp_wait1();
        __syncthreads();
        const uint32_t Ab = smb + (ch & 1) * HBUF * 2;
        const uint32_t Bb = smb + (2 + (ch & 1)) * HBUF * 2;
#pragma unroll
        for (int ks = 0; ks < 32; ks += 16) {
            uint32_t ra[2][4], rb[4][4];
#pragma unroll
            for (int mt = 0; mt < 2; mt++)
                ldsm_x4(ra[mt][0], ra[mt][1], ra[mt][2], ra[mt][3], Ab + a_off[mt] + ks * 2);
#pragma unroll
            for (int p = 0; p < 4; p++)
                ldsm_x4(rb[p][0], rb[p][1], rb[p][2], rb[p][3], Bb + b_off[p] + ks * 2);
#pragma unroll
            for (int p = 0; p < 4; p++)
#pragma unroll
                for (int mt = 0; mt < 2; mt++) {
                    mma16n8k16(acc[mt][2 * p][0], acc[mt][2 * p][1],
                               acc[mt][2 * p][2], acc[mt][2 * p][3],
                               ra[mt][0], ra[mt][1], ra[mt][2], ra[mt][3],
                               rb[p][0], rb[p][1]);
                    mma16n8k16(acc[mt][2 * p + 1][0], acc[mt][2 * p + 1][1],
                               acc[mt][2 * p + 1][2], acc[mt][2 * p + 1][3],
                               ra[mt][0], ra[mt][1], ra[mt][2], ra[mt][3],
                               rb[p][2], rb[p][3]);
                }
        }
        __syncthreads();
    }
    // logits[slot_local][node_local], scaled
#pragma unroll
    for (int mt = 0; mt < 2; mt++) {
        int r0 = warp_m * 32 + mt * 16 + grp;
#pragma unroll
        for (int nt = 0; nt < 8; nt++) {
            int c0 = warp_n * 64 + nt * 8 + 2 * tig;
#pragma unroll
            for (int half_ = 0; half_ < 2; half_++) {
                int rr = r0 + half_ * 8;
                logits[rr * LGD + c0]     = acc[mt][nt][2 * half_ + 0] * SCALE_C;
                logits[rr * LGD + c0 + 1] = acc[mt][nt][2 * half_ + 1] * SCALE_C;
            }
        }
    }
    __syncthreads();
    if (tid < 128) {
        const float* lr = logits + tid * LGD;
        float m = -INFINITY, z = 0.f;
        float tv[KTOP]; int ti[KTOP];
#pragma unroll
        for (int i = 0; i < KTOP; i++) { tv[i] = -INFINITY; ti[i] = 0; }
        for (int j = 0; j < 128; j++) {
            float v = lr[j];
            if (v > m) { z *= __expf(m - v); m = v; }
            z += __expf(v - m);
            if (v > tv[KTOP - 1]) {
                int ix = bnc * 128 + j;
                float vt = v;
#pragma unroll
                for (int p = 0; p < KTOP; p++)
                    if (vt > tv[p]) {
                        float tf = tv[p]; tv[p] = vt; vt = tf;
                        int tt = ti[p]; ti[p] = ix; ix = tt;
                    }
            }
        }
        float* rec = part + ((size_t)(bm + tid) * 512 + bnc) * 24;
        rec[0] = m; rec[1] = z;
#pragma unroll
        for (int i = 0; i < KTOP; i++) {
            rec[2 + i] = tv[i];
            rec[12 + i] = __int_as_float(ti[i]);
        }
    }
}

// ---------------------------------------------------------------------------
// dots1 Phase B: merge 512 partials per slot, softmax+eps weights, gather vv.
// 512 blocks x 256 thr.
// ---------------------------------------------------------------------------
__global__ void slot_merge(const float* __restrict__ part, const float* __restrict__ vv,
                           const float* __restrict__ e, float* __restrict__ e2cat) {
    __shared__ float sv[256 * KTOP];
    __shared__ int   si[256 * KTOP];
    __shared__ float sm_m[256];
    __shared__ float sm_z[256];
    __shared__ float sw[KTOP];
    __shared__ int   sx[KTOP];
    int s = blockIdx.x, tid = threadIdx.x;

    const float* r0 = part + ((size_t)s * 512 + 2 * tid) * 24;
    const float* r1 = r0 + 24;
    float m = r0[0], z = r0[1];
    float tv[KTOP]; int ti[KTOP];
#pragma unroll
    for (int i = 0; i < KTOP; i++) { tv[i] = r0[2 + i]; ti[i] = __float_as_int(r0[12 + i]); }
    {
        float mb = r1[0], zb = r1[1];
        float mn = fmaxf(m, mb);
        z = z * __expf(m - mn) + zb * __expf(mb - mn);
        m = mn;
#pragma unroll
        for (int i = 0; i < KTOP; i++) {
            float v = r1[2 + i];
            int ix = __float_as_int(r1[12 + i]);
            if (v > tv[KTOP - 1]) {
#pragma unroll
                for (int p = 0; p < KTOP; p++)
                    if (v > tv[p]) {
                        float tf = tv[p]; tv[p] = v; v = tf;
                        int tt = ti[p]; ti[p] = ix; ix = tt;
                    }
            }
        }
    }
#pragma unroll
    for (int i = 0; i < KTOP; i++) { sv[tid * KTOP + i] = tv[i]; si[tid * KTOP + i] = ti[i]; }
    sm_m[tid] = m; sm_z[tid] = z;
    __syncthreads();
    for (int stride = 128; stride >= 1; stride >>= 1) {
        if (tid < stride) {
#pragma unroll
            for (int i = 0; i < KTOP; i++) { tv[i] = sv[tid * KTOP + i]; ti[i] = si[tid * KTOP + i]; }
#pragma unroll
            for (int i = 0; i < KTOP; i++) {
                float v = sv[(tid + stride) * KTOP + i];
                int ix = si[(tid + stride) * KTOP + i];
                if (v > tv[KTOP - 1]) {
#pragma unroll
                    for (int p = 0; p < KTOP; p++)
                        if (v > tv[p]) {
                            float tf = tv[p]; tv[p] = v; v = tf;
                            int tt = ti[p]; ti[p] = ix; ix = tt;
                        }
                }
            }
#pragma unroll
            for (int i = 0; i < KTOP; i++) { sv[tid * KTOP + i] = tv[i]; si[tid * KTOP + i] = ti[i]; }
            float ma = sm_m[tid], za = sm_z[tid];
            float mb = sm_m[tid + stride], zb = sm_z[tid + stride];
            float mn = fmaxf(ma, mb);
            float zn = za * __expf(ma - mn) + zb * __expf(mb - mn);
            sm_m[tid] = mn; sm_z[tid] = zn;
        }
        __syncthreads();
    }
    float maxv = sm_m[0];
    float Z = sm_z[0];
    if (tid < KTOP) {
        float p = __expf(sv[tid] - maxv) / Z;
        sw[tid] = (p + EPSC) / (1.f + (float)N_NODES * EPSC);
        sx[tid] = si[tid];
    }
    __syncthreads();
    float acc = 0.f;
#pragma unroll
    for (int i = 0; i < KTOP; i++) acc += sw[i] * vv[(size_t)sx[i] * D + tid];
    e2cat[(size_t)s * 2 * D + D + tid] = acc;
    e2cat[(size_t)s * 2 * D + tid] = e[(size_t)s * D + tid];
}

// ---------------------------------------------------------------------------
// prep kernel (unchanged from R8)
// ---------------------------------------------------------------------------
__device__ __forceinline__ void tr_tile(const float* in, float* outF, __half* outH,
                                        int R, int C, int bx, float (*tile)[33]) {
    int tx = threadIdx.x, tyw = threadIdx.y;
    int xt = bx & (C / 32 - 1), yt = bx / (C / 32);
    int bxc = xt * 32, byr = yt * 32;
    for (int y = tyw; y < 32; y += 8)
        tile[y][tx] = in[(size_t)(byr + y) * C + bxc + tx];
    __syncthreads();
    if (outH) {
        for (int y = tyw; y < 32; y += 8)
            outH[(size_t)(bxc + y) * R + byr + tx] = __float2half_rn(tile[tx][y]);
    } else {
        for (int y = tyw; y < 32; y += 8)
            outF[(size_t)(bxc + y) * R + byr + tx] = tile[tx][y];
    }
}

__global__ void prep(
    const float* Wk, const float* Wv, const float* Wq, const float* Wc0,
    const float* Wc1, const float* Wt, const float* cw, const float* Wm1,
    const float* Wm2,
    __half* Wkvqh, __half* Wc0h, __half* Wc1h, __half* Wth,
    float* WqTf, float* WkTf, float* cwT, float* Wm1T, float* Wm2T,
    const float* bk, const float* bv, const float* bq, float* bkvq,
    const float* noise, const float* emu, const float* elog,
    const float* lew, const float* leb, float* e) {
    __shared__ float tile[32][33];
    int task = blockIdx.y, bx = blockIdx.x;
    switch (task) {
    case 0: tr_tile(Wk,  nullptr, Wkvqh,             D, D, bx, tile); break;
    case 1: tr_tile(Wv,  nullptr, Wkvqh + D * D,     D, D, bx, tile); break;
    case 2: tr_tile(Wq,  nullptr, Wkvqh + 2 * D * D, D, D, bx, tile); break;
    case 3: tr_tile(Wc0, nullptr, Wc0h, D, D, bx, tile); break;
    case 4: tr_tile(Wc1, nullptr, Wc1h, D, D, bx, tile); break;
    case 5: tr_tile(Wt,  nullptr, Wth,  D, D, bx, tile); break;
    case 6: tr_tile(Wq,  WqTf, nullptr, D, D, bx, tile); break;
    case 7: tr_tile(Wk,  WkTf, nullptr, D, D, bx, tile); break;
    case 8: tr_tile(cw,  cwT,  nullptr, D, D, bx, tile); break;
    case 9: tr_tile(Wm2, Wm2T, nullptr, HID, D, bx, tile); break;
    case 10: tr_tile(Wm1, Wm1T, nullptr, 2 * D, HID, bx, tile); break;
    case 11: tr_tile(Wm1, Wm1T, nullptr, 2 * D, HID, bx + 64, tile); break;
    case 12: {
        if (bx == 0) {
            int i = threadIdx.y * 32 + threadIdx.x;
            bkvq[i] = bk[i]; bkvq[D + i] = bv[i]; bkvq[2 * D + i] = bq[i];
        }
        break;
    }
    default: {
        int warp = bx * 8 + threadIdx.y;
        int lane = threadIdx.x;
        const float* r = noise + (size_t)warp * D;
        float v[8]; float s = 0.f;
#pragma unroll
        for (int j = 0; j < 8; j++) {
            int c = lane + 32 * j;
            v[j] = emu[c] + expf(elog[c]) * r[c];
            s += v[j];
        }
#pragma unroll
        for (int st = 16; st; st >>= 1) s += __shfl_xor_sync(0xffffffffu, s, st);
        float mu = s * (1.f / 256.f);
        float q = 0.f;
#pragma unroll
        for (int j = 0; j < 8; j++) { float d2 = v[j] - mu; q += d2 * d2; }
#pragma unroll
        for (int st = 16; st; st >>= 1) q += __shfl_xor_sync(0xffffffffu, q, st);
        float rinv = rsqrtf(q * (1.f / 256.f) + 1e-5f);
        float* po = e + (size_t)warp * D;
#pragma unroll
        for (int j = 0; j < 8; j++) {
            int c = lane + 32 * j;
            po[c] = (v[j] - mu) * rinv * lew[c] + leb[c];
        }
        break;
    }
    }
}

// ---------------------------------------------------------------------------
// LayerNorm -> half + x->half copy (unchanged)
// ---------------------------------------------------------------------------
__global__ void ln_rows(const float* __restrict__ x, const float* __restrict__ w,
                        const float* __restrict__ b, __half* __restrict__ o,
                        __half* __restrict__ xrh, int M) {
    int warp = (blockIdx.x * blockDim.x + threadIdx.x) >> 5;
    int lane = threadIdx.x & 31;
    if (warp >= M) return;
    const float* r = x + (size_t)warp * D;
    float v[8]; float s = 0.f;
#pragma unroll
    for (int j = 0; j < 8; j++) { v[j] = r[lane + 32 * j]; s += v[j]; }
#pragma unroll
    for (int st = 16; st; st >>= 1) s += __shfl_xor_sync(0xffffffffu, s, st);
    float mu = s * (1.f / 256.f);
    float q = 0.f;
#pragma unroll
    for (int j = 0; j < 8; j++) { float d = v[j] - mu; q += d * d; }
#pragma unroll
    for (int st = 16; st; st >>= 1) q += __shfl_xor_sync(0xffffffffu, q, st);
    float rinv = rsqrtf(q * (1.f / 256.f) + 1e-5f);
    __half* po = o + (size_t)warp * D;
    __half* px = xrh + (size_t)warp * D;
#pragma unroll
    for (int j = 0; j < 8; j++) {
        int c = lane + 32 * j;
        po[c] = __float2half_rn((v[j] - mu) * rinv * w[c] + b[c]);
        px[c] = __float2half_rn(v[j]);
    }
}

// ---------------------------------------------------------------------------
// Small fp32 NT GEMM: 32x32 tile, 128 threads, single-phase cp.async K-chunks.
// SMEM: As[32][260] + Bs[32][260] floats = 66560 B.
// Thread outputs: rows ty*2+{0,1}, cols tx + 8*{0..3}.
// ---------------------------------------------------------------------------
#define GSW 260
#define GS_SMEM_BYTES (2 * 32 * GSW * 4)

template <bool BIAS, bool RELU, bool OUTH>
__global__ void __launch_bounds__(128) gemm_small(
    const float* __restrict__ A, const float* __restrict__ B,
    float* __restrict__ C, __half* __restrict__ Ch,
    const float* __restrict__ bias, int M, int N, int K) {
    extern __shared__ float gs[];
    float* As = gs;
    float* Bs = gs + 32 * GSW;
    const int tid = threadIdx.x;
    const int tx = tid & 7, ty = tid >> 3;
    const int bm = blockIdx.y * 32, bn = blockIdx.x * 32;

    float acc[2][4];
#pragma unroll
    for (int i = 0; i < 2; i++)
#pragma unroll
        for (int j = 0; j < 4; j++) acc[i][j] = 0.f;

    for (int k0 = 0; k0 < K; k0 += 256) {
        // burst-load 32x256 tiles of A and B
#pragma unroll
        for (int i = 0; i < 16; i++) {
            int id = tid + i * 128;
            int row = id >> 6, c4 = (id & 63) << 2;
            cp_async16(&As[row * GSW + c4], &A[(size_t)(bm + row) * K + k0 + c4]);
            cp_async16(&Bs[row * GSW + c4], &B[(size_t)(bn + row) * K + k0 + c4]);
        }
        cp_commit();
        cp_wait0();
        __syncthreads();
#pragma unroll 4
        for (int k = 0; k < 256; k += 4) {
            float4 a0 = *reinterpret_cast<const float4*>(&As[(ty * 2 + 0) * GSW + k]);
            float4 a1 = *reinterpret_cast<const float4*>(&As[(ty * 2 + 1) * GSW + k]);
#pragma unroll
            for (int j = 0; j < 4; j++) {
                float4 b4 = *reinterpret_cast<const float4*>(&Bs[(tx + 8 * j) * GSW + k]);
                acc[0][j] += a0.x * b4.x + a0.y * b4.y + a0.z * b4.z + a0.w * b4.w;
                acc[1][j] += a1.x * b4.x + a1.y * b4.y + a1.z * b4.z + a1.w * b4.w;
            }
        }
        __syncthreads();
    }
#pragma unroll
    for (int i = 0; i < 2; i++) {
        int m = bm + ty * 2 + i;
#pragma unroll
        for (int j = 0; j < 4; j++) {
            int n = bn + tx + 8 * j;
            float v = acc[i][j];
            if (BIAS) v += bias[n];
            if (RELU) v = fmaxf(v, 0.f);
            if (OUTH) Ch[(size_t)m * N + n] = __float2half_rn(v);
            else      C [(size_t)m * N + n] = v;
        }
    }
}

// ---------------------------------------------------------------------------
// Launch
// ---------------------------------------------------------------------------
extern "C" void kernel_launch(void* const* d_in, const int* in_sizes, int n_in,
                              void* d_out, int out_size) {
    (void)in_sizes; (void)n_in; (void)out_size;
    const float* x      = (const float*)d_in[0];
    const float* enoise = (const float*)d_in[1];
    const float* emu    = (const float*)d_in[2];
    const float* elog   = (const float*)d_in[3];
    const float* lnw    = (const float*)d_in[4];
    const float* lnb    = (const float*)d_in[5];
    const float* lew    = (const float*)d_in[6];
    const float* leb    = (const float*)d_in[7];
    const float* Wq = (const float*)d_in[8];  const float* bq = (const float*)d_in[9];
    const float* Wk = (const float*)d_in[10]; const float* bk = (const float*)d_in[11];
    const float* Wv = (const float*)d_in[12]; const float* bv = (const float*)d_in[13];
    const float* Wm1 = (const float*)d_in[14]; const float* bm1 = (const float*)d_in[15];
    const float* Wm2 = (const float*)d_in[16]; const float* bm2 = (const float*)d_in[17];
    const float* cw = (const float*)d_in[18];  const float* cb = (const float*)d_in[19];
    const float* Wc0 = (const float*)d_in[20]; const float* bc0 = (const float*)d_in[21];
    const float* Wc1 = (const float*)d_in[22]; const float* bc1 = (const float*)d_in[23];
    const float* Wt = (const float*)d_in[24];  const float* bt = (const float*)d_in[25];
    float* out = (float*)d_out;

    void* p;
    cudaGetSymbolAddress(&p, g_xh);    __half* xh = (__half*)p;
    cudaGetSymbolAddress(&p, g_xrh);   __half* xrh = (__half*)p;
    cudaGetSymbolAddress(&p, g_kkh);   __half* kkh = (__half*)p;
    cudaGetSymbolAddress(&p, g_q2h);   __half* q2h = (__half*)p;
    cudaGetSymbolAddress(&p, g_ndh);   __half* ndh = (__half*)p;
    cudaGetSymbolAddress(&p, g_tmph);  __half* tmph = (__half*)p;
    cudaGetSymbolAddress(&p, g_vv);    float* vvb = (float*)p;
    cudaGetSymbolAddress(&p, g_nodes); float* nodesb = (float*)p;
    cudaGetSymbolAddress(&p, g_tmp);   float* tmp = (float*)p;
    cudaGetSymbolAddress(&p, g_part);  float* part = (float*)p;
    cudaGetSymbolAddress(&p, g_e);     float* e = (float*)p;
    cudaGetSymbolAddress(&p, g_qh);    __half* qh = (__half*)p;
    cudaGetSymbolAddress(&p, g_k2h);   __half* k2h = (__half*)p;
    cudaGetSymbolAddress(&p, g_e2cat); float* e2cat = (float*)p;
    cudaGetSymbolAddress(&p, g_h1);    float* h1 = (float*)p;
    cudaGetSymbolAddress(&p, g_e2);    float* e2 = (float*)p;
    cudaGetSymbolAddress(&p, g_edg);   float* edg = (float*)p;
    cudaGetSymbolAddress(&p, g_Wkvqh); __half* Wkvqh = (__half*)p;
    cudaGetSymbolAddress(&p, g_Wc0h);  __half* Wc0h = (__half*)p;
    cudaGetSymbolAddress(&p, g_Wc1h);  __half* Wc1h = (__half*)p;
    cudaGetSymbolAddress(&p, g_Wth);   __half* Wth = (__half*)p;
    cudaGetSymbolAddress(&p, g_bkvq);  float* bkvq = (float*)p;
    cudaGetSymbolAddress(&p, g_WqTf);  float* WqTf = (float*)p;
    cudaGetSymbolAddress(&p, g_WkTf);  float* WkTf = (float*)p;
    cudaGetSymbolAddress(&p, g_Wm1T);  float* Wm1T = (float*)p;
    cudaGetSymbolAddress(&p, g_Wm2T);  float* Wm2T = (float*)p;
    cudaGetSymbolAddress(&p, g_cwT);   float* cwT = (float*)p;

    cudaFuncSetAttribute(mma_gemm<1>, cudaFuncAttributeMaxDynamicSharedMemorySize, MMA_SMEM_BYTES);
    cudaFuncSetAttribute(mma_gemm<2>, cudaFuncAttributeMaxDynamicSharedMemorySize, MMA_SMEM_BYTES);
    cudaFuncSetAttribute(mma_gemm<3>, cudaFuncAttributeMaxDynamicSharedMemorySize, MMA_SMEM_BYTES);
    cudaFuncSetAttribute(mma_gemm<4>, cudaFuncAttributeMaxDynamicSharedMemorySize, MMA_SMEM_BYTES);
    cudaFuncSetAttribute(dots2_node_fused, cudaFuncAttributeMaxDynamicSharedMemorySize, FUS_SMEM_BYTES);
    cudaFuncSetAttribute(dots1_partial, cudaFuncAttributeMaxDynamicSharedMemorySize, FUS1_SMEM_BYTES);
    cudaFuncSetAttribute(gemm_small<true, true, true>, cudaFuncAttributeMaxDynamicSharedMemorySize, GS_SMEM_BYTES);
    cudaFuncSetAttribute(gemm_small<true, true, false>, cudaFuncAttributeMaxDynamicSharedMemorySize, GS_SMEM_BYTES);
    cudaFuncSetAttribute(gemm_small<true, false, false>, cudaFuncAttributeMaxDynamicSharedMemorySize, GS_SMEM_BYTES);

    prep<<<dim3(64, 14), dim3(32, 8)>>>(
        Wk, Wv, Wq, Wc0, Wc1, Wt, cw, Wm1, Wm2,
        Wkvqh, Wc0h, Wc1h, Wth, WqTf, WkTf, cwT, Wm1T, Wm2T,
        bk, bv, bq, bkvq, enoise, emu, elog, lew, leb, e);

    ln_rows<<<N_NODES / 8, 256>>>(x, lnw, lnb, xh, xrh, N_NODES);

    // fused: kk(half,relu), vv(fp32,relu), q2(half)
    mma_gemm<4><<<dim3(6, 512), 256, MMA_SMEM_BYTES>>>(
        xh, Wkvqh, nullptr, bkvq, nullptr, vvb, kkh, q2h, N_NODES, 3 * D, D, 1.f);

    // q = relu(e@Wq+bq) -> half
    gemm_small<true, true, true><<<dim3(8, 16), 128, GS_SMEM_BYTES>>>(
        e, WqTf, nullptr, qh, bq, NS, D, D);

    // dots1 partials + merge (replaces S materialization + slot_attend)
    dots1_partial<<<dim3(512, 4), 256, FUS1_SMEM_BYTES>>>(qh, kkh, part);
    slot_merge<<<NS, 256>>>(part, vvb, e, e2cat);

    // slot MLP (fp32)
    gemm_small<true, true, false><<<dim3(8, 16), 128, GS_SMEM_BYTES>>>(
        e2cat, Wm1T, h1, nullptr, bm1, NS, HID, 2 * D);
    gemm_small<true, false, false><<<dim3(8, 16), 128, GS_SMEM_BYTES>>>(
        h1, Wm2T, e2, nullptr, bm2, NS, D, HID);

    // k2 = relu(e2@Wk+bk) -> half; edg = e2@conv_w+conv_b (fp32)
    gemm_small<true, true, true><<<dim3(8, 16), 128, GS_SMEM_BYTES>>>(
        e2, WkTf, nullptr, k2h, bk, NS, D, D);
    gemm_small<true, false, false><<<dim3(8, 16), 128, GS_SMEM_BYTES>>>(
        e2, cwT, edg, nullptr, cb, NS, D, D);

    // FUSED dots2 + node attention
    dots2_node_fused<<<512, 256, FUS_SMEM_BYTES>>>(q2h, k2h, edg, nodesb, ndh);

    // tmp = x@Wc0 + bc0 (fp32)
    mma_gemm<1><<<dim3(2, 512), 256, MMA_SMEM_BYTES>>>(
        xrh, Wc0h, tmp, bc0, nullptr, nullptr, nullptr, nullptr, N_NODES, D, D, 1.f);
    // tmph = relu(tmp + nodes@Wc1 + bc1 + nodes) -> half
    mma_gemm<3><<<dim3(2, 512), 256, MMA_SMEM_BYTES>>>(
        ndh, Wc1h, tmp, bc1, nodesb, nullptr, tmph, nullptr, N_NODES, D, D, 1.f);
    // out = relu(tmph@Wt + bt) (fp32 final)
    mma_gemm<2><<<dim3(2, 512), 256, MMA_SMEM_BYTES>>>(
        tmph, Wth, out, bt, nullptr, nullptr, nullptr, nullptr, N_NODES, D, D, 1.f);
}